// round 7
// baseline (speedup 1.0000x reference)
#include <cuda_runtime.h>
#include <cuda_fp16.h>
#include <math.h>
#include <stdint.h>

#define NN 100000
#define EE 3200000
#define EA (EE + NN)
#define FIN 78
#define FG 256
#define FH 128

// ---------------- scratch (device globals; no allocation) ----------------
__device__ __half d_mx16[(size_t)NN * 80];     // padded fp16 mol_x
__device__ __half d_catA[(size_t)NN * 512];    // [x | h] fp16 (layer2 view)
__device__ __half d_catB[(size_t)NN * 512];    // [x | h] fp16 (layer3 view)
__device__ __half d_agg[(size_t)NN * 512];     // aggregated features (2 heads)
__device__ float d_h [(size_t)NN * 256];       // fp32 h (layer1 out)
__device__ float d_g [(size_t)NN * 256];       // fp32 h (layer2 out)
__device__ __half d_xt[(size_t)NN * 128];
__device__ __half d_ef[(size_t)NN * 128];
__device__ __half d_hy16[(size_t)NN * 128];
// fp16 weights
__device__ __half d_w1h[FIN * 512];
__device__ __half d_w2h[256 * 512];
__device__ __half d_w3h[256 * 512];
__device__ __half d_bch[512 * 256];
__device__ __half d_th1h[334 * 128];
__device__ __half d_th2h[128 * 128];
__device__ float d_cb[256];
__device__ float d_wv[256 * 4];
__device__ float d_asrc[NN * 2];
__device__ float d_adst[NN * 2];
__device__ int csrA_off[NN + 1]; __device__ int csrA_val[EA];
__device__ int csrC_off[NN + 1]; __device__ int csrC_val[EE];
__device__ int cntA[NN], cntC[NN];
__device__ int curA[NN], curC[NN];
__device__ float d_binv[NN], d_dinv[NN];

// ---------------- CSR construction ----------------
__global__ void zero_counts_kernel() {
    int i = blockIdx.x * blockDim.x + threadIdx.x;
    if (i < NN) { cntA[i] = 0; cntC[i] = 0; }
}

__global__ void count_kernel(const int* __restrict__ ei) {
    int i = blockIdx.x * blockDim.x + threadIdx.x;
    if (i >= EE) return;
    int s = ei[i];
    int d = ei[EE + i];
    atomicAdd(&cntA[d], 1);
    atomicAdd(&cntC[s], 1);
}

__global__ void scan2_kernel() {
    bool isA = (blockIdx.x == 0);
    const int* in = isA ? cntA : cntC;
    int* out = isA ? csrA_off : csrC_off;
    const int n = NN;
    __shared__ int wsum[32];
    __shared__ int carry;
    int tid = threadIdx.x, lane = tid & 31, wid = tid >> 5;
    if (tid == 0) carry = 0;
    __syncthreads();
    for (int base = 0; base < n; base += 1024) {
        int i = base + tid;
        int raw = (i < n) ? in[i] : 0;
        int v = raw + (isA ? ((i < n) ? 1 : 0) : 0);
        int x = v;
        #pragma unroll
        for (int d = 1; d < 32; d <<= 1) {
            int y = __shfl_up_sync(0xFFFFFFFFu, x, d);
            if (lane >= d) x += y;
        }
        if (lane == 31) wsum[wid] = x;
        __syncthreads();
        if (wid == 0) {
            int w = wsum[lane];
            #pragma unroll
            for (int d = 1; d < 32; d <<= 1) {
                int y = __shfl_up_sync(0xFFFFFFFFu, w, d);
                if (lane >= d) w += y;
            }
            wsum[lane] = w;
        }
        __syncthreads();
        int excl = carry + (wid ? wsum[wid - 1] : 0) + x - v;
        if (i < n) {
            out[i] = excl;
            if (isA) {
                curA[i] = excl;
                csrA_val[excl + raw] = i;  // self loop pinned at segment end
                d_binv[i] = raw > 0 ? 1.0f / (float)raw : 0.0f;
            } else {
                curC[i] = excl;
                d_dinv[i] = raw > 0 ? 1.0f / (float)raw : 0.0f;
            }
        }
        if (i == n - 1) out[n] = excl + v;
        __syncthreads();
        if (tid == 0) carry += wsum[31];
        __syncthreads();
    }
}

__global__ void fill_kernel(const int* __restrict__ ei) {
    int i = blockIdx.x * blockDim.x + threadIdx.x;
    if (i >= EE) return;
    int s = ei[i];
    int d = ei[EE + i];
    csrA_val[atomicAdd(&curA[d], 1)] = s;
    csrC_val[atomicAdd(&curC[s], 1)] = d;
}

// ---------------- weight conversion ----------------
__global__ void f2h_kernel(const float* __restrict__ src, __half* __restrict__ dst, int n2) {
    int i = blockIdx.x * blockDim.x + threadIdx.x;
    if (i < n2) {
        float2 v = ((const float2*)src)[i];
        ((__half2*)dst)[i] = __floats2half2_rn(v.x, v.y);
    }
}

__global__ void build_bc16_kernel(const float* __restrict__ fc1w, const float* __restrict__ fc2w,
                                  const float* __restrict__ fc1b, const float* __restrict__ fc2b) {
    int idx = blockIdx.x * blockDim.x + threadIdx.x;
    if (idx >= 512 * 256) return;
    int k = idx >> 8, n = idx & 255;
    float v = (k < 256) ? fc1w[n * 256 + k] : fc2w[n * 256 + (k - 256)];
    d_bch[idx] = __float2half_rn(v);
    if (idx < 256) d_cb[idx] = fc1b[idx] + fc2b[idx];
}

__global__ void conv_mx_kernel(const float* __restrict__ x) {
    int idx = blockIdx.x * blockDim.x + threadIdx.x;
    if (idx >= NN * 40) return;
    int n = idx / 40, c2 = idx % 40;
    float a = 0.f, b = 0.f;
    int c = c2 * 2;
    if (c < FIN) a = x[(size_t)n * FIN + c];
    if (c + 1 < FIN) b = x[(size_t)n * FIN + c + 1];
    ((__half2*)d_mx16)[idx] = __floats2half2_rn(a, b);
}

// ---------------- fp16 tensor-core GEMM (m16n8k16, pipelined) ----------------
__device__ __forceinline__ void mma_f16(float* c, const uint32_t* a, uint32_t b0, uint32_t b1) {
    asm volatile(
        "mma.sync.aligned.m16n8k16.row.col.f32.f16.f16.f32 "
        "{%0,%1,%2,%3},{%4,%5,%6,%7},{%8,%9},{%0,%1,%2,%3};"
        : "+f"(c[0]), "+f"(c[1]), "+f"(c[2]), "+f"(c[3])
        : "r"(a[0]), "r"(a[1]), "r"(a[2]), "r"(a[3]), "r"(b0), "r"(b1));
}

#define PA 18
#define TILE_U (128 * PA)

// ASRC: 0 = fp32 A (+optional concat A2), 2 = fp16 A dense
// EPI:  0 = v*scale+bias(+relu) -> optional fp32 Cf (ldc) and fp16 Ch (ldch)
//       2 = gate blend: z=sig(v+bias+molb); o=z*x(fp16 from A)+(1-z)*h(fp32 Hin=A2)
template <int ASRC, int EPI>
__global__ __launch_bounds__(256) void gemm16_kernel(
    const void* __restrict__ Ap, int lda, int K1,
    const float* __restrict__ A2, int lda2,
    const __half* __restrict__ B1, const __half* __restrict__ B2, int ldb,
    int SP, int KV1, int KV2,
    float* __restrict__ Cf, int ldc,
    __half* __restrict__ Ch, int ldch,
    int M, int N, int Ktot,
    const float* __restrict__ bias, int relu, float scale,
    const float* __restrict__ molb)
{
    __shared__ uint32_t Asm[2 * TILE_U];
    __shared__ uint32_t Bsm[2 * TILE_U];
    int tid = threadIdx.x;
    int lane = tid & 31, wid = tid >> 5;
    int wm = wid & 3, wn = wid >> 2;
    int row0 = blockIdx.y * 128, col0 = blockIdx.x * 128;
    int g = lane >> 2, tg = lane & 3;

    float acc[2][8][4];
    #pragma unroll
    for (int mi = 0; mi < 2; mi++)
        #pragma unroll
        for (int ni = 0; ni < 8; ni++)
            #pragma unroll
            for (int q = 0; q < 4; q++) acc[mi][ni][q] = 0.0f;

    const float* Af = (const float*)Ap;
    const __half* Ah = (const __half*)Ap;

    float4 raf[4];
    uint2 rah[4];
    uint2 rbh[4];

    auto loadA = [&](int k0) {
        #pragma unroll
        for (int i = 0; i < 4; i++) {
            int l4 = tid + i * 256;
            int r = l4 >> 3, c4 = (l4 & 7) << 2;
            int grow = row0 + r, gk = k0 + c4;
            if (ASRC == 2) {
                uint2 u = make_uint2(0u, 0u);
                if (grow < M) u = *(const uint2*)(Ah + (size_t)grow * lda + gk);
                rah[i] = u;
            } else {
                float4 v = make_float4(0.f, 0.f, 0.f, 0.f);
                if (grow < M) {
                    if (gk + 3 < K1) {
                        v = *(const float4*)(Af + (size_t)grow * lda + gk);
                    } else {
                        float* pv = &v.x;
                        #pragma unroll
                        for (int j = 0; j < 4; j++) {
                            int kk = gk + j;
                            float x = 0.0f;
                            if (kk < K1) x = Af[(size_t)grow * lda + kk];
                            else if (kk < Ktot) x = A2[(size_t)grow * lda2 + (kk - K1)];
                            pv[j] = x;
                        }
                    }
                }
                raf[i] = v;
            }
        }
    };
    auto storeA = [&](uint32_t* As) {
        #pragma unroll
        for (int i = 0; i < 4; i++) {
            int l4 = tid + i * 256;
            int r = l4 >> 3, c2 = (l4 & 7) << 1;
            if (ASRC == 2) {
                As[r * PA + c2] = rah[i].x;
                As[r * PA + c2 + 1] = rah[i].y;
            } else {
                __half2 h0 = __floats2half2_rn(raf[i].x, raf[i].y);
                __half2 h1 = __floats2half2_rn(raf[i].z, raf[i].w);
                As[r * PA + c2] = *(uint32_t*)&h0;
                As[r * PA + c2 + 1] = *(uint32_t*)&h1;
            }
        }
    };
    auto loadB = [&](int k0) {
        #pragma unroll
        for (int i = 0; i < 4; i++) {
            int l4 = tid + i * 256;
            int k = l4 >> 5, n4 = (l4 & 31) << 2;
            int kk = k0 + k;
            uint2 u = make_uint2(0u, 0u);
            if (kk < SP) {
                if (kk < KV1) u = *(const uint2*)(B1 + (size_t)kk * ldb + col0 + n4);
            } else if (kk < Ktot) {
                int j = kk - SP;
                if (j < KV2) u = *(const uint2*)(B2 + (size_t)j * ldb + col0 + n4);
            }
            rbh[i] = u;
        }
    };
    auto storeB = [&](uint32_t* Bs) {
        __half* BsH = (__half*)Bs;
        #pragma unroll
        for (int i = 0; i < 4; i++) {
            int l4 = tid + i * 256;
            int k = l4 >> 5, n4 = (l4 & 31) << 2;
            __half hv[4];
            *(uint2*)hv = rbh[i];
            BsH[(n4 + 0) * (2 * PA) + k] = hv[0];
            BsH[(n4 + 1) * (2 * PA) + k] = hv[1];
            BsH[(n4 + 2) * (2 * PA) + k] = hv[2];
            BsH[(n4 + 3) * (2 * PA) + k] = hv[3];
        }
    };

    int T = (Ktot + 31) >> 5;
    loadA(0); loadB(0);
    storeA(Asm); storeB(Bsm);
    __syncthreads();

    for (int t = 0; t < T; t++) {
        int buf = t & 1;
        bool more = (t + 1 < T);
        if (more) { loadA((t + 1) << 5); loadB((t + 1) << 5); }
        const uint32_t* As = Asm + buf * TILE_U;
        const uint32_t* Bs = Bsm + buf * TILE_U;
        #pragma unroll
        for (int ks = 0; ks < 2; ks++) {
            uint32_t af[2][4];
            #pragma unroll
            for (int mi = 0; mi < 2; mi++) {
                int r = wm * 32 + mi * 16 + g;
                int c = ks * 8 + tg;
                af[mi][0] = As[r * PA + c];
                af[mi][1] = As[(r + 8) * PA + c];
                af[mi][2] = As[r * PA + c + 4];
                af[mi][3] = As[(r + 8) * PA + c + 4];
            }
            #pragma unroll
            for (int ni = 0; ni < 8; ni++) {
                int n = wn * 64 + ni * 8 + g;
                uint32_t b0 = Bs[n * PA + ks * 8 + tg];
                uint32_t b1 = Bs[n * PA + ks * 8 + tg + 4];
                mma_f16(acc[0][ni], af[0], b0, b1);
                mma_f16(acc[1][ni], af[1], b0, b1);
            }
        }
        if (more) {
            storeA(Asm + (buf ^ 1) * TILE_U);
            storeB(Bsm + (buf ^ 1) * TILE_U);
        }
        __syncthreads();
    }

    // epilogue
    #pragma unroll
    for (int mi = 0; mi < 2; mi++) {
        int r0 = row0 + wm * 32 + mi * 16 + g;
        #pragma unroll
        for (int ni = 0; ni < 8; ni++) {
            int c = col0 + wn * 64 + ni * 8 + tg * 2;
            float v0 = acc[mi][ni][0], v1 = acc[mi][ni][1];
            float v2 = acc[mi][ni][2], v3 = acc[mi][ni][3];
            if (EPI == 0) {
                float b0v = bias ? bias[c] : 0.0f;
                float b1v = bias ? bias[c + 1] : 0.0f;
                v0 = v0 * scale + b0v; v1 = v1 * scale + b1v;
                v2 = v2 * scale + b0v; v3 = v3 * scale + b1v;
                if (relu) {
                    v0 = fmaxf(v0, 0.f); v1 = fmaxf(v1, 0.f);
                    v2 = fmaxf(v2, 0.f); v3 = fmaxf(v3, 0.f);
                }
                if (r0 < M) {
                    if (Cf) *(float2*)(Cf + (size_t)r0 * ldc + c) = make_float2(v0, v1);
                    if (Ch) *(__half2*)(Ch + (size_t)r0 * ldch + c) = __floats2half2_rn(v0, v1);
                }
                if (r0 + 8 < M) {
                    if (Cf) *(float2*)(Cf + (size_t)(r0 + 8) * ldc + c) = make_float2(v2, v3);
                    if (Ch) *(__half2*)(Ch + (size_t)(r0 + 8) * ldch + c) = __floats2half2_rn(v2, v3);
                }
            } else {
                float cb0 = bias[c] + molb[c];
                float cb1 = bias[c + 1] + molb[c + 1];
                #pragma unroll
                for (int hh = 0; hh < 2; hh++) {
                    int r = r0 + hh * 8;
                    if (r >= M) continue;
                    float va = hh ? v2 : v0, vb = hh ? v3 : v1;
                    float z0 = 1.0f / (1.0f + __expf(-(va + cb0)));
                    float z1 = 1.0f / (1.0f + __expf(-(vb + cb1)));
                    float2 xv = __half22float2(*(const __half2*)(Ah + (size_t)r * lda + c));
                    float h0 = A2[(size_t)r * lda2 + c], h1 = A2[(size_t)r * lda2 + c + 1];
                    float o0 = z0 * xv.x + (1.0f - z0) * h0;
                    float o1 = z1 * xv.y + (1.0f - z1) * h1;
                    *(float2*)(Cf + (size_t)r * ldc + c) = make_float2(o0, o1);
                    if (Ch) *(__half2*)(Ch + (size_t)r * ldch + c) = __floats2half2_rn(o0, o1);
                }
            }
        }
    }
}

template <int ASRC, int EPI>
static void run_gemm(const void* A, int lda, int K1, const float* A2, int lda2,
                     const __half* B1, const __half* B2, int ldb, int SP, int KV1, int KV2,
                     float* Cf, int ldc, __half* Ch, int ldch,
                     int M, int N, int Ktot,
                     const float* bias, int relu, float scale, const float* molb) {
    dim3 grid(N / 128, (M + 127) / 128);
    gemm16_kernel<ASRC, EPI><<<grid, 256>>>(
        A, lda, K1, A2, lda2, B1, B2, ldb, SP, KV1, KV2,
        Cf, ldc, Ch, ldch, M, N, Ktot, bias, relu, scale, molb);
}

// ---------------- exact attention logits ----------------
__global__ void build_wv_kernel(const float* __restrict__ W, const float* __restrict__ as,
                                const float* __restrict__ ad) {
    int k = blockIdx.x, t = threadIdx.x;
    float w0 = W[(size_t)k * 512 + t], w1 = W[(size_t)k * 512 + 256 + t];
    float p0 = w0 * as[t], p1 = w1 * as[256 + t];
    float p2 = w0 * ad[t], p3 = w1 * ad[256 + t];
    __shared__ float red[8][4];
    int lane = t & 31, wid = t >> 5;
    #pragma unroll
    for (int d = 16; d; d >>= 1) {
        p0 += __shfl_down_sync(0xFFFFFFFFu, p0, d);
        p1 += __shfl_down_sync(0xFFFFFFFFu, p1, d);
        p2 += __shfl_down_sync(0xFFFFFFFFu, p2, d);
        p3 += __shfl_down_sync(0xFFFFFFFFu, p3, d);
    }
    if (lane == 0) { red[wid][0] = p0; red[wid][1] = p1; red[wid][2] = p2; red[wid][3] = p3; }
    __syncthreads();
    if (t == 0) {
        float r0 = 0, r1 = 0, r2 = 0, r3 = 0;
        #pragma unroll
        for (int w = 0; w < 8; w++) { r0 += red[w][0]; r1 += red[w][1]; r2 += red[w][2]; r3 += red[w][3]; }
        d_wv[k * 4 + 0] = r0; d_wv[k * 4 + 1] = r1; d_wv[k * 4 + 2] = r2; d_wv[k * 4 + 3] = r3;
    }
}

__global__ void attn2_kernel(const float* __restrict__ x, int K) {
    int warp = threadIdx.x >> 5, lane = threadIdx.x & 31;
    int n = blockIdx.x * 4 + warp;
    if (n >= NN) return;
    const float* xr = x + (size_t)n * K;
    float s0 = 0, s1 = 0, s2 = 0, s3 = 0;
    for (int c = lane; c < K; c += 32) {
        float xv = xr[c];
        float4 wv = ((const float4*)d_wv)[c];
        s0 += xv * wv.x; s1 += xv * wv.y; s2 += xv * wv.z; s3 += xv * wv.w;
    }
    #pragma unroll
    for (int d = 16; d; d >>= 1) {
        s0 += __shfl_down_sync(0xFFFFFFFFu, s0, d);
        s1 += __shfl_down_sync(0xFFFFFFFFu, s1, d);
        s2 += __shfl_down_sync(0xFFFFFFFFu, s2, d);
        s3 += __shfl_down_sync(0xFFFFFFFFu, s3, d);
    }
    if (lane == 0) {
        d_asrc[n * 2] = s0; d_asrc[n * 2 + 1] = s1;
        d_adst[n * 2] = s2; d_adst[n * 2 + 1] = s3;
    }
}

__device__ __forceinline__ float lrelu02(float v) { return v >= 0.0f ? v : 0.2f * v; }

// ---------------- fused online-softmax GAT aggregate ----------------
template <int BLOCK, int CH2, int NW>
__global__ void gat_fused_kernel(const __half2* __restrict__ src, int ldh2,
                                 __half2* __restrict__ agg, int lda2) {
    int n = blockIdx.x;
    int t = threadIdx.x;
    int lane = t & 31, wid = t >> 5;
    int s0 = csrA_off[n], s1 = csrA_off[n + 1];
    float2 adst = ((const float2*)d_adst)[n];

    __shared__ int ssrc[BLOCK];
    __shared__ float sp0[BLOCK], sp1[BLOCK];
    __shared__ float rm0[NW], rm1[NW];

    float m0 = -1e30f, m1 = -1e30f;
    float sum0 = 0.f, sum1 = 0.f;
    float a0x = 0.f, a0y = 0.f, a1x = 0.f, a1y = 0.f;
    bool act = t < CH2;

    for (int base = s0; base < s1; base += BLOCK) {
        int cnt = min(BLOCK, s1 - base);
        __syncthreads();
        float er0 = -1e30f, er1 = -1e30f;
        if (t < cnt) {
            int sidx = csrA_val[base + t];
            ssrc[t] = sidx;
            float2 as = ((const float2*)d_asrc)[sidx];
            er0 = lrelu02(as.x + adst.x);
            er1 = lrelu02(as.y + adst.y);
        }
        float e0 = er0, e1 = er1;
        #pragma unroll
        for (int d = 16; d; d >>= 1) {
            e0 = fmaxf(e0, __shfl_xor_sync(0xFFFFFFFFu, e0, d));
            e1 = fmaxf(e1, __shfl_xor_sync(0xFFFFFFFFu, e1, d));
        }
        if (lane == 0) { rm0[wid] = e0; rm1[wid] = e1; }
        __syncthreads();
        float cm0 = rm0[0], cm1 = rm1[0];
        #pragma unroll
        for (int w = 1; w < NW; w++) { cm0 = fmaxf(cm0, rm0[w]); cm1 = fmaxf(cm1, rm1[w]); }
        float nm0 = fmaxf(m0, cm0), nm1 = fmaxf(m1, cm1);
        float f0 = __expf(m0 - nm0), f1 = __expf(m1 - nm1);
        a0x *= f0; a0y *= f0; a1x *= f1; a1y *= f1;
        sum0 *= f0; sum1 *= f1;
        m0 = nm0; m1 = nm1;
        if (t < cnt) {
            sp0[t] = __expf(er0 - nm0);
            sp1[t] = __expf(er1 - nm1);
        }
        __syncthreads();
        if (act) {
            for (int j = 0; j < cnt; j++) {
                float p0 = sp0[j], p1 = sp1[j];
                sum0 += p0; sum1 += p1;
                float2 f = __half22float2(src[(size_t)ssrc[j] * ldh2 + t]);
                a0x += p0 * f.x; a0y += p0 * f.y;
                a1x += p1 * f.x; a1y += p1 * f.y;
            }
        } else {
            for (int j = 0; j < cnt; j++) { sum0 += sp0[j]; sum1 += sp1[j]; }
        }
    }
    if (act) {
        float r0 = 1.0f / sum0, r1 = 1.0f / sum1;
        agg[(size_t)n * lda2 + t] = __floats2half2_rn(a0x * r0, a0y * r0);
        agg[(size_t)n * lda2 + CH2 + t] = __floats2half2_rn(a1x * r1, a1y * r1);
    }
}

// ---------------- hypergraph ----------------
// which=0: group by dst via csrA (skip self at end), scale binv
// which=1: group by src via csrC, scale dinv
template <bool OUTH>
__global__ void hyper_gather_kernel(const __half2* __restrict__ in, void* __restrict__ outp,
                                    int ostride, const float* __restrict__ bias,
                                    int which, int relu) {
    const int* off = which ? csrC_off : csrA_off;
    const int* val = which ? csrC_val : csrA_val;
    int n = blockIdx.x;
    int t = threadIdx.x;  // 64
    int s0 = off[n], s1 = off[n + 1];
    if (!which) s1 -= 1;
    float ax = 0, ay = 0;
    __shared__ int sv[64];
    for (int base = s0; base < s1; base += 64) {
        int cnt = min(64, s1 - base);
        __syncthreads();
        if (t < cnt) sv[t] = val[base + t];
        __syncthreads();
        #pragma unroll 4
        for (int j = 0; j < cnt; j++) {
            float2 f = __half22float2(in[(size_t)sv[j] * 64 + t]);
            ax += f.x; ay += f.y;
        }
    }
    float inv = which ? d_dinv[n] : d_binv[n];
    ax *= inv; ay *= inv;
    if (bias) { ax += bias[t * 2]; ay += bias[t * 2 + 1]; }
    if (relu) { ax = fmaxf(ax, 0.f); ay = fmaxf(ay, 0.f); }
    if (OUTH) ((__half2*)outp)[(size_t)n * ostride + t] = __floats2half2_rn(ax, ay);
    else ((float2*)outp)[(size_t)n * ostride + t] = make_float2(ax, ay);
}

// ---------------- host side ----------------
extern "C" void kernel_launch(void* const* d_in, const int* in_sizes, int n_in,
                              void* d_out, int out_size) {
    const float* mol_x = (const float*)d_in[0];
    const int*   ei    = (const int*)d_in[1];
    const float* W1 = (const float*)d_in[3];
    const float* as1 = (const float*)d_in[4];
    const float* ad1 = (const float*)d_in[5];
    const float* b1 = (const float*)d_in[6];
    const float* W2 = (const float*)d_in[7];
    const float* as2 = (const float*)d_in[8];
    const float* ad2 = (const float*)d_in[9];
    const float* b2 = (const float*)d_in[10];
    const float* W3 = (const float*)d_in[11];
    const float* as3 = (const float*)d_in[12];
    const float* ad3 = (const float*)d_in[13];
    const float* b3 = (const float*)d_in[14];
    const float* fc1_w = (const float*)d_in[15];
    const float* fc1_b = (const float*)d_in[16];
    const float* fc2_w = (const float*)d_in[17];
    const float* fc2_b = (const float*)d_in[18];
    const float* mol_bias = (const float*)d_in[19];
    const float* theta1 = (const float*)d_in[20];
    const float* hb1 = (const float*)d_in[21];
    const float* theta2 = (const float*)d_in[22];
    const float* hb2 = (const float*)d_in[23];

    __half *p_mx, *p_catA, *p_catB, *p_agg, *p_xt, *p_ef, *p_hy16;
    __half *p_w1h, *p_w2h, *p_w3h, *p_bch, *p_th1h, *p_th2h;
    float *p_h, *p_g, *p_cb;
    cudaGetSymbolAddress((void**)&p_mx, d_mx16);
    cudaGetSymbolAddress((void**)&p_catA, d_catA);
    cudaGetSymbolAddress((void**)&p_catB, d_catB);
    cudaGetSymbolAddress((void**)&p_agg, d_agg);
    cudaGetSymbolAddress((void**)&p_xt, d_xt);
    cudaGetSymbolAddress((void**)&p_ef, d_ef);
    cudaGetSymbolAddress((void**)&p_hy16, d_hy16);
    cudaGetSymbolAddress((void**)&p_w1h, d_w1h);
    cudaGetSymbolAddress((void**)&p_w2h, d_w2h);
    cudaGetSymbolAddress((void**)&p_w3h, d_w3h);
    cudaGetSymbolAddress((void**)&p_bch, d_bch);
    cudaGetSymbolAddress((void**)&p_th1h, d_th1h);
    cudaGetSymbolAddress((void**)&p_th2h, d_th2h);
    cudaGetSymbolAddress((void**)&p_h, d_h);
    cudaGetSymbolAddress((void**)&p_g, d_g);
    cudaGetSymbolAddress((void**)&p_cb, d_cb);
    float* p_out = (float*)d_out;

    // ---- CSR build ----
    zero_counts_kernel<<<(NN + 255) / 256, 256>>>();
    count_kernel<<<(EE + 255) / 256, 256>>>(ei);
    scan2_kernel<<<2, 1024>>>();
    fill_kernel<<<(EE + 255) / 256, 256>>>(ei);

    // ---- conversions ----
    conv_mx_kernel<<<(NN * 40 + 255) / 256, 256>>>(mol_x);
    f2h_kernel<<<(FIN * 512 / 2 + 255) / 256, 256>>>(W1, p_w1h, FIN * 512 / 2);
    f2h_kernel<<<(256 * 512 / 2 + 255) / 256, 256>>>(W2, p_w2h, 256 * 512 / 2);
    f2h_kernel<<<(256 * 512 / 2 + 255) / 256, 256>>>(W3, p_w3h, 256 * 512 / 2);
    f2h_kernel<<<(334 * 128 / 2 + 255) / 256, 256>>>(theta1, p_th1h, 334 * 128 / 2);
    f2h_kernel<<<(128 * 128 / 2 + 255) / 256, 256>>>(theta2, p_th2h, 128 * 128 / 2);
    build_bc16_kernel<<<(512 * 256 + 255) / 256, 256>>>(fc1_w, fc2_w, fc1_b, fc2_b);

    // ---- GAT layer 1: h = relu(gat(mol_x)) ----
    build_wv_kernel<<<FIN, 256>>>(W1, as1, ad1);
    attn2_kernel<<<(NN + 3) / 4, 128>>>(mol_x, FIN);
    gat_fused_kernel<64, 40, 2><<<NN, 64>>>((const __half2*)p_mx, 40, (__half2*)p_agg, 80);
    run_gemm<2, 0>(p_agg, 160, 0, nullptr, 0, p_w1h, p_w1h + 256, 512, 80, FIN, FIN,
                   p_h, 256, p_catA + 256, 512, NN, 256, 160, b1, 1, 0.5f, nullptr);

    // ---- GAT layer 2 ----
    build_wv_kernel<<<256, 256>>>(W2, as2, ad2);
    attn2_kernel<<<(NN + 3) / 4, 128>>>(p_h, 256);
    gat_fused_kernel<128, 128, 4><<<NN, 128>>>((const __half2*)(p_catA + 256), 256,
                                               (__half2*)p_agg, 256);
    run_gemm<2, 0>(p_agg, 512, 0, nullptr, 0, p_w2h, p_w2h + 256, 512, 256, 256, 256,
                   nullptr, 0, p_catA, 512, NN, 256, 512, b2, 1, 0.5f, nullptr);
    run_gemm<2, 2>(p_catA, 512, 0, p_h /*Hin*/, 256, p_bch, nullptr, 256, 512, 512, 0,
                   p_g, 256, p_catB + 256, 512, NN, 256, 512, p_cb, 0, 1.0f, mol_bias);
    // h2 fp32 in d_g; fp16 in catB[256:)

    // ---- GAT layer 3 ----
    build_wv_kernel<<<256, 256>>>(W3, as3, ad3);
    attn2_kernel<<<(NN + 3) / 4, 128>>>(p_g, 256);
    gat_fused_kernel<128, 128, 4><<<NN, 128>>>((const __half2*)(p_catB + 256), 256,
                                               (__half2*)p_agg, 256);
    run_gemm<2, 0>(p_agg, 512, 0, nullptr, 0, p_w3h, p_w3h + 256, 512, 256, 256, 256,
                   nullptr, 0, p_catB, 512, NN, 256, 512, b3, 0, 0.5f, nullptr);
    run_gemm<2, 2>(p_catB, 512, 0, p_g /*Hin*/, 256, p_bch, nullptr, 256, 512, 512, 0,
                   p_out, 384, nullptr, 0, NN, 256, 512, p_cb, 0, 1.0f, mol_bias);
    // final h fp32 in d_out[:, 0:256)

    // ---- hypergraph branch ----
    run_gemm<0, 0>(p_out, 384, 256, mol_x, FIN, p_th1h, nullptr, 128, 334, 334, 0,
                   nullptr, 0, p_xt, 128, NN, 128, 334, nullptr, 0, 1.0f, nullptr);
    hyper_gather_kernel<true ><<<NN, 64>>>((const __half2*)p_xt, p_ef, 64, nullptr, 0, 0);
    hyper_gather_kernel<true ><<<NN, 64>>>((const __half2*)p_ef, p_hy16, 64, hb1, 1, 1);
    run_gemm<2, 0>(p_hy16, 128, 0, nullptr, 0, p_th2h, nullptr, 128, 128, 128, 0,
                   nullptr, 0, p_xt, 128, NN, 128, 128, nullptr, 0, 1.0f, nullptr);
    hyper_gather_kernel<true ><<<NN, 64>>>((const __half2*)p_xt, p_ef, 64, nullptr, 0, 0);
    hyper_gather_kernel<false><<<NN, 64>>>((const __half2*)p_ef, (float2*)p_out + 128, 192,
                                           hb2, 1, 1);
}

// round 8
// speedup vs baseline: 1.3618x; 1.3618x over previous
#include <cuda_runtime.h>
#include <cuda_fp16.h>
#include <math.h>
#include <stdint.h>

#define NN 100000
#define EE 3200000
#define EA (EE + NN)
#define FIN 78
#define FG 256
#define FH 128

// ---------------- scratch (device globals; no allocation) ----------------
__device__ __half d_mx16[(size_t)NN * 80];     // padded fp16 mol_x
__device__ __half d_catA[(size_t)NN * 512];    // [x | h] fp16 (layer2 view)
__device__ __half d_catB[(size_t)NN * 512];    // [x | h] fp16 (layer3 view)
__device__ __half d_agg[(size_t)NN * 512];     // aggregated features (2 heads)
__device__ float d_h [(size_t)NN * 256];       // fp32 h (layer1 out)
__device__ float d_g [(size_t)NN * 256];       // fp32 h (layer2 out)
__device__ __half d_xt[(size_t)NN * 128];
__device__ __half d_ef[(size_t)NN * 128];
__device__ __half d_hy16[(size_t)NN * 128];
// fp16 weights
__device__ __half d_w1h[FIN * 512];
__device__ __half d_w2h[256 * 512];
__device__ __half d_w3h[256 * 512];
__device__ __half d_bch[512 * 256];
__device__ __half d_th1h[334 * 128];
__device__ __half d_th2h[128 * 128];
__device__ float d_cb[256];
__device__ float d_wv[256 * 4];
__device__ float d_asrc[NN * 2];
__device__ float d_adst[NN * 2];
__device__ float2 d_alpha[EA];
__device__ int csrA_off[NN + 1]; __device__ int csrA_val[EA];
__device__ int csrC_off[NN + 1]; __device__ int csrC_val[EE];
__device__ int cntA[NN], cntC[NN];
__device__ int curA[NN], curC[NN];
__device__ float d_binv[NN], d_dinv[NN];

// ---------------- CSR construction ----------------
__global__ void zero_counts_kernel() {
    int i = blockIdx.x * blockDim.x + threadIdx.x;
    if (i < NN) { cntA[i] = 0; cntC[i] = 0; }
}

__global__ void count_kernel(const int* __restrict__ ei) {
    int i = blockIdx.x * blockDim.x + threadIdx.x;
    if (i >= EE) return;
    int s = ei[i];
    int d = ei[EE + i];
    atomicAdd(&cntA[d], 1);
    atomicAdd(&cntC[s], 1);
}

__global__ void scan2_kernel() {
    bool isA = (blockIdx.x == 0);
    const int* in = isA ? cntA : cntC;
    int* out = isA ? csrA_off : csrC_off;
    const int n = NN;
    __shared__ int wsum[32];
    __shared__ int carry;
    int tid = threadIdx.x, lane = tid & 31, wid = tid >> 5;
    if (tid == 0) carry = 0;
    __syncthreads();
    for (int base = 0; base < n; base += 1024) {
        int i = base + tid;
        int raw = (i < n) ? in[i] : 0;
        int v = raw + (isA ? ((i < n) ? 1 : 0) : 0);
        int x = v;
        #pragma unroll
        for (int d = 1; d < 32; d <<= 1) {
            int y = __shfl_up_sync(0xFFFFFFFFu, x, d);
            if (lane >= d) x += y;
        }
        if (lane == 31) wsum[wid] = x;
        __syncthreads();
        if (wid == 0) {
            int w = wsum[lane];
            #pragma unroll
            for (int d = 1; d < 32; d <<= 1) {
                int y = __shfl_up_sync(0xFFFFFFFFu, w, d);
                if (lane >= d) w += y;
            }
            wsum[lane] = w;
        }
        __syncthreads();
        int excl = carry + (wid ? wsum[wid - 1] : 0) + x - v;
        if (i < n) {
            out[i] = excl;
            if (isA) {
                curA[i] = excl;
                csrA_val[excl + raw] = i;  // self loop pinned at segment end
                d_binv[i] = raw > 0 ? 1.0f / (float)raw : 0.0f;
            } else {
                curC[i] = excl;
                d_dinv[i] = raw > 0 ? 1.0f / (float)raw : 0.0f;
            }
        }
        if (i == n - 1) out[n] = excl + v;
        __syncthreads();
        if (tid == 0) carry += wsum[31];
        __syncthreads();
    }
}

__global__ void fill_kernel(const int* __restrict__ ei) {
    int i = blockIdx.x * blockDim.x + threadIdx.x;
    if (i >= EE) return;
    int s = ei[i];
    int d = ei[EE + i];
    csrA_val[atomicAdd(&curA[d], 1)] = s;
    csrC_val[atomicAdd(&curC[s], 1)] = d;
}

// ---------------- weight conversion ----------------
__global__ void f2h_kernel(const float* __restrict__ src, __half* __restrict__ dst, int n2) {
    int i = blockIdx.x * blockDim.x + threadIdx.x;
    if (i < n2) {
        float2 v = ((const float2*)src)[i];
        ((__half2*)dst)[i] = __floats2half2_rn(v.x, v.y);
    }
}

__global__ void build_bc16_kernel(const float* __restrict__ fc1w, const float* __restrict__ fc2w,
                                  const float* __restrict__ fc1b, const float* __restrict__ fc2b) {
    int idx = blockIdx.x * blockDim.x + threadIdx.x;
    if (idx >= 512 * 256) return;
    int k = idx >> 8, n = idx & 255;
    float v = (k < 256) ? fc1w[n * 256 + k] : fc2w[n * 256 + (k - 256)];
    d_bch[idx] = __float2half_rn(v);
    if (idx < 256) d_cb[idx] = fc1b[idx] + fc2b[idx];
}

__global__ void conv_mx_kernel(const float* __restrict__ x) {
    int idx = blockIdx.x * blockDim.x + threadIdx.x;
    if (idx >= NN * 40) return;
    int n = idx / 40, c2 = idx % 40;
    float a = 0.f, b = 0.f;
    int c = c2 * 2;
    if (c < FIN) a = x[(size_t)n * FIN + c];
    if (c + 1 < FIN) b = x[(size_t)n * FIN + c + 1];
    ((__half2*)d_mx16)[idx] = __floats2half2_rn(a, b);
}

// ---------------- fp16 tensor-core GEMM (m16n8k16 + ldmatrix, pipelined) ----------------
__device__ __forceinline__ void mma_f16(float* c, const uint32_t* a, uint32_t b0, uint32_t b1) {
    asm volatile(
        "mma.sync.aligned.m16n8k16.row.col.f32.f16.f16.f32 "
        "{%0,%1,%2,%3},{%4,%5,%6,%7},{%8,%9},{%0,%1,%2,%3};"
        : "+f"(c[0]), "+f"(c[1]), "+f"(c[2]), "+f"(c[3])
        : "r"(a[0]), "r"(a[1]), "r"(a[2]), "r"(a[3]), "r"(b0), "r"(b1));
}

__device__ __forceinline__ void ldsm_x4(uint32_t& r0, uint32_t& r1, uint32_t& r2, uint32_t& r3,
                                        uint32_t addr) {
    asm volatile("ldmatrix.sync.aligned.m8n8.x4.shared.b16 {%0,%1,%2,%3}, [%4];"
                 : "=r"(r0), "=r"(r1), "=r"(r2), "=r"(r3) : "r"(addr));
}

__device__ __forceinline__ void ldsm_x4t(uint32_t& r0, uint32_t& r1, uint32_t& r2, uint32_t& r3,
                                         uint32_t addr) {
    asm volatile("ldmatrix.sync.aligned.m8n8.x4.trans.shared.b16 {%0,%1,%2,%3}, [%4];"
                 : "=r"(r0), "=r"(r1), "=r"(r2), "=r"(r3) : "r"(addr));
}

#define APITCH 80    // bytes per A row (32 halves + pad), 16B aligned
#define BPITCH 272   // bytes per B row (128 halves + pad), 16B aligned
#define ABYTES (128 * APITCH)
#define BBYTES (32 * BPITCH)

// ASRC: 0 = fp32 A (+optional concat A2), 2 = fp16 A dense
// EPI:  0 = v*scale+bias(+relu) -> optional fp32 Cf (ldc) and fp16 Ch (ldch)
//       2 = gate blend: z=sig(v+bias+molb); o=z*x(fp16 from A)+(1-z)*h(fp32 Hin=A2)
template <int ASRC, int EPI>
__global__ __launch_bounds__(256) void gemm16_kernel(
    const void* __restrict__ Ap, int lda, int K1,
    const float* __restrict__ A2, int lda2,
    const __half* __restrict__ B1, const __half* __restrict__ B2, int ldb,
    int SP, int KV1, int KV2,
    float* __restrict__ Cf, int ldc,
    __half* __restrict__ Ch, int ldch,
    int M, int N, int Ktot,
    const float* __restrict__ bias, int relu, float scale,
    const float* __restrict__ molb)
{
    __shared__ __align__(16) uint8_t AsmB[2 * ABYTES];
    __shared__ __align__(16) uint8_t BsmB[2 * BBYTES];
    int tid = threadIdx.x;
    int lane = tid & 31, wid = tid >> 5;
    int wm = wid & 3, wn = wid >> 2;
    int row0 = blockIdx.y * 128, col0 = blockIdx.x * 128;
    int g = lane >> 2, tg = lane & 3;
    int l15 = lane & 15;
    int lhi = (lane & 16) ? 8 : 0;

    float acc[2][8][4];
    #pragma unroll
    for (int mi = 0; mi < 2; mi++)
        #pragma unroll
        for (int ni = 0; ni < 8; ni++)
            #pragma unroll
            for (int q = 0; q < 4; q++) acc[mi][ni][q] = 0.0f;

    const float* Af = (const float*)Ap;
    const __half* Ah = (const __half*)Ap;

    float4 raf[4];
    uint2 rah[4];
    uint2 rbh[4];

    auto loadA = [&](int k0) {
        #pragma unroll
        for (int i = 0; i < 4; i++) {
            int l4 = tid + i * 256;
            int r = l4 >> 3, c4 = (l4 & 7) << 2;
            int grow = row0 + r, gk = k0 + c4;
            if (ASRC == 2) {
                uint2 u = make_uint2(0u, 0u);
                if (grow < M) u = *(const uint2*)(Ah + (size_t)grow * lda + gk);
                rah[i] = u;
            } else {
                float4 v = make_float4(0.f, 0.f, 0.f, 0.f);
                if (grow < M) {
                    if (gk + 3 < K1) {
                        v = *(const float4*)(Af + (size_t)grow * lda + gk);
                    } else {
                        float* pv = &v.x;
                        #pragma unroll
                        for (int j = 0; j < 4; j++) {
                            int kk = gk + j;
                            float x = 0.0f;
                            if (kk < K1) x = Af[(size_t)grow * lda + kk];
                            else if (kk < Ktot) x = A2[(size_t)grow * lda2 + (kk - K1)];
                            pv[j] = x;
                        }
                    }
                }
                raf[i] = v;
            }
        }
    };
    auto storeA = [&](uint8_t* As) {
        #pragma unroll
        for (int i = 0; i < 4; i++) {
            int l4 = tid + i * 256;
            int r = l4 >> 3, c4 = (l4 & 7) << 2;
            uint2 u;
            if (ASRC == 2) {
                u = rah[i];
            } else {
                __half2 h0 = __floats2half2_rn(raf[i].x, raf[i].y);
                __half2 h1 = __floats2half2_rn(raf[i].z, raf[i].w);
                u.x = *(uint32_t*)&h0;
                u.y = *(uint32_t*)&h1;
            }
            *(uint2*)(As + r * APITCH + c4 * 2) = u;
        }
    };
    auto loadB = [&](int k0) {
        #pragma unroll
        for (int i = 0; i < 4; i++) {
            int l4 = tid + i * 256;
            int k = l4 >> 5, n4 = (l4 & 31) << 2;
            int kk = k0 + k;
            uint2 u = make_uint2(0u, 0u);
            if (kk < SP) {
                if (kk < KV1) u = *(const uint2*)(B1 + (size_t)kk * ldb + col0 + n4);
            } else if (kk < Ktot) {
                int j = kk - SP;
                if (j < KV2) u = *(const uint2*)(B2 + (size_t)j * ldb + col0 + n4);
            }
            rbh[i] = u;
        }
    };
    auto storeB = [&](uint8_t* Bs) {
        #pragma unroll
        for (int i = 0; i < 4; i++) {
            int l4 = tid + i * 256;
            int k = l4 >> 5, n4 = (l4 & 31) << 2;
            *(uint2*)(Bs + k * BPITCH + n4 * 2) = rbh[i];
        }
    };

    uint32_t aShm = (uint32_t)__cvta_generic_to_shared(AsmB);
    uint32_t bShm = (uint32_t)__cvta_generic_to_shared(BsmB);

    int T = (Ktot + 31) >> 5;
    loadA(0); loadB(0);
    storeA(AsmB); storeB(BsmB);
    __syncthreads();

    for (int t = 0; t < T; t++) {
        int buf = t & 1;
        bool more = (t + 1 < T);
        if (more) { loadA((t + 1) << 5); loadB((t + 1) << 5); }
        uint32_t aB = aShm + buf * ABYTES;
        uint32_t bB = bShm + buf * BBYTES;
        #pragma unroll
        for (int ks = 0; ks < 2; ks++) {
            uint32_t afr[2][4];
            #pragma unroll
            for (int mi = 0; mi < 2; mi++) {
                uint32_t addr = aB + (uint32_t)((wm * 32 + mi * 16 + l15) * APITCH
                                                + (ks * 16 + lhi) * 2);
                ldsm_x4(afr[mi][0], afr[mi][1], afr[mi][2], afr[mi][3], addr);
            }
            uint32_t bfr[8][2];
            #pragma unroll
            for (int p = 0; p < 4; p++) {
                uint32_t addr = bB + (uint32_t)((ks * 16 + l15) * BPITCH
                                                + (wn * 64 + p * 16 + lhi) * 2);
                ldsm_x4t(bfr[2 * p][0], bfr[2 * p][1], bfr[2 * p + 1][0], bfr[2 * p + 1][1], addr);
            }
            #pragma unroll
            for (int ni = 0; ni < 8; ni++) {
                mma_f16(acc[0][ni], afr[0], bfr[ni][0], bfr[ni][1]);
                mma_f16(acc[1][ni], afr[1], bfr[ni][0], bfr[ni][1]);
            }
        }
        if (more) {
            storeA(AsmB + (buf ^ 1) * ABYTES);
            storeB(BsmB + (buf ^ 1) * BBYTES);
        }
        __syncthreads();
    }

    // epilogue
    #pragma unroll
    for (int mi = 0; mi < 2; mi++) {
        int r0 = row0 + wm * 32 + mi * 16 + g;
        #pragma unroll
        for (int ni = 0; ni < 8; ni++) {
            int c = col0 + wn * 64 + ni * 8 + tg * 2;
            float v0 = acc[mi][ni][0], v1 = acc[mi][ni][1];
            float v2 = acc[mi][ni][2], v3 = acc[mi][ni][3];
            if (EPI == 0) {
                float b0v = bias ? bias[c] : 0.0f;
                float b1v = bias ? bias[c + 1] : 0.0f;
                v0 = v0 * scale + b0v; v1 = v1 * scale + b1v;
                v2 = v2 * scale + b0v; v3 = v3 * scale + b1v;
                if (relu) {
                    v0 = fmaxf(v0, 0.f); v1 = fmaxf(v1, 0.f);
                    v2 = fmaxf(v2, 0.f); v3 = fmaxf(v3, 0.f);
                }
                if (r0 < M) {
                    if (Cf) *(float2*)(Cf + (size_t)r0 * ldc + c) = make_float2(v0, v1);
                    if (Ch) *(__half2*)(Ch + (size_t)r0 * ldch + c) = __floats2half2_rn(v0, v1);
                }
                if (r0 + 8 < M) {
                    if (Cf) *(float2*)(Cf + (size_t)(r0 + 8) * ldc + c) = make_float2(v2, v3);
                    if (Ch) *(__half2*)(Ch + (size_t)(r0 + 8) * ldch + c) = __floats2half2_rn(v2, v3);
                }
            } else {
                float cb0 = bias[c] + molb[c];
                float cb1 = bias[c + 1] + molb[c + 1];
                #pragma unroll
                for (int hh = 0; hh < 2; hh++) {
                    int r = r0 + hh * 8;
                    if (r >= M) continue;
                    float va = hh ? v2 : v0, vb = hh ? v3 : v1;
                    float z0 = 1.0f / (1.0f + __expf(-(va + cb0)));
                    float z1 = 1.0f / (1.0f + __expf(-(vb + cb1)));
                    float2 xv = __half22float2(*(const __half2*)(Ah + (size_t)r * lda + c));
                    float h0 = A2[(size_t)r * lda2 + c], h1 = A2[(size_t)r * lda2 + c + 1];
                    float o0 = z0 * xv.x + (1.0f - z0) * h0;
                    float o1 = z1 * xv.y + (1.0f - z1) * h1;
                    *(float2*)(Cf + (size_t)r * ldc + c) = make_float2(o0, o1);
                    if (Ch) *(__half2*)(Ch + (size_t)r * ldch + c) = __floats2half2_rn(o0, o1);
                }
            }
        }
    }
}

template <int ASRC, int EPI>
static void run_gemm(const void* A, int lda, int K1, const float* A2, int lda2,
                     const __half* B1, const __half* B2, int ldb, int SP, int KV1, int KV2,
                     float* Cf, int ldc, __half* Ch, int ldch,
                     int M, int N, int Ktot,
                     const float* bias, int relu, float scale, const float* molb) {
    dim3 grid(N / 128, (M + 127) / 128);
    gemm16_kernel<ASRC, EPI><<<grid, 256>>>(
        A, lda, K1, A2, lda2, B1, B2, ldb, SP, KV1, KV2,
        Cf, ldc, Ch, ldch, M, N, Ktot, bias, relu, scale, molb);
}

// ---------------- exact attention logits ----------------
__global__ void build_wv_kernel(const float* __restrict__ W, const float* __restrict__ as,
                                const float* __restrict__ ad) {
    int k = blockIdx.x, t = threadIdx.x;
    float w0 = W[(size_t)k * 512 + t], w1 = W[(size_t)k * 512 + 256 + t];
    float p0 = w0 * as[t], p1 = w1 * as[256 + t];
    float p2 = w0 * ad[t], p3 = w1 * ad[256 + t];
    __shared__ float red[8][4];
    int lane = t & 31, wid = t >> 5;
    #pragma unroll
    for (int d = 16; d; d >>= 1) {
        p0 += __shfl_down_sync(0xFFFFFFFFu, p0, d);
        p1 += __shfl_down_sync(0xFFFFFFFFu, p1, d);
        p2 += __shfl_down_sync(0xFFFFFFFFu, p2, d);
        p3 += __shfl_down_sync(0xFFFFFFFFu, p3, d);
    }
    if (lane == 0) { red[wid][0] = p0; red[wid][1] = p1; red[wid][2] = p2; red[wid][3] = p3; }
    __syncthreads();
    if (t == 0) {
        float r0 = 0, r1 = 0, r2 = 0, r3 = 0;
        #pragma unroll
        for (int w = 0; w < 8; w++) { r0 += red[w][0]; r1 += red[w][1]; r2 += red[w][2]; r3 += red[w][3]; }
        d_wv[k * 4 + 0] = r0; d_wv[k * 4 + 1] = r1; d_wv[k * 4 + 2] = r2; d_wv[k * 4 + 3] = r3;
    }
}

__global__ void attn2_kernel(const float* __restrict__ x, int K) {
    int warp = threadIdx.x >> 5, lane = threadIdx.x & 31;
    int n = blockIdx.x * 4 + warp;
    if (n >= NN) return;
    const float* xr = x + (size_t)n * K;
    float s0 = 0, s1 = 0, s2 = 0, s3 = 0;
    for (int c = lane; c < K; c += 32) {
        float xv = xr[c];
        float4 wv = ((const float4*)d_wv)[c];
        s0 += xv * wv.x; s1 += xv * wv.y; s2 += xv * wv.z; s3 += xv * wv.w;
    }
    #pragma unroll
    for (int d = 16; d; d >>= 1) {
        s0 += __shfl_down_sync(0xFFFFFFFFu, s0, d);
        s1 += __shfl_down_sync(0xFFFFFFFFu, s1, d);
        s2 += __shfl_down_sync(0xFFFFFFFFu, s2, d);
        s3 += __shfl_down_sync(0xFFFFFFFFu, s3, d);
    }
    if (lane == 0) {
        d_asrc[n * 2] = s0; d_asrc[n * 2 + 1] = s1;
        d_adst[n * 2] = s2; d_adst[n * 2 + 1] = s3;
    }
}

__device__ __forceinline__ float lrelu02(float v) { return v >= 0.0f ? v : 0.2f * v; }

// warp per destination node: segment softmax over csrA, writes alpha (float2)
__global__ void softmax_kernel() {
    int n = blockIdx.x * (blockDim.x >> 5) + (threadIdx.x >> 5);
    int lane = threadIdx.x & 31;
    if (n >= NN) return;
    int s0 = csrA_off[n], s1 = csrA_off[n + 1];
    float ad0 = d_adst[n * 2], ad1 = d_adst[n * 2 + 1];
    float m0 = -1e30f, m1 = -1e30f;
    for (int p = s0 + lane; p < s1; p += 32) {
        int src = csrA_val[p];
        float e0 = lrelu02(d_asrc[src * 2] + ad0);
        float e1 = lrelu02(d_asrc[src * 2 + 1] + ad1);
        m0 = fmaxf(m0, e0); m1 = fmaxf(m1, e1);
    }
    #pragma unroll
    for (int d = 16; d; d >>= 1) {
        m0 = fmaxf(m0, __shfl_xor_sync(0xFFFFFFFFu, m0, d));
        m1 = fmaxf(m1, __shfl_xor_sync(0xFFFFFFFFu, m1, d));
    }
    float sum0 = 0.0f, sum1 = 0.0f;
    for (int p = s0 + lane; p < s1; p += 32) {
        int src = csrA_val[p];
        float e0 = lrelu02(d_asrc[src * 2] + ad0);
        float e1 = lrelu02(d_asrc[src * 2 + 1] + ad1);
        float x0 = __expf(e0 - m0), x1 = __expf(e1 - m1);
        d_alpha[p] = make_float2(x0, x1);
        sum0 += x0; sum1 += x1;
    }
    #pragma unroll
    for (int d = 16; d; d >>= 1) {
        sum0 += __shfl_xor_sync(0xFFFFFFFFu, sum0, d);
        sum1 += __shfl_xor_sync(0xFFFFFFFFu, sum1, d);
    }
    float r0 = 1.0f / sum0, r1 = 1.0f / sum1;
    for (int p = s0 + lane; p < s1; p += 32) {
        float2 a = d_alpha[p];
        a.x *= r0; a.y *= r1;
        d_alpha[p] = a;
    }
}

// block per destination node: aggregate raw features with precomputed alpha
template <int BLOCK, int CH2>
__global__ void gat_aggregate_kernel(const __half2* __restrict__ src, int ldh2,
                                     __half2* __restrict__ agg, int lda2) {
    int n = blockIdx.x;
    int t = threadIdx.x;
    int s0 = csrA_off[n], s1 = csrA_off[n + 1];
    float a0x = 0, a0y = 0, a1x = 0, a1y = 0;
    __shared__ int ssrc[BLOCK];
    __shared__ float2 salp[BLOCK];
    bool act = t < CH2;
    for (int base = s0; base < s1; base += BLOCK) {
        int cnt = min(BLOCK, s1 - base);
        __syncthreads();
        if (t < cnt) { ssrc[t] = csrA_val[base + t]; salp[t] = d_alpha[base + t]; }
        __syncthreads();
        if (act) {
            #pragma unroll 2
            for (int j = 0; j < cnt; j++) {
                float2 f = __half22float2(src[(size_t)ssrc[j] * ldh2 + t]);
                float2 a = salp[j];
                a0x += a.x * f.x; a0y += a.x * f.y;
                a1x += a.y * f.x; a1y += a.y * f.y;
            }
        }
    }
    if (act) {
        agg[(size_t)n * lda2 + t] = __floats2half2_rn(a0x, a0y);
        agg[(size_t)n * lda2 + CH2 + t] = __floats2half2_rn(a1x, a1y);
    }
}

// ---------------- hypergraph ----------------
// which=0: group by dst via csrA (skip self at end), scale binv
// which=1: group by src via csrC, scale dinv
template <bool OUTH>
__global__ void hyper_gather_kernel(const __half2* __restrict__ in, void* __restrict__ outp,
                                    int ostride, const float* __restrict__ bias,
                                    int which, int relu) {
    const int* off = which ? csrC_off : csrA_off;
    const int* val = which ? csrC_val : csrA_val;
    int n = blockIdx.x;
    int t = threadIdx.x;  // 64
    int s0 = off[n], s1 = off[n + 1];
    if (!which) s1 -= 1;
    float ax = 0, ay = 0;
    __shared__ int sv[64];
    for (int base = s0; base < s1; base += 64) {
        int cnt = min(64, s1 - base);
        __syncthreads();
        if (t < cnt) sv[t] = val[base + t];
        __syncthreads();
        #pragma unroll 4
        for (int j = 0; j < cnt; j++) {
            float2 f = __half22float2(in[(size_t)sv[j] * 64 + t]);
            ax += f.x; ay += f.y;
        }
    }
    float inv = which ? d_dinv[n] : d_binv[n];
    ax *= inv; ay *= inv;
    if (bias) { ax += bias[t * 2]; ay += bias[t * 2 + 1]; }
    if (relu) { ax = fmaxf(ax, 0.f); ay = fmaxf(ay, 0.f); }
    if (OUTH) ((__half2*)outp)[(size_t)n * ostride + t] = __floats2half2_rn(ax, ay);
    else ((float2*)outp)[(size_t)n * ostride + t] = make_float2(ax, ay);
}

// ---------------- host side ----------------
extern "C" void kernel_launch(void* const* d_in, const int* in_sizes, int n_in,
                              void* d_out, int out_size) {
    const float* mol_x = (const float*)d_in[0];
    const int*   ei    = (const int*)d_in[1];
    const float* W1 = (const float*)d_in[3];
    const float* as1 = (const float*)d_in[4];
    const float* ad1 = (const float*)d_in[5];
    const float* b1 = (const float*)d_in[6];
    const float* W2 = (const float*)d_in[7];
    const float* as2 = (const float*)d_in[8];
    const float* ad2 = (const float*)d_in[9];
    const float* b2 = (const float*)d_in[10];
    const float* W3 = (const float*)d_in[11];
    const float* as3 = (const float*)d_in[12];
    const float* ad3 = (const float*)d_in[13];
    const float* b3 = (const float*)d_in[14];
    const float* fc1_w = (const float*)d_in[15];
    const float* fc1_b = (const float*)d_in[16];
    const float* fc2_w = (const float*)d_in[17];
    const float* fc2_b = (const float*)d_in[18];
    const float* mol_bias = (const float*)d_in[19];
    const float* theta1 = (const float*)d_in[20];
    const float* hb1 = (const float*)d_in[21];
    const float* theta2 = (const float*)d_in[22];
    const float* hb2 = (const float*)d_in[23];

    __half *p_mx, *p_catA, *p_catB, *p_agg, *p_xt, *p_ef, *p_hy16;
    __half *p_w1h, *p_w2h, *p_w3h, *p_bch, *p_th1h, *p_th2h;
    float *p_h, *p_g, *p_cb;
    cudaGetSymbolAddress((void**)&p_mx, d_mx16);
    cudaGetSymbolAddress((void**)&p_catA, d_catA);
    cudaGetSymbolAddress((void**)&p_catB, d_catB);
    cudaGetSymbolAddress((void**)&p_agg, d_agg);
    cudaGetSymbolAddress((void**)&p_xt, d_xt);
    cudaGetSymbolAddress((void**)&p_ef, d_ef);
    cudaGetSymbolAddress((void**)&p_hy16, d_hy16);
    cudaGetSymbolAddress((void**)&p_w1h, d_w1h);
    cudaGetSymbolAddress((void**)&p_w2h, d_w2h);
    cudaGetSymbolAddress((void**)&p_w3h, d_w3h);
    cudaGetSymbolAddress((void**)&p_bch, d_bch);
    cudaGetSymbolAddress((void**)&p_th1h, d_th1h);
    cudaGetSymbolAddress((void**)&p_th2h, d_th2h);
    cudaGetSymbolAddress((void**)&p_h, d_h);
    cudaGetSymbolAddress((void**)&p_g, d_g);
    cudaGetSymbolAddress((void**)&p_cb, d_cb);
    float* p_out = (float*)d_out;

    // ---- CSR build ----
    zero_counts_kernel<<<(NN + 255) / 256, 256>>>();
    count_kernel<<<(EE + 255) / 256, 256>>>(ei);
    scan2_kernel<<<2, 1024>>>();
    fill_kernel<<<(EE + 255) / 256, 256>>>(ei);

    // ---- conversions ----
    conv_mx_kernel<<<(NN * 40 + 255) / 256, 256>>>(mol_x);
    f2h_kernel<<<(FIN * 512 / 2 + 255) / 256, 256>>>(W1, p_w1h, FIN * 512 / 2);
    f2h_kernel<<<(256 * 512 / 2 + 255) / 256, 256>>>(W2, p_w2h, 256 * 512 / 2);
    f2h_kernel<<<(256 * 512 / 2 + 255) / 256, 256>>>(W3, p_w3h, 256 * 512 / 2);
    f2h_kernel<<<(334 * 128 / 2 + 255) / 256, 256>>>(theta1, p_th1h, 334 * 128 / 2);
    f2h_kernel<<<(128 * 128 / 2 + 255) / 256, 256>>>(theta2, p_th2h, 128 * 128 / 2);
    build_bc16_kernel<<<(512 * 256 + 255) / 256, 256>>>(fc1_w, fc2_w, fc1_b, fc2_b);

    // ---- GAT layer 1: h = relu(gat(mol_x)) ----
    build_wv_kernel<<<FIN, 256>>>(W1, as1, ad1);
    attn2_kernel<<<(NN + 3) / 4, 128>>>(mol_x, FIN);
    softmax_kernel<<<(NN + 7) / 8, 256>>>();
    gat_aggregate_kernel<64, 40><<<NN, 64>>>((const __half2*)p_mx, 40, (__half2*)p_agg, 80);
    run_gemm<2, 0>(p_agg, 160, 0, nullptr, 0, p_w1h, p_w1h + 256, 512, 80, FIN, FIN,
                   p_h, 256, p_catA + 256, 512, NN, 256, 160, b1, 1, 0.5f, nullptr);

    // ---- GAT layer 2 ----
    build_wv_kernel<<<256, 256>>>(W2, as2, ad2);
    attn2_kernel<<<(NN + 3) / 4, 128>>>(p_h, 256);
    softmax_kernel<<<(NN + 7) / 8, 256>>>();
    gat_aggregate_kernel<128, 128><<<NN, 128>>>((const __half2*)(p_catA + 256), 256,
                                                (__half2*)p_agg, 256);
    run_gemm<2, 0>(p_agg, 512, 0, nullptr, 0, p_w2h, p_w2h + 256, 512, 256, 256, 256,
                   nullptr, 0, p_catA, 512, NN, 256, 512, b2, 1, 0.5f, nullptr);
    run_gemm<2, 2>(p_catA, 512, 0, p_h /*Hin*/, 256, p_bch, nullptr, 256, 512, 512, 0,
                   p_g, 256, p_catB + 256, 512, NN, 256, 512, p_cb, 0, 1.0f, mol_bias);
    // h2 fp32 in d_g; fp16 in catB[256:)

    // ---- GAT layer 3 ----
    build_wv_kernel<<<256, 256>>>(W3, as3, ad3);
    attn2_kernel<<<(NN + 3) / 4, 128>>>(p_g, 256);
    softmax_kernel<<<(NN + 7) / 8, 256>>>();
    gat_aggregate_kernel<128, 128><<<NN, 128>>>((const __half2*)(p_catB + 256), 256,
                                                (__half2*)p_agg, 256);
    run_gemm<2, 0>(p_agg, 512, 0, nullptr, 0, p_w3h, p_w3h + 256, 512, 256, 256, 256,
                   nullptr, 0, p_catB, 512, NN, 256, 512, b3, 0, 0.5f, nullptr);
    run_gemm<2, 2>(p_catB, 512, 0, p_g /*Hin*/, 256, p_bch, nullptr, 256, 512, 512, 0,
                   p_out, 384, nullptr, 0, NN, 256, 512, p_cb, 0, 1.0f, mol_bias);
    // final h fp32 in d_out[:, 0:256)

    // ---- hypergraph branch ----
    run_gemm<0, 0>(p_out, 384, 256, mol_x, FIN, p_th1h, nullptr, 128, 334, 334, 0,
                   nullptr, 0, p_xt, 128, NN, 128, 334, nullptr, 0, 1.0f, nullptr);
    hyper_gather_kernel<true ><<<NN, 64>>>((const __half2*)p_xt, p_ef, 64, nullptr, 0, 0);
    hyper_gather_kernel<true ><<<NN, 64>>>((const __half2*)p_ef, p_hy16, 64, hb1, 1, 1);
    run_gemm<2, 0>(p_hy16, 128, 0, nullptr, 0, p_th2h, nullptr, 128, 128, 128, 0,
                   nullptr, 0, p_xt, 128, NN, 128, 128, nullptr, 0, 1.0f, nullptr);
    hyper_gather_kernel<true ><<<NN, 64>>>((const __half2*)p_xt, p_ef, 64, nullptr, 0, 0);
    hyper_gather_kernel<false><<<NN, 64>>>((const __half2*)p_ef, (float2*)p_out + 128, 192,
                                           hb2, 1, 1);
}

// round 9
// speedup vs baseline: 1.3675x; 1.0042x over previous
#include <cuda_runtime.h>
#include <cuda_fp16.h>
#include <math.h>
#include <stdint.h>

#define NN 100000
#define EE 3200000
#define EA (EE + NN)
#define FIN 78
#define FG 256
#define FH 128

// ---------------- scratch (device globals; no allocation) ----------------
__device__ __half d_mx16[(size_t)NN * 80];
__device__ __half d_catA[(size_t)NN * 512];
__device__ __half d_catB[(size_t)NN * 512];
__device__ __half d_agg[(size_t)NN * 512];
__device__ float d_h [(size_t)NN * 256];
__device__ float d_g [(size_t)NN * 256];
__device__ __half d_xt[(size_t)NN * 128];
__device__ __half d_ef[(size_t)NN * 128];
__device__ __half d_hy16[(size_t)NN * 128];
__device__ __half d_w1h[FIN * 512];
__device__ __half d_w2h[256 * 512];
__device__ __half d_w3h[256 * 512];
__device__ __half d_bch[512 * 256];
__device__ __half d_th1h[334 * 128];
__device__ __half d_th2h[128 * 128];
__device__ float d_cb[256];
__device__ float d_wv[256 * 4];
__device__ float d_asrc[NN * 2];
__device__ float d_adst[NN * 2];
__device__ float2 d_alpha[EA];
__device__ int csrA_off[NN + 1]; __device__ int csrA_val[EA];
__device__ int csrC_off[NN + 1]; __device__ int csrC_val[EE];
__device__ int cntA[NN], cntC[NN];
__device__ int curA[NN], curC[NN];
__device__ float d_binv[NN], d_dinv[NN];

// ---------------- CSR construction ----------------
__global__ void zero_counts_kernel() {
    int i = blockIdx.x * blockDim.x + threadIdx.x;
    if (i < NN) { cntA[i] = 0; cntC[i] = 0; }
}

__global__ void count_kernel(const int* __restrict__ ei) {
    int i = blockIdx.x * blockDim.x + threadIdx.x;
    if (i >= EE) return;
    int s = ei[i];
    int d = ei[EE + i];
    atomicAdd(&cntA[d], 1);
    atomicAdd(&cntC[s], 1);
}

__global__ void scan2_kernel() {
    bool isA = (blockIdx.x == 0);
    const int* in = isA ? cntA : cntC;
    int* out = isA ? csrA_off : csrC_off;
    const int n = NN;
    __shared__ int wsum[32];
    __shared__ int carry;
    int tid = threadIdx.x, lane = tid & 31, wid = tid >> 5;
    if (tid == 0) carry = 0;
    __syncthreads();
    for (int base = 0; base < n; base += 1024) {
        int i = base + tid;
        int raw = (i < n) ? in[i] : 0;
        int v = raw + (isA ? ((i < n) ? 1 : 0) : 0);
        int x = v;
        #pragma unroll
        for (int d = 1; d < 32; d <<= 1) {
            int y = __shfl_up_sync(0xFFFFFFFFu, x, d);
            if (lane >= d) x += y;
        }
        if (lane == 31) wsum[wid] = x;
        __syncthreads();
        if (wid == 0) {
            int w = wsum[lane];
            #pragma unroll
            for (int d = 1; d < 32; d <<= 1) {
                int y = __shfl_up_sync(0xFFFFFFFFu, w, d);
                if (lane >= d) w += y;
            }
            wsum[lane] = w;
        }
        __syncthreads();
        int excl = carry + (wid ? wsum[wid - 1] : 0) + x - v;
        if (i < n) {
            out[i] = excl;
            if (isA) {
                curA[i] = excl;
                csrA_val[excl + raw] = i;
                d_binv[i] = raw > 0 ? 1.0f / (float)raw : 0.0f;
            } else {
                curC[i] = excl;
                d_dinv[i] = raw > 0 ? 1.0f / (float)raw : 0.0f;
            }
        }
        if (i == n - 1) out[n] = excl + v;
        __syncthreads();
        if (tid == 0) carry += wsum[31];
        __syncthreads();
    }
}

__global__ void fill_kernel(const int* __restrict__ ei) {
    int i = blockIdx.x * blockDim.x + threadIdx.x;
    if (i >= EE) return;
    int s = ei[i];
    int d = ei[EE + i];
    csrA_val[atomicAdd(&curA[d], 1)] = s;
    csrC_val[atomicAdd(&curC[s], 1)] = d;
}

// ---------------- weight conversion ----------------
__global__ void f2h_kernel(const float* __restrict__ src, __half* __restrict__ dst, int n2) {
    int i = blockIdx.x * blockDim.x + threadIdx.x;
    if (i < n2) {
        float2 v = ((const float2*)src)[i];
        ((__half2*)dst)[i] = __floats2half2_rn(v.x, v.y);
    }
}

__global__ void build_bc16_kernel(const float* __restrict__ fc1w, const float* __restrict__ fc2w,
                                  const float* __restrict__ fc1b, const float* __restrict__ fc2b) {
    int idx = blockIdx.x * blockDim.x + threadIdx.x;
    if (idx >= 512 * 256) return;
    int k = idx >> 8, n = idx & 255;
    float v = (k < 256) ? fc1w[n * 256 + k] : fc2w[n * 256 + (k - 256)];
    d_bch[idx] = __float2half_rn(v);
    if (idx < 256) d_cb[idx] = fc1b[idx] + fc2b[idx];
}

__global__ void conv_mx_kernel(const float* __restrict__ x) {
    int idx = blockIdx.x * blockDim.x + threadIdx.x;
    if (idx >= NN * 40) return;
    int n = idx / 40, c2 = idx % 40;
    float a = 0.f, b = 0.f;
    int c = c2 * 2;
    if (c < FIN) a = x[(size_t)n * FIN + c];
    if (c + 1 < FIN) b = x[(size_t)n * FIN + c + 1];
    ((__half2*)d_mx16)[idx] = __floats2half2_rn(a, b);
}

// ---------------- fp16 tensor-core GEMM (m16n8k16 + ldmatrix, pipelined) ----------------
__device__ __forceinline__ void mma_f16(float* c, const uint32_t* a, uint32_t b0, uint32_t b1) {
    asm volatile(
        "mma.sync.aligned.m16n8k16.row.col.f32.f16.f16.f32 "
        "{%0,%1,%2,%3},{%4,%5,%6,%7},{%8,%9},{%0,%1,%2,%3};"
        : "+f"(c[0]), "+f"(c[1]), "+f"(c[2]), "+f"(c[3])
        : "r"(a[0]), "r"(a[1]), "r"(a[2]), "r"(a[3]), "r"(b0), "r"(b1));
}

__device__ __forceinline__ void ldsm_x4(uint32_t& r0, uint32_t& r1, uint32_t& r2, uint32_t& r3,
                                        uint32_t addr) {
    asm volatile("ldmatrix.sync.aligned.m8n8.x4.shared.b16 {%0,%1,%2,%3}, [%4];"
                 : "=r"(r0), "=r"(r1), "=r"(r2), "=r"(r3) : "r"(addr));
}

__device__ __forceinline__ void ldsm_x4t(uint32_t& r0, uint32_t& r1, uint32_t& r2, uint32_t& r3,
                                         uint32_t addr) {
    asm volatile("ldmatrix.sync.aligned.m8n8.x4.trans.shared.b16 {%0,%1,%2,%3}, [%4];"
                 : "=r"(r0), "=r"(r1), "=r"(r2), "=r"(r3) : "r"(addr));
}

#define APITCH 80
#define BPITCH 272
#define ABYTES (128 * APITCH)
#define BBYTES (32 * BPITCH)

// ASRC: 0 = fp32 A (+optional concat A2), 2 = fp16 A dense
// EPI:  0 = v*scale+bias(+relu) -> optional fp32 Cf and fp16 Ch
//       2 = gate blend
template <int ASRC, int EPI>
__global__ __launch_bounds__(256) void gemm16_kernel(
    const void* __restrict__ Ap, int lda, int K1,
    const float* __restrict__ A2, int lda2,
    const __half* __restrict__ B1, const __half* __restrict__ B2, int ldb,
    int SP, int KV1, int KV2,
    float* __restrict__ Cf, int ldc,
    __half* __restrict__ Ch, int ldch,
    int M, int N, int Ktot,
    const float* __restrict__ bias, int relu, float scale,
    const float* __restrict__ molb)
{
    __shared__ __align__(16) uint8_t AsmB[2 * ABYTES];
    __shared__ __align__(16) uint8_t BsmB[2 * BBYTES];
    int tid = threadIdx.x;
    int lane = tid & 31, wid = tid >> 5;
    int wm = wid & 3, wn = wid >> 2;
    int row0 = blockIdx.y * 128, col0 = blockIdx.x * 128;
    int g = lane >> 2, tg = lane & 3;
    int l15 = lane & 15;
    int lhi = (lane & 16) ? 8 : 0;

    float acc[2][8][4];
    #pragma unroll
    for (int mi = 0; mi < 2; mi++)
        #pragma unroll
        for (int ni = 0; ni < 8; ni++)
            #pragma unroll
            for (int q = 0; q < 4; q++) acc[mi][ni][q] = 0.0f;

    const float* Af = (const float*)Ap;
    const __half* Ah = (const __half*)Ap;

    float4 raf[4];
    uint2 rah[4];
    uint2 rbh[4];

    auto loadA = [&](int k0) {
        #pragma unroll
        for (int i = 0; i < 4; i++) {
            int l4 = tid + i * 256;
            int r = l4 >> 3, c4 = (l4 & 7) << 2;
            int grow = row0 + r, gk = k0 + c4;
            if (ASRC == 2) {
                uint2 u = make_uint2(0u, 0u);
                if (grow < M) u = *(const uint2*)(Ah + (size_t)grow * lda + gk);
                rah[i] = u;
            } else {
                float4 v = make_float4(0.f, 0.f, 0.f, 0.f);
                if (grow < M) {
                    if (gk + 3 < K1) {
                        v = *(const float4*)(Af + (size_t)grow * lda + gk);
                    } else {
                        float* pv = &v.x;
                        #pragma unroll
                        for (int j = 0; j < 4; j++) {
                            int kk = gk + j;
                            float x = 0.0f;
                            if (kk < K1) x = Af[(size_t)grow * lda + kk];
                            else if (kk < Ktot) x = A2[(size_t)grow * lda2 + (kk - K1)];
                            pv[j] = x;
                        }
                    }
                }
                raf[i] = v;
            }
        }
    };
    auto storeA = [&](uint8_t* As) {
        #pragma unroll
        for (int i = 0; i < 4; i++) {
            int l4 = tid + i * 256;
            int r = l4 >> 3, c4 = (l4 & 7) << 2;
            uint2 u;
            if (ASRC == 2) {
                u = rah[i];
            } else {
                __half2 h0 = __floats2half2_rn(raf[i].x, raf[i].y);
                __half2 h1 = __floats2half2_rn(raf[i].z, raf[i].w);
                u.x = *(uint32_t*)&h0;
                u.y = *(uint32_t*)&h1;
            }
            *(uint2*)(As + r * APITCH + c4 * 2) = u;
        }
    };
    auto loadB = [&](int k0) {
        #pragma unroll
        for (int i = 0; i < 4; i++) {
            int l4 = tid + i * 256;
            int k = l4 >> 5, n4 = (l4 & 31) << 2;
            int kk = k0 + k;
            uint2 u = make_uint2(0u, 0u);
            if (kk < SP) {
                if (kk < KV1) u = *(const uint2*)(B1 + (size_t)kk * ldb + col0 + n4);
            } else if (kk < Ktot) {
                int j = kk - SP;
                if (j < KV2) u = *(const uint2*)(B2 + (size_t)j * ldb + col0 + n4);
            }
            rbh[i] = u;
        }
    };
    auto storeB = [&](uint8_t* Bs) {
        #pragma unroll
        for (int i = 0; i < 4; i++) {
            int l4 = tid + i * 256;
            int k = l4 >> 5, n4 = (l4 & 31) << 2;
            *(uint2*)(Bs + k * BPITCH + n4 * 2) = rbh[i];
        }
    };

    uint32_t aShm = (uint32_t)__cvta_generic_to_shared(AsmB);
    uint32_t bShm = (uint32_t)__cvta_generic_to_shared(BsmB);

    int T = (Ktot + 31) >> 5;
    loadA(0); loadB(0);
    storeA(AsmB); storeB(BsmB);
    __syncthreads();

    for (int t = 0; t < T; t++) {
        int buf = t & 1;
        bool more = (t + 1 < T);
        if (more) { loadA((t + 1) << 5); loadB((t + 1) << 5); }
        uint32_t aB = aShm + buf * ABYTES;
        uint32_t bB = bShm + buf * BBYTES;
        #pragma unroll
        for (int ks = 0; ks < 2; ks++) {
            uint32_t afr[2][4];
            #pragma unroll
            for (int mi = 0; mi < 2; mi++) {
                uint32_t addr = aB + (uint32_t)((wm * 32 + mi * 16 + l15) * APITCH
                                                + (ks * 16 + lhi) * 2);
                ldsm_x4(afr[mi][0], afr[mi][1], afr[mi][2], afr[mi][3], addr);
            }
            uint32_t bfr[8][2];
            #pragma unroll
            for (int p = 0; p < 4; p++) {
                uint32_t addr = bB + (uint32_t)((ks * 16 + l15) * BPITCH
                                                + (wn * 64 + p * 16 + lhi) * 2);
                ldsm_x4t(bfr[2 * p][0], bfr[2 * p][1], bfr[2 * p + 1][0], bfr[2 * p + 1][1], addr);
            }
            #pragma unroll
            for (int ni = 0; ni < 8; ni++) {
                mma_f16(acc[0][ni], afr[0], bfr[ni][0], bfr[ni][1]);
                mma_f16(acc[1][ni], afr[1], bfr[ni][0], bfr[ni][1]);
            }
        }
        if (more) {
            storeA(AsmB + (buf ^ 1) * ABYTES);
            storeB(BsmB + (buf ^ 1) * BBYTES);
        }
        __syncthreads();
    }

    // epilogue
    #pragma unroll
    for (int mi = 0; mi < 2; mi++) {
        int r0 = row0 + wm * 32 + mi * 16 + g;
        #pragma unroll
        for (int ni = 0; ni < 8; ni++) {
            int c = col0 + wn * 64 + ni * 8 + tg * 2;
            float v0 = acc[mi][ni][0], v1 = acc[mi][ni][1];
            float v2 = acc[mi][ni][2], v3 = acc[mi][ni][3];
            if (EPI == 0) {
                float b0v = bias ? bias[c] : 0.0f;
                float b1v = bias ? bias[c + 1] : 0.0f;
                v0 = v0 * scale + b0v; v1 = v1 * scale + b1v;
                v2 = v2 * scale + b0v; v3 = v3 * scale + b1v;
                if (relu) {
                    v0 = fmaxf(v0, 0.f); v1 = fmaxf(v1, 0.f);
                    v2 = fmaxf(v2, 0.f); v3 = fmaxf(v3, 0.f);
                }
                if (r0 < M) {
                    if (Cf) *(float2*)(Cf + (size_t)r0 * ldc + c) = make_float2(v0, v1);
                    if (Ch) *(__half2*)(Ch + (size_t)r0 * ldch + c) = __floats2half2_rn(v0, v1);
                }
                if (r0 + 8 < M) {
                    if (Cf) *(float2*)(Cf + (size_t)(r0 + 8) * ldc + c) = make_float2(v2, v3);
                    if (Ch) *(__half2*)(Ch + (size_t)(r0 + 8) * ldch + c) = __floats2half2_rn(v2, v3);
                }
            } else {
                float cb0 = bias[c] + molb[c];
                float cb1 = bias[c + 1] + molb[c + 1];
                #pragma unroll
                for (int hh = 0; hh < 2; hh++) {
                    int r = r0 + hh * 8;
                    if (r >= M) continue;
                    float va = hh ? v2 : v0, vb = hh ? v3 : v1;
                    float z0 = 1.0f / (1.0f + __expf(-(va + cb0)));
                    float z1 = 1.0f / (1.0f + __expf(-(vb + cb1)));
                    float2 xv = __half22float2(*(const __half2*)(Ah + (size_t)r * lda + c));
                    float h0 = A2[(size_t)r * lda2 + c], h1 = A2[(size_t)r * lda2 + c + 1];
                    float o0 = z0 * xv.x + (1.0f - z0) * h0;
                    float o1 = z1 * xv.y + (1.0f - z1) * h1;
                    *(float2*)(Cf + (size_t)r * ldc + c) = make_float2(o0, o1);
                    if (Ch) *(__half2*)(Ch + (size_t)r * ldch + c) = __floats2half2_rn(o0, o1);
                }
            }
        }
    }
}

template <int ASRC, int EPI>
static void run_gemm(const void* A, int lda, int K1, const float* A2, int lda2,
                     const __half* B1, const __half* B2, int ldb, int SP, int KV1, int KV2,
                     float* Cf, int ldc, __half* Ch, int ldch,
                     int M, int N, int Ktot,
                     const float* bias, int relu, float scale, const float* molb) {
    dim3 grid(N / 128, (M + 127) / 128);
    gemm16_kernel<ASRC, EPI><<<grid, 256>>>(
        A, lda, K1, A2, lda2, B1, B2, ldb, SP, KV1, KV2,
        Cf, ldc, Ch, ldch, M, N, Ktot, bias, relu, scale, molb);
}

// ---------------- exact attention logits ----------------
__global__ void build_wv_kernel(const float* __restrict__ W, const float* __restrict__ as,
                                const float* __restrict__ ad) {
    int k = blockIdx.x, t = threadIdx.x;
    float w0 = W[(size_t)k * 512 + t], w1 = W[(size_t)k * 512 + 256 + t];
    float p0 = w0 * as[t], p1 = w1 * as[256 + t];
    float p2 = w0 * ad[t], p3 = w1 * ad[256 + t];
    __shared__ float red[8][4];
    int lane = t & 31, wid = t >> 5;
    #pragma unroll
    for (int d = 16; d; d >>= 1) {
        p0 += __shfl_down_sync(0xFFFFFFFFu, p0, d);
        p1 += __shfl_down_sync(0xFFFFFFFFu, p1, d);
        p2 += __shfl_down_sync(0xFFFFFFFFu, p2, d);
        p3 += __shfl_down_sync(0xFFFFFFFFu, p3, d);
    }
    if (lane == 0) { red[wid][0] = p0; red[wid][1] = p1; red[wid][2] = p2; red[wid][3] = p3; }
    __syncthreads();
    if (t == 0) {
        float r0 = 0, r1 = 0, r2 = 0, r3 = 0;
        #pragma unroll
        for (int w = 0; w < 8; w++) { r0 += red[w][0]; r1 += red[w][1]; r2 += red[w][2]; r3 += red[w][3]; }
        d_wv[k * 4 + 0] = r0; d_wv[k * 4 + 1] = r1; d_wv[k * 4 + 2] = r2; d_wv[k * 4 + 3] = r3;
    }
}

__global__ void attn2_kernel(const float* __restrict__ x, int K) {
    int warp = threadIdx.x >> 5, lane = threadIdx.x & 31;
    int n = blockIdx.x * 4 + warp;
    if (n >= NN) return;
    const float* xr = x + (size_t)n * K;
    float s0 = 0, s1 = 0, s2 = 0, s3 = 0;
    for (int c = lane; c < K; c += 32) {
        float xv = xr[c];
        float4 wv = ((const float4*)d_wv)[c];
        s0 += xv * wv.x; s1 += xv * wv.y; s2 += xv * wv.z; s3 += xv * wv.w;
    }
    #pragma unroll
    for (int d = 16; d; d >>= 1) {
        s0 += __shfl_down_sync(0xFFFFFFFFu, s0, d);
        s1 += __shfl_down_sync(0xFFFFFFFFu, s1, d);
        s2 += __shfl_down_sync(0xFFFFFFFFu, s2, d);
        s3 += __shfl_down_sync(0xFFFFFFFFu, s3, d);
    }
    if (lane == 0) {
        d_asrc[n * 2] = s0; d_asrc[n * 2 + 1] = s1;
        d_adst[n * 2] = s2; d_adst[n * 2 + 1] = s3;
    }
}

__device__ __forceinline__ float lrelu02(float v) { return v >= 0.0f ? v : 0.2f * v; }

// warp per destination node: segment softmax over csrA, writes alpha (float2)
__global__ void softmax_kernel() {
    int n = blockIdx.x * (blockDim.x >> 5) + (threadIdx.x >> 5);
    int lane = threadIdx.x & 31;
    if (n >= NN) return;
    int s0 = csrA_off[n], s1 = csrA_off[n + 1];
    float ad0 = d_adst[n * 2], ad1 = d_adst[n * 2 + 1];
    float m0 = -1e30f, m1 = -1e30f;
    for (int p = s0 + lane; p < s1; p += 32) {
        int src = csrA_val[p];
        float e0 = lrelu02(d_asrc[src * 2] + ad0);
        float e1 = lrelu02(d_asrc[src * 2 + 1] + ad1);
        m0 = fmaxf(m0, e0); m1 = fmaxf(m1, e1);
    }
    #pragma unroll
    for (int d = 16; d; d >>= 1) {
        m0 = fmaxf(m0, __shfl_xor_sync(0xFFFFFFFFu, m0, d));
        m1 = fmaxf(m1, __shfl_xor_sync(0xFFFFFFFFu, m1, d));
    }
    float sum0 = 0.0f, sum1 = 0.0f;
    for (int p = s0 + lane; p < s1; p += 32) {
        int src = csrA_val[p];
        float e0 = lrelu02(d_asrc[src * 2] + ad0);
        float e1 = lrelu02(d_asrc[src * 2 + 1] + ad1);
        float x0 = __expf(e0 - m0), x1 = __expf(e1 - m1);
        d_alpha[p] = make_float2(x0, x1);
        sum0 += x0; sum1 += x1;
    }
    #pragma unroll
    for (int d = 16; d; d >>= 1) {
        sum0 += __shfl_xor_sync(0xFFFFFFFFu, sum0, d);
        sum1 += __shfl_xor_sync(0xFFFFFFFFu, sum1, d);
    }
    float r0 = 1.0f / sum0, r1 = 1.0f / sum1;
    for (int p = s0 + lane; p < s1; p += 32) {
        float2 a = d_alpha[p];
        a.x *= r0; a.y *= r1;
        d_alpha[p] = a;
    }
}

// layer-1 aggregate (40 half2 rows): original one-group form
template <int BLOCK, int CH2>
__global__ void gat_aggregate_kernel(const __half2* __restrict__ src, int ldh2,
                                     __half2* __restrict__ agg, int lda2) {
    int n = blockIdx.x;
    int t = threadIdx.x;
    int s0 = csrA_off[n], s1 = csrA_off[n + 1];
    float a0x = 0, a0y = 0, a1x = 0, a1y = 0;
    __shared__ int ssrc[BLOCK];
    __shared__ float2 salp[BLOCK];
    bool act = t < CH2;
    for (int base = s0; base < s1; base += BLOCK) {
        int cnt = min(BLOCK, s1 - base);
        __syncthreads();
        if (t < cnt) { ssrc[t] = csrA_val[base + t]; salp[t] = d_alpha[base + t]; }
        __syncthreads();
        if (act) {
            #pragma unroll 2
            for (int j = 0; j < cnt; j++) {
                float2 f = __half22float2(src[(size_t)ssrc[j] * ldh2 + t]);
                float2 a = salp[j];
                a0x += a.x * f.x; a0y += a.x * f.y;
                a1x += a.y * f.x; a1y += a.y * f.y;
            }
        }
    }
    if (act) {
        agg[(size_t)n * lda2 + t] = __floats2half2_rn(a0x, a0y);
        agg[(size_t)n * lda2 + CH2 + t] = __floats2half2_rn(a1x, a1y);
    }
}

// layer-2/3 aggregate: 128 threads = 2 edge-groups of 64, uint2 (8B) loads.
// src row = 128 half2 (stride ldh2), agg row = 256 half2 (head0 | head1).
__global__ void gat_agg256_kernel(const __half2* __restrict__ src, int ldh2,
                                  __half2* __restrict__ agg) {
    int n = blockIdx.x;
    int t = threadIdx.x;            // 128
    int gid = t >> 6, tl = t & 63;  // group, lane-in-group
    int s0 = csrA_off[n], s1 = csrA_off[n + 1];
    float h0[4] = {0, 0, 0, 0}, h1[4] = {0, 0, 0, 0};
    __shared__ int ssrc[128];
    __shared__ float2 salp[128];
    __shared__ float red[64][8];
    for (int base = s0; base < s1; base += 128) {
        int cnt = min(128, s1 - base);
        __syncthreads();
        if (t < cnt) { ssrc[t] = csrA_val[base + t]; salp[t] = d_alpha[base + t]; }
        __syncthreads();
        for (int j = gid; j < cnt; j += 2) {
            uint2 u = *(const uint2*)(src + (size_t)ssrc[j] * ldh2 + tl * 2);
            float2 g0 = __half22float2(*(__half2*)&u.x);
            float2 g1 = __half22float2(*(__half2*)&u.y);
            float2 a = salp[j];
            h0[0] += a.x * g0.x; h0[1] += a.x * g0.y; h0[2] += a.x * g1.x; h0[3] += a.x * g1.y;
            h1[0] += a.y * g0.x; h1[1] += a.y * g0.y; h1[2] += a.y * g1.x; h1[3] += a.y * g1.y;
        }
    }
    __syncthreads();
    if (gid == 1) {
        red[tl][0] = h0[0]; red[tl][1] = h0[1]; red[tl][2] = h0[2]; red[tl][3] = h0[3];
        red[tl][4] = h1[0]; red[tl][5] = h1[1]; red[tl][6] = h1[2]; red[tl][7] = h1[3];
    }
    __syncthreads();
    if (gid == 0) {
        h0[0] += red[tl][0]; h0[1] += red[tl][1]; h0[2] += red[tl][2]; h0[3] += red[tl][3];
        h1[0] += red[tl][4]; h1[1] += red[tl][5]; h1[2] += red[tl][6]; h1[3] += red[tl][7];
        __half2* row = agg + (size_t)n * 256;
        row[tl * 2] = __floats2half2_rn(h0[0], h0[1]);
        row[tl * 2 + 1] = __floats2half2_rn(h0[2], h0[3]);
        row[128 + tl * 2] = __floats2half2_rn(h1[0], h1[1]);
        row[128 + tl * 2 + 1] = __floats2half2_rn(h1[2], h1[3]);
    }
}

// ---------------- hypergraph ----------------
// 64 threads = 2 edge-groups of 32, uint2 loads. row = 64 half2.
// which=0: csrA (skip self at end), binv; which=1: csrC, dinv
template <bool OUTH>
__global__ void hyper_gather_kernel(const __half2* __restrict__ in, void* __restrict__ outp,
                                    int ostride, const float* __restrict__ bias,
                                    int which, int relu) {
    const int* off = which ? csrC_off : csrA_off;
    const int* val = which ? csrC_val : csrA_val;
    int n = blockIdx.x;
    int t = threadIdx.x;            // 64
    int gid = t >> 5, tl = t & 31;
    int s0 = off[n], s1 = off[n + 1];
    if (!which) s1 -= 1;
    float a[4] = {0, 0, 0, 0};
    __shared__ int sv[64];
    __shared__ float red[32][4];
    for (int base = s0; base < s1; base += 64) {
        int cnt = min(64, s1 - base);
        __syncthreads();
        if (t < cnt) sv[t] = val[base + t];
        __syncthreads();
        for (int j = gid; j < cnt; j += 2) {
            uint2 u = *(const uint2*)(in + (size_t)sv[j] * 64 + tl * 2);
            float2 g0 = __half22float2(*(__half2*)&u.x);
            float2 g1 = __half22float2(*(__half2*)&u.y);
            a[0] += g0.x; a[1] += g0.y; a[2] += g1.x; a[3] += g1.y;
        }
    }
    __syncthreads();
    if (gid == 1) { red[tl][0] = a[0]; red[tl][1] = a[1]; red[tl][2] = a[2]; red[tl][3] = a[3]; }
    __syncthreads();
    if (gid == 0) {
        a[0] += red[tl][0]; a[1] += red[tl][1]; a[2] += red[tl][2]; a[3] += red[tl][3];
        float inv = which ? d_dinv[n] : d_binv[n];
        #pragma unroll
        for (int q = 0; q < 4; q++) a[q] *= inv;
        if (bias) {
            a[0] += bias[tl * 4]; a[1] += bias[tl * 4 + 1];
            a[2] += bias[tl * 4 + 2]; a[3] += bias[tl * 4 + 3];
        }
        if (relu) {
            #pragma unroll
            for (int q = 0; q < 4; q++) a[q] = fmaxf(a[q], 0.f);
        }
        if (OUTH) {
            __half2* o = (__half2*)outp;
            o[(size_t)n * ostride + tl * 2] = __floats2half2_rn(a[0], a[1]);
            o[(size_t)n * ostride + tl * 2 + 1] = __floats2half2_rn(a[2], a[3]);
        } else {
            float2* o = (float2*)outp;
            o[(size_t)n * ostride + tl * 2] = make_float2(a[0], a[1]);
            o[(size_t)n * ostride + tl * 2 + 1] = make_float2(a[2], a[3]);
        }
    }
}

// ---------------- host side ----------------
extern "C" void kernel_launch(void* const* d_in, const int* in_sizes, int n_in,
                              void* d_out, int out_size) {
    const float* mol_x = (const float*)d_in[0];
    const int*   ei    = (const int*)d_in[1];
    const float* W1 = (const float*)d_in[3];
    const float* as1 = (const float*)d_in[4];
    const float* ad1 = (const float*)d_in[5];
    const float* b1 = (const float*)d_in[6];
    const float* W2 = (const float*)d_in[7];
    const float* as2 = (const float*)d_in[8];
    const float* ad2 = (const float*)d_in[9];
    const float* b2 = (const float*)d_in[10];
    const float* W3 = (const float*)d_in[11];
    const float* as3 = (const float*)d_in[12];
    const float* ad3 = (const float*)d_in[13];
    const float* b3 = (const float*)d_in[14];
    const float* fc1_w = (const float*)d_in[15];
    const float* fc1_b = (const float*)d_in[16];
    const float* fc2_w = (const float*)d_in[17];
    const float* fc2_b = (const float*)d_in[18];
    const float* mol_bias = (const float*)d_in[19];
    const float* theta1 = (const float*)d_in[20];
    const float* hb1 = (const float*)d_in[21];
    const float* theta2 = (const float*)d_in[22];
    const float* hb2 = (const float*)d_in[23];

    __half *p_mx, *p_catA, *p_catB, *p_agg, *p_xt, *p_ef, *p_hy16;
    __half *p_w1h, *p_w2h, *p_w3h, *p_bch, *p_th1h, *p_th2h;
    float *p_h, *p_g, *p_cb;
    cudaGetSymbolAddress((void**)&p_mx, d_mx16);
    cudaGetSymbolAddress((void**)&p_catA, d_catA);
    cudaGetSymbolAddress((void**)&p_catB, d_catB);
    cudaGetSymbolAddress((void**)&p_agg, d_agg);
    cudaGetSymbolAddress((void**)&p_xt, d_xt);
    cudaGetSymbolAddress((void**)&p_ef, d_ef);
    cudaGetSymbolAddress((void**)&p_hy16, d_hy16);
    cudaGetSymbolAddress((void**)&p_w1h, d_w1h);
    cudaGetSymbolAddress((void**)&p_w2h, d_w2h);
    cudaGetSymbolAddress((void**)&p_w3h, d_w3h);
    cudaGetSymbolAddress((void**)&p_bch, d_bch);
    cudaGetSymbolAddress((void**)&p_th1h, d_th1h);
    cudaGetSymbolAddress((void**)&p_th2h, d_th2h);
    cudaGetSymbolAddress((void**)&p_h, d_h);
    cudaGetSymbolAddress((void**)&p_g, d_g);
    cudaGetSymbolAddress((void**)&p_cb, d_cb);
    float* p_out = (float*)d_out;

    // ---- CSR build ----
    zero_counts_kernel<<<(NN + 255) / 256, 256>>>();
    count_kernel<<<(EE + 255) / 256, 256>>>(ei);
    scan2_kernel<<<2, 1024>>>();
    fill_kernel<<<(EE + 255) / 256, 256>>>(ei);

    // ---- conversions ----
    conv_mx_kernel<<<(NN * 40 + 255) / 256, 256>>>(mol_x);
    f2h_kernel<<<(FIN * 512 / 2 + 255) / 256, 256>>>(W1, p_w1h, FIN * 512 / 2);
    f2h_kernel<<<(256 * 512 / 2 + 255) / 256, 256>>>(W2, p_w2h, 256 * 512 / 2);
    f2h_kernel<<<(256 * 512 / 2 + 255) / 256, 256>>>(W3, p_w3h, 256 * 512 / 2);
    f2h_kernel<<<(334 * 128 / 2 + 255) / 256, 256>>>(theta1, p_th1h, 334 * 128 / 2);
    f2h_kernel<<<(128 * 128 / 2 + 255) / 256, 256>>>(theta2, p_th2h, 128 * 128 / 2);
    build_bc16_kernel<<<(512 * 256 + 255) / 256, 256>>>(fc1_w, fc2_w, fc1_b, fc2_b);

    // ---- GAT layer 1: h = relu(gat(mol_x)) ----
    build_wv_kernel<<<FIN, 256>>>(W1, as1, ad1);
    attn2_kernel<<<(NN + 3) / 4, 128>>>(mol_x, FIN);
    softmax_kernel<<<(NN + 7) / 8, 256>>>();
    gat_aggregate_kernel<64, 40><<<NN, 64>>>((const __half2*)p_mx, 40, (__half2*)p_agg, 80);
    run_gemm<2, 0>(p_agg, 160, 0, nullptr, 0, p_w1h, p_w1h + 256, 512, 80, FIN, FIN,
                   p_h, 256, p_catA + 256, 512, NN, 256, 160, b1, 1, 0.5f, nullptr);

    // ---- GAT layer 2 ----
    build_wv_kernel<<<256, 256>>>(W2, as2, ad2);
    attn2_kernel<<<(NN + 3) / 4, 128>>>(p_h, 256);
    softmax_kernel<<<(NN + 7) / 8, 256>>>();
    gat_agg256_kernel<<<NN, 128>>>((const __half2*)(p_catA + 256), 256, (__half2*)p_agg);
    run_gemm<2, 0>(p_agg, 512, 0, nullptr, 0, p_w2h, p_w2h + 256, 512, 256, 256, 256,
                   nullptr, 0, p_catA, 512, NN, 256, 512, b2, 1, 0.5f, nullptr);
    run_gemm<2, 2>(p_catA, 512, 0, p_h, 256, p_bch, nullptr, 256, 512, 512, 0,
                   p_g, 256, p_catB + 256, 512, NN, 256, 512, p_cb, 0, 1.0f, mol_bias);

    // ---- GAT layer 3 ----
    build_wv_kernel<<<256, 256>>>(W3, as3, ad3);
    attn2_kernel<<<(NN + 3) / 4, 128>>>(p_g, 256);
    softmax_kernel<<<(NN + 7) / 8, 256>>>();
    gat_agg256_kernel<<<NN, 128>>>((const __half2*)(p_catB + 256), 256, (__half2*)p_agg);
    run_gemm<2, 0>(p_agg, 512, 0, nullptr, 0, p_w3h, p_w3h + 256, 512, 256, 256, 256,
                   nullptr, 0, p_catB, 512, NN, 256, 512, b3, 0, 0.5f, nullptr);
    run_gemm<2, 2>(p_catB, 512, 0, p_g, 256, p_bch, nullptr, 256, 512, 512, 0,
                   p_out, 384, nullptr, 0, NN, 256, 512, p_cb, 0, 1.0f, mol_bias);

    // ---- hypergraph branch ----
    run_gemm<0, 0>(p_out, 384, 256, mol_x, FIN, p_th1h, nullptr, 128, 334, 334, 0,
                   nullptr, 0, p_xt, 128, NN, 128, 334, nullptr, 0, 1.0f, nullptr);
    hyper_gather_kernel<true ><<<NN, 64>>>((const __half2*)p_xt, p_ef, 64, nullptr, 0, 0);
    hyper_gather_kernel<true ><<<NN, 64>>>((const __half2*)p_ef, p_hy16, 64, hb1, 1, 1);
    run_gemm<2, 0>(p_hy16, 128, 0, nullptr, 0, p_th2h, nullptr, 128, 128, 128, 0,
                   nullptr, 0, p_xt, 128, NN, 128, 128, nullptr, 0, 1.0f, nullptr);
    hyper_gather_kernel<true ><<<NN, 64>>>((const __half2*)p_xt, p_ef, 64, nullptr, 0, 0);
    hyper_gather_kernel<false><<<NN, 64>>>((const __half2*)p_ef, (float2*)p_out + 128, 192,
                                           hb2, 1, 1);
}

// round 10
// speedup vs baseline: 1.4444x; 1.0563x over previous
#include <cuda_runtime.h>
#include <cuda_fp16.h>
#include <math.h>
#include <stdint.h>

#define NN 100000
#define EE 3200000
#define EA (EE + NN)
#define FIN 78
#define FG 256
#define FH 128

// ---------------- scratch (device globals; no allocation) ----------------
__device__ __half d_mx16[(size_t)NN * 80];
__device__ __half d_catA[(size_t)NN * 512];   // [x1 | h1]
__device__ __half d_catB[(size_t)NN * 512];   // [x2 | h2]
__device__ __half d_agg[(size_t)NN * 512];
__device__ __half d_xt[(size_t)NN * 128];
__device__ __half d_ef[(size_t)NN * 128];
__device__ __half d_hy16[(size_t)NN * 128];
__device__ __half d_w1h[FIN * 512];
__device__ __half d_w2h[256 * 512];
__device__ __half d_w3h[256 * 512];
__device__ __half d_bch[512 * 256];
__device__ __half d_th1h[334 * 128];
__device__ __half d_th2h[128 * 128];
__device__ float d_cb[256];
__device__ float d_wv[256 * 4];
__device__ float d_asrc[NN * 2];
__device__ float d_adst[NN * 2];
__device__ float2 d_rsum[NN];
__device__ float2 d_alpha[EA];
__device__ int csrA_off[NN + 1]; __device__ int csrA_val[EA];
__device__ int csrC_off[NN + 1]; __device__ int csrC_val[EE];
__device__ int cntA[NN], cntC[NN];
__device__ int curA[NN], curC[NN];
__device__ float d_binv[NN], d_dinv[NN];

// ---------------- CSR construction ----------------
__global__ void zero_counts_kernel() {
    int i = blockIdx.x * blockDim.x + threadIdx.x;
    if (i < NN) { cntA[i] = 0; cntC[i] = 0; }
}

__global__ void count_kernel(const int* __restrict__ ei) {
    int i = blockIdx.x * blockDim.x + threadIdx.x;
    if (i >= EE) return;
    int s = ei[i];
    int d = ei[EE + i];
    atomicAdd(&cntA[d], 1);
    atomicAdd(&cntC[s], 1);
}

__global__ void scan2_kernel() {
    bool isA = (blockIdx.x == 0);
    const int* in = isA ? cntA : cntC;
    int* out = isA ? csrA_off : csrC_off;
    const int n = NN;
    __shared__ int wsum[32];
    __shared__ int carry;
    int tid = threadIdx.x, lane = tid & 31, wid = tid >> 5;
    if (tid == 0) carry = 0;
    __syncthreads();
    for (int base = 0; base < n; base += 1024) {
        int i = base + tid;
        int raw = (i < n) ? in[i] : 0;
        int v = raw + (isA ? ((i < n) ? 1 : 0) : 0);
        int x = v;
        #pragma unroll
        for (int d = 1; d < 32; d <<= 1) {
            int y = __shfl_up_sync(0xFFFFFFFFu, x, d);
            if (lane >= d) x += y;
        }
        if (lane == 31) wsum[wid] = x;
        __syncthreads();
        if (wid == 0) {
            int w = wsum[lane];
            #pragma unroll
            for (int d = 1; d < 32; d <<= 1) {
                int y = __shfl_up_sync(0xFFFFFFFFu, w, d);
                if (lane >= d) w += y;
            }
            wsum[lane] = w;
        }
        __syncthreads();
        int excl = carry + (wid ? wsum[wid - 1] : 0) + x - v;
        if (i < n) {
            out[i] = excl;
            if (isA) {
                curA[i] = excl;
                csrA_val[excl + raw] = i;
                d_binv[i] = raw > 0 ? 1.0f / (float)raw : 0.0f;
            } else {
                curC[i] = excl;
                d_dinv[i] = raw > 0 ? 1.0f / (float)raw : 0.0f;
            }
        }
        if (i == n - 1) out[n] = excl + v;
        __syncthreads();
        if (tid == 0) carry += wsum[31];
        __syncthreads();
    }
}

__global__ void fill_kernel(const int* __restrict__ ei) {
    int i = blockIdx.x * blockDim.x + threadIdx.x;
    if (i >= EE) return;
    int s = ei[i];
    int d = ei[EE + i];
    csrA_val[atomicAdd(&curA[d], 1)] = s;
    csrC_val[atomicAdd(&curC[s], 1)] = d;
}

// ---------------- weight conversion ----------------
__global__ void f2h_kernel(const float* __restrict__ src, __half* __restrict__ dst, int n2) {
    int i = blockIdx.x * blockDim.x + threadIdx.x;
    if (i < n2) {
        float2 v = ((const float2*)src)[i];
        ((__half2*)dst)[i] = __floats2half2_rn(v.x, v.y);
    }
}

__global__ void build_bc16_kernel(const float* __restrict__ fc1w, const float* __restrict__ fc2w,
                                  const float* __restrict__ fc1b, const float* __restrict__ fc2b) {
    int idx = blockIdx.x * blockDim.x + threadIdx.x;
    if (idx >= 512 * 256) return;
    int k = idx >> 8, n = idx & 255;
    float v = (k < 256) ? fc1w[n * 256 + k] : fc2w[n * 256 + (k - 256)];
    d_bch[idx] = __float2half_rn(v);
    if (idx < 256) d_cb[idx] = fc1b[idx] + fc2b[idx];
}

__global__ void conv_mx_kernel(const float* __restrict__ x) {
    int idx = blockIdx.x * blockDim.x + threadIdx.x;
    if (idx >= NN * 40) return;
    int n = idx / 40, c2 = idx % 40;
    float a = 0.f, b = 0.f;
    int c = c2 * 2;
    if (c < FIN) a = x[(size_t)n * FIN + c];
    if (c + 1 < FIN) b = x[(size_t)n * FIN + c + 1];
    ((__half2*)d_mx16)[idx] = __floats2half2_rn(a, b);
}

// ---------------- fp16 tensor-core GEMM (m16n8k16 + ldmatrix, pipelined) ----------------
__device__ __forceinline__ void mma_f16(float* c, const uint32_t* a, uint32_t b0, uint32_t b1) {
    asm volatile(
        "mma.sync.aligned.m16n8k16.row.col.f32.f16.f16.f32 "
        "{%0,%1,%2,%3},{%4,%5,%6,%7},{%8,%9},{%0,%1,%2,%3};"
        : "+f"(c[0]), "+f"(c[1]), "+f"(c[2]), "+f"(c[3])
        : "r"(a[0]), "r"(a[1]), "r"(a[2]), "r"(a[3]), "r"(b0), "r"(b1));
}

__device__ __forceinline__ void ldsm_x4(uint32_t& r0, uint32_t& r1, uint32_t& r2, uint32_t& r3,
                                        uint32_t addr) {
    asm volatile("ldmatrix.sync.aligned.m8n8.x4.shared.b16 {%0,%1,%2,%3}, [%4];"
                 : "=r"(r0), "=r"(r1), "=r"(r2), "=r"(r3) : "r"(addr));
}

__device__ __forceinline__ void ldsm_x4t(uint32_t& r0, uint32_t& r1, uint32_t& r2, uint32_t& r3,
                                         uint32_t addr) {
    asm volatile("ldmatrix.sync.aligned.m8n8.x4.trans.shared.b16 {%0,%1,%2,%3}, [%4];"
                 : "=r"(r0), "=r"(r1), "=r"(r2), "=r"(r3) : "r"(addr));
}

#define APITCH 80
#define BPITCH 272
#define ABYTES (128 * APITCH)
#define BBYTES (32 * BPITCH)

// ASRC: 0 = fp32 A (+optional concat A2 fp32), 2 = fp16 A dense
// EPI:  0 = v*scale+bias(+relu) -> optional fp32 Cf and fp16 Ch
//       2 = gate blend: z=sig(v+bias+molb); o=z*x(fp16 A)+(1-z)*h(fp16 Hh)
template <int ASRC, int EPI>
__global__ __launch_bounds__(256) void gemm16_kernel(
    const void* __restrict__ Ap, int lda, int K1,
    const float* __restrict__ A2, int lda2,
    const __half* __restrict__ Hh, int ldhh,
    const __half* __restrict__ B1, const __half* __restrict__ B2, int ldb,
    int SP, int KV1, int KV2,
    float* __restrict__ Cf, int ldc,
    __half* __restrict__ Ch, int ldch,
    int M, int N, int Ktot,
    const float* __restrict__ bias, int relu, float scale,
    const float* __restrict__ molb)
{
    __shared__ __align__(16) uint8_t AsmB[2 * ABYTES];
    __shared__ __align__(16) uint8_t BsmB[2 * BBYTES];
    int tid = threadIdx.x;
    int lane = tid & 31, wid = tid >> 5;
    int wm = wid & 3, wn = wid >> 2;
    int row0 = blockIdx.y * 128, col0 = blockIdx.x * 128;
    int g = lane >> 2, tg = lane & 3;
    int l15 = lane & 15;
    int lhi = (lane & 16) ? 8 : 0;

    float acc[2][8][4];
    #pragma unroll
    for (int mi = 0; mi < 2; mi++)
        #pragma unroll
        for (int ni = 0; ni < 8; ni++)
            #pragma unroll
            for (int q = 0; q < 4; q++) acc[mi][ni][q] = 0.0f;

    const float* Af = (const float*)Ap;
    const __half* Ah = (const __half*)Ap;

    float4 raf[4];
    uint2 rah[4];
    uint2 rbh[4];

    auto loadA = [&](int k0) {
        #pragma unroll
        for (int i = 0; i < 4; i++) {
            int l4 = tid + i * 256;
            int r = l4 >> 3, c4 = (l4 & 7) << 2;
            int grow = row0 + r, gk = k0 + c4;
            if (ASRC == 2) {
                uint2 u = make_uint2(0u, 0u);
                if (grow < M) u = *(const uint2*)(Ah + (size_t)grow * lda + gk);
                rah[i] = u;
            } else {
                float4 v = make_float4(0.f, 0.f, 0.f, 0.f);
                if (grow < M) {
                    if (gk + 3 < K1) {
                        v = *(const float4*)(Af + (size_t)grow * lda + gk);
                    } else {
                        float* pv = &v.x;
                        #pragma unroll
                        for (int j = 0; j < 4; j++) {
                            int kk = gk + j;
                            float x = 0.0f;
                            if (kk < K1) x = Af[(size_t)grow * lda + kk];
                            else if (kk < Ktot) x = A2[(size_t)grow * lda2 + (kk - K1)];
                            pv[j] = x;
                        }
                    }
                }
                raf[i] = v;
            }
        }
    };
    auto storeA = [&](uint8_t* As) {
        #pragma unroll
        for (int i = 0; i < 4; i++) {
            int l4 = tid + i * 256;
            int r = l4 >> 3, c4 = (l4 & 7) << 2;
            uint2 u;
            if (ASRC == 2) {
                u = rah[i];
            } else {
                __half2 h0 = __floats2half2_rn(raf[i].x, raf[i].y);
                __half2 h1 = __floats2half2_rn(raf[i].z, raf[i].w);
                u.x = *(uint32_t*)&h0;
                u.y = *(uint32_t*)&h1;
            }
            *(uint2*)(As + r * APITCH + c4 * 2) = u;
        }
    };
    auto loadB = [&](int k0) {
        #pragma unroll
        for (int i = 0; i < 4; i++) {
            int l4 = tid + i * 256;
            int k = l4 >> 5, n4 = (l4 & 31) << 2;
            int kk = k0 + k;
            uint2 u = make_uint2(0u, 0u);
            if (kk < SP) {
                if (kk < KV1) u = *(const uint2*)(B1 + (size_t)kk * ldb + col0 + n4);
            } else if (kk < Ktot) {
                int j = kk - SP;
                if (j < KV2) u = *(const uint2*)(B2 + (size_t)j * ldb + col0 + n4);
            }
            rbh[i] = u;
        }
    };
    auto storeB = [&](uint8_t* Bs) {
        #pragma unroll
        for (int i = 0; i < 4; i++) {
            int l4 = tid + i * 256;
            int k = l4 >> 5, n4 = (l4 & 31) << 2;
            *(uint2*)(Bs + k * BPITCH + n4 * 2) = rbh[i];
        }
    };

    uint32_t aShm = (uint32_t)__cvta_generic_to_shared(AsmB);
    uint32_t bShm = (uint32_t)__cvta_generic_to_shared(BsmB);

    int T = (Ktot + 31) >> 5;
    loadA(0); loadB(0);
    storeA(AsmB); storeB(BsmB);
    __syncthreads();

    for (int t = 0; t < T; t++) {
        int buf = t & 1;
        bool more = (t + 1 < T);
        if (more) { loadA((t + 1) << 5); loadB((t + 1) << 5); }
        uint32_t aB = aShm + buf * ABYTES;
        uint32_t bB = bShm + buf * BBYTES;
        #pragma unroll
        for (int ks = 0; ks < 2; ks++) {
            uint32_t afr[2][4];
            #pragma unroll
            for (int mi = 0; mi < 2; mi++) {
                uint32_t addr = aB + (uint32_t)((wm * 32 + mi * 16 + l15) * APITCH
                                                + (ks * 16 + lhi) * 2);
                ldsm_x4(afr[mi][0], afr[mi][1], afr[mi][2], afr[mi][3], addr);
            }
            uint32_t bfr[8][2];
            #pragma unroll
            for (int p = 0; p < 4; p++) {
                uint32_t addr = bB + (uint32_t)((ks * 16 + l15) * BPITCH
                                                + (wn * 64 + p * 16 + lhi) * 2);
                ldsm_x4t(bfr[2 * p][0], bfr[2 * p][1], bfr[2 * p + 1][0], bfr[2 * p + 1][1], addr);
            }
            #pragma unroll
            for (int ni = 0; ni < 8; ni++) {
                mma_f16(acc[0][ni], afr[0], bfr[ni][0], bfr[ni][1]);
                mma_f16(acc[1][ni], afr[1], bfr[ni][0], bfr[ni][1]);
            }
        }
        if (more) {
            storeA(AsmB + (buf ^ 1) * ABYTES);
            storeB(BsmB + (buf ^ 1) * BBYTES);
        }
        __syncthreads();
    }

    // epilogue
    #pragma unroll
    for (int mi = 0; mi < 2; mi++) {
        int r0 = row0 + wm * 32 + mi * 16 + g;
        #pragma unroll
        for (int ni = 0; ni < 8; ni++) {
            int c = col0 + wn * 64 + ni * 8 + tg * 2;
            float v0 = acc[mi][ni][0], v1 = acc[mi][ni][1];
            float v2 = acc[mi][ni][2], v3 = acc[mi][ni][3];
            if (EPI == 0) {
                float b0v = bias ? bias[c] : 0.0f;
                float b1v = bias ? bias[c + 1] : 0.0f;
                v0 = v0 * scale + b0v; v1 = v1 * scale + b1v;
                v2 = v2 * scale + b0v; v3 = v3 * scale + b1v;
                if (relu) {
                    v0 = fmaxf(v0, 0.f); v1 = fmaxf(v1, 0.f);
                    v2 = fmaxf(v2, 0.f); v3 = fmaxf(v3, 0.f);
                }
                if (r0 < M) {
                    if (Cf) *(float2*)(Cf + (size_t)r0 * ldc + c) = make_float2(v0, v1);
                    if (Ch) *(__half2*)(Ch + (size_t)r0 * ldch + c) = __floats2half2_rn(v0, v1);
                }
                if (r0 + 8 < M) {
                    if (Cf) *(float2*)(Cf + (size_t)(r0 + 8) * ldc + c) = make_float2(v2, v3);
                    if (Ch) *(__half2*)(Ch + (size_t)(r0 + 8) * ldch + c) = __floats2half2_rn(v2, v3);
                }
            } else {
                float cb0 = bias[c] + molb[c];
                float cb1 = bias[c + 1] + molb[c + 1];
                #pragma unroll
                for (int hh = 0; hh < 2; hh++) {
                    int r = r0 + hh * 8;
                    if (r >= M) continue;
                    float va = hh ? v2 : v0, vb = hh ? v3 : v1;
                    float z0 = 1.0f / (1.0f + __expf(-(va + cb0)));
                    float z1 = 1.0f / (1.0f + __expf(-(vb + cb1)));
                    float2 xv = __half22float2(*(const __half2*)(Ah + (size_t)r * lda + c));
                    float2 hv = __half22float2(*(const __half2*)(Hh + (size_t)r * ldhh + c));
                    float o0 = z0 * xv.x + (1.0f - z0) * hv.x;
                    float o1 = z1 * xv.y + (1.0f - z1) * hv.y;
                    if (Cf) *(float2*)(Cf + (size_t)r * ldc + c) = make_float2(o0, o1);
                    if (Ch) *(__half2*)(Ch + (size_t)r * ldch + c) = __floats2half2_rn(o0, o1);
                }
            }
        }
    }
}

template <int ASRC, int EPI>
static void run_gemm(const void* A, int lda, int K1, const float* A2, int lda2,
                     const __half* Hh, int ldhh,
                     const __half* B1, const __half* B2, int ldb, int SP, int KV1, int KV2,
                     float* Cf, int ldc, __half* Ch, int ldch,
                     int M, int N, int Ktot,
                     const float* bias, int relu, float scale, const float* molb) {
    dim3 grid(N / 128, (M + 127) / 128);
    gemm16_kernel<ASRC, EPI><<<grid, 256>>>(
        A, lda, K1, A2, lda2, Hh, ldhh, B1, B2, ldb, SP, KV1, KV2,
        Cf, ldc, Ch, ldch, M, N, Ktot, bias, relu, scale, molb);
}

// ---------------- attention logits ----------------
__global__ void build_wv_kernel(const float* __restrict__ W, const float* __restrict__ as,
                                const float* __restrict__ ad) {
    int k = blockIdx.x, t = threadIdx.x;
    float w0 = W[(size_t)k * 512 + t], w1 = W[(size_t)k * 512 + 256 + t];
    float p0 = w0 * as[t], p1 = w1 * as[256 + t];
    float p2 = w0 * ad[t], p3 = w1 * ad[256 + t];
    __shared__ float red[8][4];
    int lane = t & 31, wid = t >> 5;
    #pragma unroll
    for (int d = 16; d; d >>= 1) {
        p0 += __shfl_down_sync(0xFFFFFFFFu, p0, d);
        p1 += __shfl_down_sync(0xFFFFFFFFu, p1, d);
        p2 += __shfl_down_sync(0xFFFFFFFFu, p2, d);
        p3 += __shfl_down_sync(0xFFFFFFFFu, p3, d);
    }
    if (lane == 0) { red[wid][0] = p0; red[wid][1] = p1; red[wid][2] = p2; red[wid][3] = p3; }
    __syncthreads();
    if (t == 0) {
        float r0 = 0, r1 = 0, r2 = 0, r3 = 0;
        #pragma unroll
        for (int w = 0; w < 8; w++) { r0 += red[w][0]; r1 += red[w][1]; r2 += red[w][2]; r3 += red[w][3]; }
        d_wv[k * 4 + 0] = r0; d_wv[k * 4 + 1] = r1; d_wv[k * 4 + 2] = r2; d_wv[k * 4 + 3] = r3;
    }
}

// fp32 input (layer 1)
__global__ void attn2_kernel(const float* __restrict__ x, int K) {
    int warp = threadIdx.x >> 5, lane = threadIdx.x & 31;
    int n = blockIdx.x * 4 + warp;
    if (n >= NN) return;
    const float* xr = x + (size_t)n * K;
    float s0 = 0, s1 = 0, s2 = 0, s3 = 0;
    for (int c = lane; c < K; c += 32) {
        float xv = xr[c];
        float4 wv = ((const float4*)d_wv)[c];
        s0 += xv * wv.x; s1 += xv * wv.y; s2 += xv * wv.z; s3 += xv * wv.w;
    }
    #pragma unroll
    for (int d = 16; d; d >>= 1) {
        s0 += __shfl_down_sync(0xFFFFFFFFu, s0, d);
        s1 += __shfl_down_sync(0xFFFFFFFFu, s1, d);
        s2 += __shfl_down_sync(0xFFFFFFFFu, s2, d);
        s3 += __shfl_down_sync(0xFFFFFFFFu, s3, d);
    }
    if (lane == 0) {
        d_asrc[n * 2] = s0; d_asrc[n * 2 + 1] = s1;
        d_adst[n * 2] = s2; d_adst[n * 2 + 1] = s3;
    }
}

// fp16 input (layers 2,3), K = 256, row stride ldh halves
__global__ void attn2h_kernel(const __half* __restrict__ x, int ldh) {
    int warp = threadIdx.x >> 5, lane = threadIdx.x & 31;
    int n = blockIdx.x * 4 + warp;
    if (n >= NN) return;
    const __half2* xr = (const __half2*)(x + (size_t)n * ldh);
    float s0 = 0, s1 = 0, s2 = 0, s3 = 0;
    #pragma unroll
    for (int w = 0; w < 4; w++) {
        int c2 = lane + w * 32;          // half2 index 0..127
        float2 xv = __half22float2(xr[c2]);
        float4 wv0 = ((const float4*)d_wv)[c2 * 2];
        float4 wv1 = ((const float4*)d_wv)[c2 * 2 + 1];
        s0 += xv.x * wv0.x + xv.y * wv1.x;
        s1 += xv.x * wv0.y + xv.y * wv1.y;
        s2 += xv.x * wv0.z + xv.y * wv1.z;
        s3 += xv.x * wv0.w + xv.y * wv1.w;
    }
    #pragma unroll
    for (int d = 16; d; d >>= 1) {
        s0 += __shfl_down_sync(0xFFFFFFFFu, s0, d);
        s1 += __shfl_down_sync(0xFFFFFFFFu, s1, d);
        s2 += __shfl_down_sync(0xFFFFFFFFu, s2, d);
        s3 += __shfl_down_sync(0xFFFFFFFFu, s3, d);
    }
    if (lane == 0) {
        d_asrc[n * 2] = s0; d_asrc[n * 2 + 1] = s1;
        d_adst[n * 2] = s2; d_adst[n * 2 + 1] = s3;
    }
}

__device__ __forceinline__ float lrelu02(float v) { return v >= 0.0f ? v : 0.2f * v; }

// single-pass softmax: logits are small (|e| < ~2), exp without max is safe.
// writes UNNORMALIZED p to d_alpha and 1/sum to d_rsum.
__global__ void softmax_kernel() {
    int n = blockIdx.x * (blockDim.x >> 5) + (threadIdx.x >> 5);
    int lane = threadIdx.x & 31;
    if (n >= NN) return;
    int s0 = csrA_off[n], s1 = csrA_off[n + 1];
    float ad0 = d_adst[n * 2], ad1 = d_adst[n * 2 + 1];
    float sum0 = 0.0f, sum1 = 0.0f;
    for (int p = s0 + lane; p < s1; p += 32) {
        int src = csrA_val[p];
        float x0 = __expf(lrelu02(d_asrc[src * 2] + ad0));
        float x1 = __expf(lrelu02(d_asrc[src * 2 + 1] + ad1));
        d_alpha[p] = make_float2(x0, x1);
        sum0 += x0; sum1 += x1;
    }
    #pragma unroll
    for (int d = 16; d; d >>= 1) {
        sum0 += __shfl_xor_sync(0xFFFFFFFFu, sum0, d);
        sum1 += __shfl_xor_sync(0xFFFFFFFFu, sum1, d);
    }
    if (lane == 0) d_rsum[n] = make_float2(1.0f / sum0, 1.0f / sum1);
}

// layer-1 aggregate (40 half2 cols); scales by rsum at end
template <int BLOCK, int CH2>
__global__ void gat_aggregate_kernel(const __half2* __restrict__ src, int ldh2,
                                     __half2* __restrict__ agg, int lda2) {
    int n = blockIdx.x;
    int t = threadIdx.x;
    int s0 = csrA_off[n], s1 = csrA_off[n + 1];
    float a0x = 0, a0y = 0, a1x = 0, a1y = 0;
    __shared__ int ssrc[BLOCK];
    __shared__ float2 salp[BLOCK];
    bool act = t < CH2;
    for (int base = s0; base < s1; base += BLOCK) {
        int cnt = min(BLOCK, s1 - base);
        __syncthreads();
        if (t < cnt) { ssrc[t] = csrA_val[base + t]; salp[t] = d_alpha[base + t]; }
        __syncthreads();
        if (act) {
            #pragma unroll 2
            for (int j = 0; j < cnt; j++) {
                float2 f = __half22float2(src[(size_t)ssrc[j] * ldh2 + t]);
                float2 a = salp[j];
                a0x += a.x * f.x; a0y += a.x * f.y;
                a1x += a.y * f.x; a1y += a.y * f.y;
            }
        }
    }
    if (act) {
        float2 rs = d_rsum[n];
        agg[(size_t)n * lda2 + t] = __floats2half2_rn(a0x * rs.x, a0y * rs.x);
        agg[(size_t)n * lda2 + CH2 + t] = __floats2half2_rn(a1x * rs.y, a1y * rs.y);
    }
}

// layer-2/3 aggregate: 2 edge-groups of 64, uint2 loads; scales by rsum at end
__global__ void gat_agg256_kernel(const __half2* __restrict__ src, int ldh2,
                                  __half2* __restrict__ agg) {
    int n = blockIdx.x;
    int t = threadIdx.x;
    int gid = t >> 6, tl = t & 63;
    int s0 = csrA_off[n], s1 = csrA_off[n + 1];
    float h0[4] = {0, 0, 0, 0}, h1[4] = {0, 0, 0, 0};
    __shared__ int ssrc[128];
    __shared__ float2 salp[128];
    __shared__ float red[64][8];
    for (int base = s0; base < s1; base += 128) {
        int cnt = min(128, s1 - base);
        __syncthreads();
        if (t < cnt) { ssrc[t] = csrA_val[base + t]; salp[t] = d_alpha[base + t]; }
        __syncthreads();
        for (int j = gid; j < cnt; j += 2) {
            uint2 u = *(const uint2*)(src + (size_t)ssrc[j] * ldh2 + tl * 2);
            float2 g0 = __half22float2(*(__half2*)&u.x);
            float2 g1 = __half22float2(*(__half2*)&u.y);
            float2 a = salp[j];
            h0[0] += a.x * g0.x; h0[1] += a.x * g0.y; h0[2] += a.x * g1.x; h0[3] += a.x * g1.y;
            h1[0] += a.y * g0.x; h1[1] += a.y * g0.y; h1[2] += a.y * g1.x; h1[3] += a.y * g1.y;
        }
    }
    __syncthreads();
    if (gid == 1) {
        red[tl][0] = h0[0]; red[tl][1] = h0[1]; red[tl][2] = h0[2]; red[tl][3] = h0[3];
        red[tl][4] = h1[0]; red[tl][5] = h1[1]; red[tl][6] = h1[2]; red[tl][7] = h1[3];
    }
    __syncthreads();
    if (gid == 0) {
        float2 rs = d_rsum[n];
        h0[0] += red[tl][0]; h0[1] += red[tl][1]; h0[2] += red[tl][2]; h0[3] += red[tl][3];
        h1[0] += red[tl][4]; h1[1] += red[tl][5]; h1[2] += red[tl][6]; h1[3] += red[tl][7];
        __half2* row = agg + (size_t)n * 256;
        row[tl * 2] = __floats2half2_rn(h0[0] * rs.x, h0[1] * rs.x);
        row[tl * 2 + 1] = __floats2half2_rn(h0[2] * rs.x, h0[3] * rs.x);
        row[128 + tl * 2] = __floats2half2_rn(h1[0] * rs.y, h1[1] * rs.y);
        row[128 + tl * 2 + 1] = __floats2half2_rn(h1[2] * rs.y, h1[3] * rs.y);
    }
}

// ---------------- hypergraph ----------------
template <bool OUTH>
__global__ void hyper_gather_kernel(const __half2* __restrict__ in, void* __restrict__ outp,
                                    int ostride, const float* __restrict__ bias,
                                    int which, int relu) {
    const int* off = which ? csrC_off : csrA_off;
    const int* val = which ? csrC_val : csrA_val;
    int n = blockIdx.x;
    int t = threadIdx.x;
    int gid = t >> 5, tl = t & 31;
    int s0 = off[n], s1 = off[n + 1];
    if (!which) s1 -= 1;
    float a[4] = {0, 0, 0, 0};
    __shared__ int sv[64];
    __shared__ float red[32][4];
    for (int base = s0; base < s1; base += 64) {
        int cnt = min(64, s1 - base);
        __syncthreads();
        if (t < cnt) sv[t] = val[base + t];
        __syncthreads();
        for (int j = gid; j < cnt; j += 2) {
            uint2 u = *(const uint2*)(in + (size_t)sv[j] * 64 + tl * 2);
            float2 g0 = __half22float2(*(__half2*)&u.x);
            float2 g1 = __half22float2(*(__half2*)&u.y);
            a[0] += g0.x; a[1] += g0.y; a[2] += g1.x; a[3] += g1.y;
        }
    }
    __syncthreads();
    if (gid == 1) { red[tl][0] = a[0]; red[tl][1] = a[1]; red[tl][2] = a[2]; red[tl][3] = a[3]; }
    __syncthreads();
    if (gid == 0) {
        a[0] += red[tl][0]; a[1] += red[tl][1]; a[2] += red[tl][2]; a[3] += red[tl][3];
        float inv = which ? d_dinv[n] : d_binv[n];
        #pragma unroll
        for (int q = 0; q < 4; q++) a[q] *= inv;
        if (bias) {
            a[0] += bias[tl * 4]; a[1] += bias[tl * 4 + 1];
            a[2] += bias[tl * 4 + 2]; a[3] += bias[tl * 4 + 3];
        }
        if (relu) {
            #pragma unroll
            for (int q = 0; q < 4; q++) a[q] = fmaxf(a[q], 0.f);
        }
        if (OUTH) {
            __half2* o = (__half2*)outp;
            o[(size_t)n * ostride + tl * 2] = __floats2half2_rn(a[0], a[1]);
            o[(size_t)n * ostride + tl * 2 + 1] = __floats2half2_rn(a[2], a[3]);
        } else {
            float2* o = (float2*)outp;
            o[(size_t)n * ostride + tl * 2] = make_float2(a[0], a[1]);
            o[(size_t)n * ostride + tl * 2 + 1] = make_float2(a[2], a[3]);
        }
    }
}

// ---------------- host side ----------------
extern "C" void kernel_launch(void* const* d_in, const int* in_sizes, int n_in,
                              void* d_out, int out_size) {
    const float* mol_x = (const float*)d_in[0];
    const int*   ei    = (const int*)d_in[1];
    const float* W1 = (const float*)d_in[3];
    const float* as1 = (const float*)d_in[4];
    const float* ad1 = (const float*)d_in[5];
    const float* b1 = (const float*)d_in[6];
    const float* W2 = (const float*)d_in[7];
    const float* as2 = (const float*)d_in[8];
    const float* ad2 = (const float*)d_in[9];
    const float* b2 = (const float*)d_in[10];
    const float* W3 = (const float*)d_in[11];
    const float* as3 = (const float*)d_in[12];
    const float* ad3 = (const float*)d_in[13];
    const float* b3 = (const float*)d_in[14];
    const float* fc1_w = (const float*)d_in[15];
    const float* fc1_b = (const float*)d_in[16];
    const float* fc2_w = (const float*)d_in[17];
    const float* fc2_b = (const float*)d_in[18];
    const float* mol_bias = (const float*)d_in[19];
    const float* theta1 = (const float*)d_in[20];
    const float* hb1 = (const float*)d_in[21];
    const float* theta2 = (const float*)d_in[22];
    const float* hb2 = (const float*)d_in[23];

    __half *p_mx, *p_catA, *p_catB, *p_agg, *p_xt, *p_ef, *p_hy16;
    __half *p_w1h, *p_w2h, *p_w3h, *p_bch, *p_th1h, *p_th2h;
    float *p_cb;
    cudaGetSymbolAddress((void**)&p_mx, d_mx16);
    cudaGetSymbolAddress((void**)&p_catA, d_catA);
    cudaGetSymbolAddress((void**)&p_catB, d_catB);
    cudaGetSymbolAddress((void**)&p_agg, d_agg);
    cudaGetSymbolAddress((void**)&p_xt, d_xt);
    cudaGetSymbolAddress((void**)&p_ef, d_ef);
    cudaGetSymbolAddress((void**)&p_hy16, d_hy16);
    cudaGetSymbolAddress((void**)&p_w1h, d_w1h);
    cudaGetSymbolAddress((void**)&p_w2h, d_w2h);
    cudaGetSymbolAddress((void**)&p_w3h, d_w3h);
    cudaGetSymbolAddress((void**)&p_bch, d_bch);
    cudaGetSymbolAddress((void**)&p_th1h, d_th1h);
    cudaGetSymbolAddress((void**)&p_th2h, d_th2h);
    cudaGetSymbolAddress((void**)&p_cb, d_cb);
    float* p_out = (float*)d_out;

    // ---- CSR build ----
    zero_counts_kernel<<<(NN + 255) / 256, 256>>>();
    count_kernel<<<(EE + 255) / 256, 256>>>(ei);
    scan2_kernel<<<2, 1024>>>();
    fill_kernel<<<(EE + 255) / 256, 256>>>(ei);

    // ---- conversions ----
    conv_mx_kernel<<<(NN * 40 + 255) / 256, 256>>>(mol_x);
    f2h_kernel<<<(FIN * 512 / 2 + 255) / 256, 256>>>(W1, p_w1h, FIN * 512 / 2);
    f2h_kernel<<<(256 * 512 / 2 + 255) / 256, 256>>>(W2, p_w2h, 256 * 512 / 2);
    f2h_kernel<<<(256 * 512 / 2 + 255) / 256, 256>>>(W3, p_w3h, 256 * 512 / 2);
    f2h_kernel<<<(334 * 128 / 2 + 255) / 256, 256>>>(theta1, p_th1h, 334 * 128 / 2);
    f2h_kernel<<<(128 * 128 / 2 + 255) / 256, 256>>>(theta2, p_th2h, 128 * 128 / 2);
    build_bc16_kernel<<<(512 * 256 + 255) / 256, 256>>>(fc1_w, fc2_w, fc1_b, fc2_b);

    // ---- GAT layer 1: h1 (fp16 only) = relu(gat(mol_x)) ----
    build_wv_kernel<<<FIN, 256>>>(W1, as1, ad1);
    attn2_kernel<<<(NN + 3) / 4, 128>>>(mol_x, FIN);
    softmax_kernel<<<(NN + 7) / 8, 256>>>();
    gat_aggregate_kernel<64, 40><<<NN, 64>>>((const __half2*)p_mx, 40, (__half2*)p_agg, 80);
    run_gemm<2, 0>(p_agg, 160, 0, nullptr, 0, nullptr, 0, p_w1h, p_w1h + 256, 512, 80, FIN, FIN,
                   nullptr, 0, p_catA + 256, 512, NN, 256, 160, b1, 1, 0.5f, nullptr);

    // ---- GAT layer 2 ----
    build_wv_kernel<<<256, 256>>>(W2, as2, ad2);
    attn2h_kernel<<<(NN + 3) / 4, 128>>>(p_catA + 256, 512);
    softmax_kernel<<<(NN + 7) / 8, 256>>>();
    gat_agg256_kernel<<<NN, 128>>>((const __half2*)(p_catA + 256), 256, (__half2*)p_agg);
    run_gemm<2, 0>(p_agg, 512, 0, nullptr, 0, nullptr, 0, p_w2h, p_w2h + 256, 512, 256, 256, 256,
                   nullptr, 0, p_catA, 512, NN, 256, 512, b2, 1, 0.5f, nullptr);
    run_gemm<2, 2>(p_catA, 512, 0, nullptr, 0, p_catA + 256, 512, p_bch, nullptr, 256, 512, 512, 0,
                   nullptr, 0, p_catB + 256, 512, NN, 256, 512, p_cb, 0, 1.0f, mol_bias);
    // h2 fp16 in catB[256:)

    // ---- GAT layer 3 ----
    build_wv_kernel<<<256, 256>>>(W3, as3, ad3);
    attn2h_kernel<<<(NN + 3) / 4, 128>>>(p_catB + 256, 512);
    softmax_kernel<<<(NN + 7) / 8, 256>>>();
    gat_agg256_kernel<<<NN, 128>>>((const __half2*)(p_catB + 256), 256, (__half2*)p_agg);
    run_gemm<2, 0>(p_agg, 512, 0, nullptr, 0, nullptr, 0, p_w3h, p_w3h + 256, 512, 256, 256, 256,
                   nullptr, 0, p_catB, 512, NN, 256, 512, b3, 0, 0.5f, nullptr);
    run_gemm<2, 2>(p_catB, 512, 0, nullptr, 0, p_catB + 256, 512, p_bch, nullptr, 256, 512, 512, 0,
                   p_out, 384, nullptr, 0, NN, 256, 512, p_cb, 0, 1.0f, mol_bias);
    // final h fp32 in d_out[:, 0:256)

    // ---- hypergraph branch ----
    run_gemm<0, 0>(p_out, 384, 256, mol_x, FIN, nullptr, 0, p_th1h, nullptr, 128, 334, 334, 0,
                   nullptr, 0, p_xt, 128, NN, 128, 334, nullptr, 0, 1.0f, nullptr);
    hyper_gather_kernel<true ><<<NN, 64>>>((const __half2*)p_xt, p_ef, 64, nullptr, 0, 0);
    hyper_gather_kernel<true ><<<NN, 64>>>((const __half2*)p_ef, p_hy16, 64, hb1, 1, 1);
    run_gemm<2, 0>(p_hy16, 128, 0, nullptr, 0, nullptr, 0, p_th2h, nullptr, 128, 128, 128, 0,
                   nullptr, 0, p_xt, 128, NN, 128, 128, nullptr, 0, 1.0f, nullptr);
    hyper_gather_kernel<true ><<<NN, 64>>>((const __half2*)p_xt, p_ef, 64, nullptr, 0, 0);
    hyper_gather_kernel<false><<<NN, 64>>>((const __half2*)p_ef, (float2*)p_out + 128, 192,
                                           hb2, 1, 1);
}

// round 11
// speedup vs baseline: 1.5148x; 1.0487x over previous
#include <cuda_runtime.h>
#include <cuda_fp16.h>
#include <math.h>
#include <stdint.h>

#define NN 100000
#define EE 3200000
#define EA (EE + NN)
#define FIN 78
#define FG 256
#define FH 128

// ---------------- scratch (device globals; no allocation) ----------------
__device__ __half d_mx16[(size_t)NN * 80];
__device__ __half d_catA[(size_t)NN * 512];   // [x1 | h1]
__device__ __half d_catB[(size_t)NN * 512];   // [x2 | h2]
__device__ __half d_agg[(size_t)NN * 512];
__device__ __half d_xt[(size_t)NN * 128];
__device__ __half d_ef[(size_t)NN * 128];
__device__ __half d_hy16[(size_t)NN * 128];
__device__ __half d_w1h[FIN * 512];
__device__ __half d_w2h[256 * 512];
__device__ __half d_w3h[256 * 512];
__device__ __half d_bch[512 * 256];
__device__ __half d_th1h[334 * 128];
__device__ __half d_th2h[128 * 128];
__device__ float d_cb[256];
__device__ float d_wv[256 * 4];
__device__ float d_asrc[NN * 2];
__device__ float d_adst[NN * 2];
__device__ int csrA_off[NN + 1]; __device__ int csrA_val[EA];
__device__ int csrC_off[NN + 1]; __device__ int csrC_val[EE];
__device__ int cntA[NN], cntC[NN];
__device__ int curA[NN], curC[NN];
__device__ float d_binv[NN], d_dinv[NN];

// ---------------- CSR construction ----------------
__global__ void zero_counts_kernel() {
    int i = blockIdx.x * blockDim.x + threadIdx.x;
    if (i < NN) { cntA[i] = 0; cntC[i] = 0; }
}

__global__ void count_kernel(const int* __restrict__ ei) {
    int i = blockIdx.x * blockDim.x + threadIdx.x;
    if (i >= EE) return;
    int s = ei[i];
    int d = ei[EE + i];
    atomicAdd(&cntA[d], 1);
    atomicAdd(&cntC[s], 1);
}

__global__ void scan2_kernel() {
    bool isA = (blockIdx.x == 0);
    const int* in = isA ? cntA : cntC;
    int* out = isA ? csrA_off : csrC_off;
    const int n = NN;
    __shared__ int wsum[32];
    __shared__ int carry;
    int tid = threadIdx.x, lane = tid & 31, wid = tid >> 5;
    if (tid == 0) carry = 0;
    __syncthreads();
    for (int base = 0; base < n; base += 1024) {
        int i = base + tid;
        int raw = (i < n) ? in[i] : 0;
        int v = raw + (isA ? ((i < n) ? 1 : 0) : 0);
        int x = v;
        #pragma unroll
        for (int d = 1; d < 32; d <<= 1) {
            int y = __shfl_up_sync(0xFFFFFFFFu, x, d);
            if (lane >= d) x += y;
        }
        if (lane == 31) wsum[wid] = x;
        __syncthreads();
        if (wid == 0) {
            int w = wsum[lane];
            #pragma unroll
            for (int d = 1; d < 32; d <<= 1) {
                int y = __shfl_up_sync(0xFFFFFFFFu, w, d);
                if (lane >= d) w += y;
            }
            wsum[lane] = w;
        }
        __syncthreads();
        int excl = carry + (wid ? wsum[wid - 1] : 0) + x - v;
        if (i < n) {
            out[i] = excl;
            if (isA) {
                curA[i] = excl;
                csrA_val[excl + raw] = i;
                d_binv[i] = raw > 0 ? 1.0f / (float)raw : 0.0f;
            } else {
                curC[i] = excl;
                d_dinv[i] = raw > 0 ? 1.0f / (float)raw : 0.0f;
            }
        }
        if (i == n - 1) out[n] = excl + v;
        __syncthreads();
        if (tid == 0) carry += wsum[31];
        __syncthreads();
    }
}

__global__ void fill_kernel(const int* __restrict__ ei) {
    int i = blockIdx.x * blockDim.x + threadIdx.x;
    if (i >= EE) return;
    int s = ei[i];
    int d = ei[EE + i];
    csrA_val[atomicAdd(&curA[d], 1)] = s;
    csrC_val[atomicAdd(&curC[s], 1)] = d;
}

// ---------------- weight conversion ----------------
__global__ void f2h_kernel(const float* __restrict__ src, __half* __restrict__ dst, int n2) {
    int i = blockIdx.x * blockDim.x + threadIdx.x;
    if (i < n2) {
        float2 v = ((const float2*)src)[i];
        ((__half2*)dst)[i] = __floats2half2_rn(v.x, v.y);
    }
}

__global__ void build_bc16_kernel(const float* __restrict__ fc1w, const float* __restrict__ fc2w,
                                  const float* __restrict__ fc1b, const float* __restrict__ fc2b) {
    int idx = blockIdx.x * blockDim.x + threadIdx.x;
    if (idx >= 512 * 256) return;
    int k = idx >> 8, n = idx & 255;
    float v = (k < 256) ? fc1w[n * 256 + k] : fc2w[n * 256 + (k - 256)];
    d_bch[idx] = __float2half_rn(v);
    if (idx < 256) d_cb[idx] = fc1b[idx] + fc2b[idx];
}

__global__ void conv_mx_kernel(const float* __restrict__ x) {
    int idx = blockIdx.x * blockDim.x + threadIdx.x;
    if (idx >= NN * 40) return;
    int n = idx / 40, c2 = idx % 40;
    float a = 0.f, b = 0.f;
    int c = c2 * 2;
    if (c < FIN) a = x[(size_t)n * FIN + c];
    if (c + 1 < FIN) b = x[(size_t)n * FIN + c + 1];
    ((__half2*)d_mx16)[idx] = __floats2half2_rn(a, b);
}

// ---------------- fp16 tensor-core GEMM (m16n8k16 + ldmatrix, pipelined) ----------------
__device__ __forceinline__ void mma_f16(float* c, const uint32_t* a, uint32_t b0, uint32_t b1) {
    asm volatile(
        "mma.sync.aligned.m16n8k16.row.col.f32.f16.f16.f32 "
        "{%0,%1,%2,%3},{%4,%5,%6,%7},{%8,%9},{%0,%1,%2,%3};"
        : "+f"(c[0]), "+f"(c[1]), "+f"(c[2]), "+f"(c[3])
        : "r"(a[0]), "r"(a[1]), "r"(a[2]), "r"(a[3]), "r"(b0), "r"(b1));
}

__device__ __forceinline__ void ldsm_x4(uint32_t& r0, uint32_t& r1, uint32_t& r2, uint32_t& r3,
                                        uint32_t addr) {
    asm volatile("ldmatrix.sync.aligned.m8n8.x4.shared.b16 {%0,%1,%2,%3}, [%4];"
                 : "=r"(r0), "=r"(r1), "=r"(r2), "=r"(r3) : "r"(addr));
}

__device__ __forceinline__ void ldsm_x4t(uint32_t& r0, uint32_t& r1, uint32_t& r2, uint32_t& r3,
                                         uint32_t addr) {
    asm volatile("ldmatrix.sync.aligned.m8n8.x4.trans.shared.b16 {%0,%1,%2,%3}, [%4];"
                 : "=r"(r0), "=r"(r1), "=r"(r2), "=r"(r3) : "r"(addr));
}

#define APITCH 80
#define BPITCH 272
#define ABYTES (128 * APITCH)
#define BBYTES (32 * BPITCH)

// ASRC: 0 = fp32 A (+optional concat A2 fp32), 2 = fp16 A dense
// EPI:  0 = v*scale+bias(+relu) -> optional fp32 Cf and fp16 Ch
//       2 = gate blend: z=sig(v+bias+molb); o=z*x(fp16 A)+(1-z)*h(fp16 Hh)
template <int ASRC, int EPI>
__global__ __launch_bounds__(256) void gemm16_kernel(
    const void* __restrict__ Ap, int lda, int K1,
    const float* __restrict__ A2, int lda2,
    const __half* __restrict__ Hh, int ldhh,
    const __half* __restrict__ B1, const __half* __restrict__ B2, int ldb,
    int SP, int KV1, int KV2,
    float* __restrict__ Cf, int ldc,
    __half* __restrict__ Ch, int ldch,
    int M, int N, int Ktot,
    const float* __restrict__ bias, int relu, float scale,
    const float* __restrict__ molb)
{
    __shared__ __align__(16) uint8_t AsmB[2 * ABYTES];
    __shared__ __align__(16) uint8_t BsmB[2 * BBYTES];
    int tid = threadIdx.x;
    int lane = tid & 31, wid = tid >> 5;
    int wm = wid & 3, wn = wid >> 2;
    int row0 = blockIdx.y * 128, col0 = blockIdx.x * 128;
    int g = lane >> 2, tg = lane & 3;
    int l15 = lane & 15;
    int lhi = (lane & 16) ? 8 : 0;

    float acc[2][8][4];
    #pragma unroll
    for (int mi = 0; mi < 2; mi++)
        #pragma unroll
        for (int ni = 0; ni < 8; ni++)
            #pragma unroll
            for (int q = 0; q < 4; q++) acc[mi][ni][q] = 0.0f;

    const float* Af = (const float*)Ap;
    const __half* Ah = (const __half*)Ap;

    float4 raf[4];
    uint2 rah[4];
    uint2 rbh[4];

    auto loadA = [&](int k0) {
        #pragma unroll
        for (int i = 0; i < 4; i++) {
            int l4 = tid + i * 256;
            int r = l4 >> 3, c4 = (l4 & 7) << 2;
            int grow = row0 + r, gk = k0 + c4;
            if (ASRC == 2) {
                uint2 u = make_uint2(0u, 0u);
                if (grow < M) u = *(const uint2*)(Ah + (size_t)grow * lda + gk);
                rah[i] = u;
            } else {
                float4 v = make_float4(0.f, 0.f, 0.f, 0.f);
                if (grow < M) {
                    if (gk + 3 < K1) {
                        v = *(const float4*)(Af + (size_t)grow * lda + gk);
                    } else {
                        float* pv = &v.x;
                        #pragma unroll
                        for (int j = 0; j < 4; j++) {
                            int kk = gk + j;
                            float x = 0.0f;
                            if (kk < K1) x = Af[(size_t)grow * lda + kk];
                            else if (kk < Ktot) x = A2[(size_t)grow * lda2 + (kk - K1)];
                            pv[j] = x;
                        }
                    }
                }
                raf[i] = v;
            }
        }
    };
    auto storeA = [&](uint8_t* As) {
        #pragma unroll
        for (int i = 0; i < 4; i++) {
            int l4 = tid + i * 256;
            int r = l4 >> 3, c4 = (l4 & 7) << 2;
            uint2 u;
            if (ASRC == 2) {
                u = rah[i];
            } else {
                __half2 h0 = __floats2half2_rn(raf[i].x, raf[i].y);
                __half2 h1 = __floats2half2_rn(raf[i].z, raf[i].w);
                u.x = *(uint32_t*)&h0;
                u.y = *(uint32_t*)&h1;
            }
            *(uint2*)(As + r * APITCH + c4 * 2) = u;
        }
    };
    auto loadB = [&](int k0) {
        #pragma unroll
        for (int i = 0; i < 4; i++) {
            int l4 = tid + i * 256;
            int k = l4 >> 5, n4 = (l4 & 31) << 2;
            int kk = k0 + k;
            uint2 u = make_uint2(0u, 0u);
            if (kk < SP) {
                if (kk < KV1) u = *(const uint2*)(B1 + (size_t)kk * ldb + col0 + n4);
            } else if (kk < Ktot) {
                int j = kk - SP;
                if (j < KV2) u = *(const uint2*)(B2 + (size_t)j * ldb + col0 + n4);
            }
            rbh[i] = u;
        }
    };
    auto storeB = [&](uint8_t* Bs) {
        #pragma unroll
        for (int i = 0; i < 4; i++) {
            int l4 = tid + i * 256;
            int k = l4 >> 5, n4 = (l4 & 31) << 2;
            *(uint2*)(Bs + k * BPITCH + n4 * 2) = rbh[i];
        }
    };

    uint32_t aShm = (uint32_t)__cvta_generic_to_shared(AsmB);
    uint32_t bShm = (uint32_t)__cvta_generic_to_shared(BsmB);

    int T = (Ktot + 31) >> 5;
    loadA(0); loadB(0);
    storeA(AsmB); storeB(BsmB);
    __syncthreads();

    for (int t = 0; t < T; t++) {
        int buf = t & 1;
        bool more = (t + 1 < T);
        if (more) { loadA((t + 1) << 5); loadB((t + 1) << 5); }
        uint32_t aB = aShm + buf * ABYTES;
        uint32_t bB = bShm + buf * BBYTES;
        #pragma unroll
        for (int ks = 0; ks < 2; ks++) {
            uint32_t afr[2][4];
            #pragma unroll
            for (int mi = 0; mi < 2; mi++) {
                uint32_t addr = aB + (uint32_t)((wm * 32 + mi * 16 + l15) * APITCH
                                                + (ks * 16 + lhi) * 2);
                ldsm_x4(afr[mi][0], afr[mi][1], afr[mi][2], afr[mi][3], addr);
            }
            uint32_t bfr[8][2];
            #pragma unroll
            for (int p = 0; p < 4; p++) {
                uint32_t addr = bB + (uint32_t)((ks * 16 + l15) * BPITCH
                                                + (wn * 64 + p * 16 + lhi) * 2);
                ldsm_x4t(bfr[2 * p][0], bfr[2 * p][1], bfr[2 * p + 1][0], bfr[2 * p + 1][1], addr);
            }
            #pragma unroll
            for (int ni = 0; ni < 8; ni++) {
                mma_f16(acc[0][ni], afr[0], bfr[ni][0], bfr[ni][1]);
                mma_f16(acc[1][ni], afr[1], bfr[ni][0], bfr[ni][1]);
            }
        }
        if (more) {
            storeA(AsmB + (buf ^ 1) * ABYTES);
            storeB(BsmB + (buf ^ 1) * BBYTES);
        }
        __syncthreads();
    }

    // epilogue
    #pragma unroll
    for (int mi = 0; mi < 2; mi++) {
        int r0 = row0 + wm * 32 + mi * 16 + g;
        #pragma unroll
        for (int ni = 0; ni < 8; ni++) {
            int c = col0 + wn * 64 + ni * 8 + tg * 2;
            float v0 = acc[mi][ni][0], v1 = acc[mi][ni][1];
            float v2 = acc[mi][ni][2], v3 = acc[mi][ni][3];
            if (EPI == 0) {
                float b0v = bias ? bias[c] : 0.0f;
                float b1v = bias ? bias[c + 1] : 0.0f;
                v0 = v0 * scale + b0v; v1 = v1 * scale + b1v;
                v2 = v2 * scale + b0v; v3 = v3 * scale + b1v;
                if (relu) {
                    v0 = fmaxf(v0, 0.f); v1 = fmaxf(v1, 0.f);
                    v2 = fmaxf(v2, 0.f); v3 = fmaxf(v3, 0.f);
                }
                if (r0 < M) {
                    if (Cf) *(float2*)(Cf + (size_t)r0 * ldc + c) = make_float2(v0, v1);
                    if (Ch) *(__half2*)(Ch + (size_t)r0 * ldch + c) = __floats2half2_rn(v0, v1);
                }
                if (r0 + 8 < M) {
                    if (Cf) *(float2*)(Cf + (size_t)(r0 + 8) * ldc + c) = make_float2(v2, v3);
                    if (Ch) *(__half2*)(Ch + (size_t)(r0 + 8) * ldch + c) = __floats2half2_rn(v2, v3);
                }
            } else {
                float cb0 = bias[c] + molb[c];
                float cb1 = bias[c + 1] + molb[c + 1];
                #pragma unroll
                for (int hh = 0; hh < 2; hh++) {
                    int r = r0 + hh * 8;
                    if (r >= M) continue;
                    float va = hh ? v2 : v0, vb = hh ? v3 : v1;
                    float z0 = 1.0f / (1.0f + __expf(-(va + cb0)));
                    float z1 = 1.0f / (1.0f + __expf(-(vb + cb1)));
                    float2 xv = __half22float2(*(const __half2*)(Ah + (size_t)r * lda + c));
                    float2 hv = __half22float2(*(const __half2*)(Hh + (size_t)r * ldhh + c));
                    float o0 = z0 * xv.x + (1.0f - z0) * hv.x;
                    float o1 = z1 * xv.y + (1.0f - z1) * hv.y;
                    if (Cf) *(float2*)(Cf + (size_t)r * ldc + c) = make_float2(o0, o1);
                    if (Ch) *(__half2*)(Ch + (size_t)r * ldch + c) = __floats2half2_rn(o0, o1);
                }
            }
        }
    }
}

template <int ASRC, int EPI>
static void run_gemm(const void* A, int lda, int K1, const float* A2, int lda2,
                     const __half* Hh, int ldhh,
                     const __half* B1, const __half* B2, int ldb, int SP, int KV1, int KV2,
                     float* Cf, int ldc, __half* Ch, int ldch,
                     int M, int N, int Ktot,
                     const float* bias, int relu, float scale, const float* molb) {
    dim3 grid(N / 128, (M + 127) / 128);
    gemm16_kernel<ASRC, EPI><<<grid, 256>>>(
        A, lda, K1, A2, lda2, Hh, ldhh, B1, B2, ldb, SP, KV1, KV2,
        Cf, ldc, Ch, ldch, M, N, Ktot, bias, relu, scale, molb);
}

// ---------------- attention logits ----------------
__global__ void build_wv_kernel(const float* __restrict__ W, const float* __restrict__ as,
                                const float* __restrict__ ad) {
    int k = blockIdx.x, t = threadIdx.x;
    float w0 = W[(size_t)k * 512 + t], w1 = W[(size_t)k * 512 + 256 + t];
    float p0 = w0 * as[t], p1 = w1 * as[256 + t];
    float p2 = w0 * ad[t], p3 = w1 * ad[256 + t];
    __shared__ float red[8][4];
    int lane = t & 31, wid = t >> 5;
    #pragma unroll
    for (int d = 16; d; d >>= 1) {
        p0 += __shfl_down_sync(0xFFFFFFFFu, p0, d);
        p1 += __shfl_down_sync(0xFFFFFFFFu, p1, d);
        p2 += __shfl_down_sync(0xFFFFFFFFu, p2, d);
        p3 += __shfl_down_sync(0xFFFFFFFFu, p3, d);
    }
    if (lane == 0) { red[wid][0] = p0; red[wid][1] = p1; red[wid][2] = p2; red[wid][3] = p3; }
    __syncthreads();
    if (t == 0) {
        float r0 = 0, r1 = 0, r2 = 0, r3 = 0;
        #pragma unroll
        for (int w = 0; w < 8; w++) { r0 += red[w][0]; r1 += red[w][1]; r2 += red[w][2]; r3 += red[w][3]; }
        d_wv[k * 4 + 0] = r0; d_wv[k * 4 + 1] = r1; d_wv[k * 4 + 2] = r2; d_wv[k * 4 + 3] = r3;
    }
}

// fp32 input (layer 1)
__global__ void attn2_kernel(const float* __restrict__ x, int K) {
    int warp = threadIdx.x >> 5, lane = threadIdx.x & 31;
    int n = blockIdx.x * 4 + warp;
    if (n >= NN) return;
    const float* xr = x + (size_t)n * K;
    float s0 = 0, s1 = 0, s2 = 0, s3 = 0;
    for (int c = lane; c < K; c += 32) {
        float xv = xr[c];
        float4 wv = ((const float4*)d_wv)[c];
        s0 += xv * wv.x; s1 += xv * wv.y; s2 += xv * wv.z; s3 += xv * wv.w;
    }
    #pragma unroll
    for (int d = 16; d; d >>= 1) {
        s0 += __shfl_down_sync(0xFFFFFFFFu, s0, d);
        s1 += __shfl_down_sync(0xFFFFFFFFu, s1, d);
        s2 += __shfl_down_sync(0xFFFFFFFFu, s2, d);
        s3 += __shfl_down_sync(0xFFFFFFFFu, s3, d);
    }
    if (lane == 0) {
        d_asrc[n * 2] = s0; d_asrc[n * 2 + 1] = s1;
        d_adst[n * 2] = s2; d_adst[n * 2 + 1] = s3;
    }
}

// fp16 input (layers 2,3), K = 256, row stride ldh halves
__global__ void attn2h_kernel(const __half* __restrict__ x, int ldh) {
    int warp = threadIdx.x >> 5, lane = threadIdx.x & 31;
    int n = blockIdx.x * 4 + warp;
    if (n >= NN) return;
    const __half2* xr = (const __half2*)(x + (size_t)n * ldh);
    float s0 = 0, s1 = 0, s2 = 0, s3 = 0;
    #pragma unroll
    for (int w = 0; w < 4; w++) {
        int c2 = lane + w * 32;
        float2 xv = __half22float2(xr[c2]);
        float4 wv0 = ((const float4*)d_wv)[c2 * 2];
        float4 wv1 = ((const float4*)d_wv)[c2 * 2 + 1];
        s0 += xv.x * wv0.x + xv.y * wv1.x;
        s1 += xv.x * wv0.y + xv.y * wv1.y;
        s2 += xv.x * wv0.z + xv.y * wv1.z;
        s3 += xv.x * wv0.w + xv.y * wv1.w;
    }
    #pragma unroll
    for (int d = 16; d; d >>= 1) {
        s0 += __shfl_down_sync(0xFFFFFFFFu, s0, d);
        s1 += __shfl_down_sync(0xFFFFFFFFu, s1, d);
        s2 += __shfl_down_sync(0xFFFFFFFFu, s2, d);
        s3 += __shfl_down_sync(0xFFFFFFFFu, s3, d);
    }
    if (lane == 0) {
        d_asrc[n * 2] = s0; d_asrc[n * 2 + 1] = s1;
        d_adst[n * 2] = s2; d_adst[n * 2 + 1] = s3;
    }
}

__device__ __forceinline__ float lrelu02(float v) { return v >= 0.0f ? v : 0.2f * v; }

// ---------------- fused no-max softmax + aggregate ----------------
// Loader phase computes p = exp(lrelu(asrc+adst)) (logits are small: no max needed),
// accumulates per-thread sums; ONE block reduction at the end, scale by 1/sum.

// layer-1 (40 half2 cols, 64 threads, 2 warps)
__global__ void gat_agg80_kernel(const __half2* __restrict__ src,
                                 __half2* __restrict__ agg) {
    int n = blockIdx.x;
    int t = threadIdx.x;  // 64
    int lane = t & 31, wid = t >> 5;
    int s0 = csrA_off[n], s1 = csrA_off[n + 1];
    float2 adst = ((const float2*)d_adst)[n];
    __shared__ int ssrc[64];
    __shared__ float2 salp[64];
    __shared__ float2 ssum[2];
    float a0x = 0, a0y = 0, a1x = 0, a1y = 0, sum0 = 0, sum1 = 0;
    bool act = t < 40;
    for (int base = s0; base < s1; base += 64) {
        int cnt = min(64, s1 - base);
        __syncthreads();
        if (t < cnt) {
            int sidx = csrA_val[base + t];
            ssrc[t] = sidx;
            float2 as = ((const float2*)d_asrc)[sidx];
            float p0 = __expf(lrelu02(as.x + adst.x));
            float p1 = __expf(lrelu02(as.y + adst.y));
            salp[t] = make_float2(p0, p1);
            sum0 += p0; sum1 += p1;
        }
        __syncthreads();
        if (act) {
            #pragma unroll 2
            for (int j = 0; j < cnt; j++) {
                float2 f = __half22float2(src[(size_t)ssrc[j] * 40 + t]);
                float2 a = salp[j];
                a0x += a.x * f.x; a0y += a.x * f.y;
                a1x += a.y * f.x; a1y += a.y * f.y;
            }
        }
    }
    #pragma unroll
    for (int d = 16; d; d >>= 1) {
        sum0 += __shfl_xor_sync(0xFFFFFFFFu, sum0, d);
        sum1 += __shfl_xor_sync(0xFFFFFFFFu, sum1, d);
    }
    if (lane == 0) ssum[wid] = make_float2(sum0, sum1);
    __syncthreads();
    if (act) {
        float r0 = 1.0f / (ssum[0].x + ssum[1].x);
        float r1 = 1.0f / (ssum[0].y + ssum[1].y);
        agg[(size_t)n * 80 + t] = __floats2half2_rn(a0x * r0, a0y * r0);
        agg[(size_t)n * 80 + 40 + t] = __floats2half2_rn(a1x * r1, a1y * r1);
    }
}

// layers 2/3: 128 threads = 2 edge-groups of 64, uint2 loads
__global__ void gat_agg256_kernel(const __half2* __restrict__ src, int ldh2,
                                  __half2* __restrict__ agg) {
    int n = blockIdx.x;
    int t = threadIdx.x;
    int lane = t & 31, wwid = t >> 5;
    int gid = t >> 6, tl = t & 63;
    int s0 = csrA_off[n], s1 = csrA_off[n + 1];
    float2 adst = ((const float2*)d_adst)[n];
    float h0[4] = {0, 0, 0, 0}, h1[4] = {0, 0, 0, 0};
    float sum0 = 0, sum1 = 0;
    __shared__ int ssrc[128];
    __shared__ float2 salp[128];
    __shared__ float red[64][8];
    __shared__ float2 ssum[4];
    for (int base = s0; base < s1; base += 128) {
        int cnt = min(128, s1 - base);
        __syncthreads();
        if (t < cnt) {
            int sidx = csrA_val[base + t];
            ssrc[t] = sidx;
            float2 as = ((const float2*)d_asrc)[sidx];
            float p0 = __expf(lrelu02(as.x + adst.x));
            float p1 = __expf(lrelu02(as.y + adst.y));
            salp[t] = make_float2(p0, p1);
            sum0 += p0; sum1 += p1;
        }
        __syncthreads();
        for (int j = gid; j < cnt; j += 2) {
            uint2 u = *(const uint2*)(src + (size_t)ssrc[j] * ldh2 + tl * 2);
            float2 g0 = __half22float2(*(__half2*)&u.x);
            float2 g1 = __half22float2(*(__half2*)&u.y);
            float2 a = salp[j];
            h0[0] += a.x * g0.x; h0[1] += a.x * g0.y; h0[2] += a.x * g1.x; h0[3] += a.x * g1.y;
            h1[0] += a.y * g0.x; h1[1] += a.y * g0.y; h1[2] += a.y * g1.x; h1[3] += a.y * g1.y;
        }
    }
    #pragma unroll
    for (int d = 16; d; d >>= 1) {
        sum0 += __shfl_xor_sync(0xFFFFFFFFu, sum0, d);
        sum1 += __shfl_xor_sync(0xFFFFFFFFu, sum1, d);
    }
    __syncthreads();
    if (lane == 0) ssum[wwid] = make_float2(sum0, sum1);
    if (gid == 1) {
        red[tl][0] = h0[0]; red[tl][1] = h0[1]; red[tl][2] = h0[2]; red[tl][3] = h0[3];
        red[tl][4] = h1[0]; red[tl][5] = h1[1]; red[tl][6] = h1[2]; red[tl][7] = h1[3];
    }
    __syncthreads();
    if (gid == 0) {
        float ts0 = ssum[0].x + ssum[1].x + ssum[2].x + ssum[3].x;
        float ts1 = ssum[0].y + ssum[1].y + ssum[2].y + ssum[3].y;
        float r0 = 1.0f / ts0, r1 = 1.0f / ts1;
        h0[0] += red[tl][0]; h0[1] += red[tl][1]; h0[2] += red[tl][2]; h0[3] += red[tl][3];
        h1[0] += red[tl][4]; h1[1] += red[tl][5]; h1[2] += red[tl][6]; h1[3] += red[tl][7];
        __half2* row = agg + (size_t)n * 256;
        row[tl * 2] = __floats2half2_rn(h0[0] * r0, h0[1] * r0);
        row[tl * 2 + 1] = __floats2half2_rn(h0[2] * r0, h0[3] * r0);
        row[128 + tl * 2] = __floats2half2_rn(h1[0] * r1, h1[1] * r1);
        row[128 + tl * 2 + 1] = __floats2half2_rn(h1[2] * r1, h1[3] * r1);
    }
}

// ---------------- hypergraph ----------------
template <bool OUTH>
__global__ void hyper_gather_kernel(const __half2* __restrict__ in, void* __restrict__ outp,
                                    int ostride, const float* __restrict__ bias,
                                    int which, int relu) {
    const int* off = which ? csrC_off : csrA_off;
    const int* val = which ? csrC_val : csrA_val;
    int n = blockIdx.x;
    int t = threadIdx.x;
    int gid = t >> 5, tl = t & 31;
    int s0 = off[n], s1 = off[n + 1];
    if (!which) s1 -= 1;
    float a[4] = {0, 0, 0, 0};
    __shared__ int sv[64];
    __shared__ float red[32][4];
    for (int base = s0; base < s1; base += 64) {
        int cnt = min(64, s1 - base);
        __syncthreads();
        if (t < cnt) sv[t] = val[base + t];
        __syncthreads();
        for (int j = gid; j < cnt; j += 2) {
            uint2 u = *(const uint2*)(in + (size_t)sv[j] * 64 + tl * 2);
            float2 g0 = __half22float2(*(__half2*)&u.x);
            float2 g1 = __half22float2(*(__half2*)&u.y);
            a[0] += g0.x; a[1] += g0.y; a[2] += g1.x; a[3] += g1.y;
        }
    }
    __syncthreads();
    if (gid == 1) { red[tl][0] = a[0]; red[tl][1] = a[1]; red[tl][2] = a[2]; red[tl][3] = a[3]; }
    __syncthreads();
    if (gid == 0) {
        a[0] += red[tl][0]; a[1] += red[tl][1]; a[2] += red[tl][2]; a[3] += red[tl][3];
        float inv = which ? d_dinv[n] : d_binv[n];
        #pragma unroll
        for (int q = 0; q < 4; q++) a[q] *= inv;
        if (bias) {
            a[0] += bias[tl * 4]; a[1] += bias[tl * 4 + 1];
            a[2] += bias[tl * 4 + 2]; a[3] += bias[tl * 4 + 3];
        }
        if (relu) {
            #pragma unroll
            for (int q = 0; q < 4; q++) a[q] = fmaxf(a[q], 0.f);
        }
        if (OUTH) {
            __half2* o = (__half2*)outp;
            o[(size_t)n * ostride + tl * 2] = __floats2half2_rn(a[0], a[1]);
            o[(size_t)n * ostride + tl * 2 + 1] = __floats2half2_rn(a[2], a[3]);
        } else {
            float2* o = (float2*)outp;
            o[(size_t)n * ostride + tl * 2] = make_float2(a[0], a[1]);
            o[(size_t)n * ostride + tl * 2 + 1] = make_float2(a[2], a[3]);
        }
    }
}

// ---------------- host side ----------------
extern "C" void kernel_launch(void* const* d_in, const int* in_sizes, int n_in,
                              void* d_out, int out_size) {
    const float* mol_x = (const float*)d_in[0];
    const int*   ei    = (const int*)d_in[1];
    const float* W1 = (const float*)d_in[3];
    const float* as1 = (const float*)d_in[4];
    const float* ad1 = (const float*)d_in[5];
    const float* b1 = (const float*)d_in[6];
    const float* W2 = (const float*)d_in[7];
    const float* as2 = (const float*)d_in[8];
    const float* ad2 = (const float*)d_in[9];
    const float* b2 = (const float*)d_in[10];
    const float* W3 = (const float*)d_in[11];
    const float* as3 = (const float*)d_in[12];
    const float* ad3 = (const float*)d_in[13];
    const float* b3 = (const float*)d_in[14];
    const float* fc1_w = (const float*)d_in[15];
    const float* fc1_b = (const float*)d_in[16];
    const float* fc2_w = (const float*)d_in[17];
    const float* fc2_b = (const float*)d_in[18];
    const float* mol_bias = (const float*)d_in[19];
    const float* theta1 = (const float*)d_in[20];
    const float* hb1 = (const float*)d_in[21];
    const float* theta2 = (const float*)d_in[22];
    const float* hb2 = (const float*)d_in[23];

    __half *p_mx, *p_catA, *p_catB, *p_agg, *p_xt, *p_ef, *p_hy16;
    __half *p_w1h, *p_w2h, *p_w3h, *p_bch, *p_th1h, *p_th2h;
    float *p_cb;
    cudaGetSymbolAddress((void**)&p_mx, d_mx16);
    cudaGetSymbolAddress((void**)&p_catA, d_catA);
    cudaGetSymbolAddress((void**)&p_catB, d_catB);
    cudaGetSymbolAddress((void**)&p_agg, d_agg);
    cudaGetSymbolAddress((void**)&p_xt, d_xt);
    cudaGetSymbolAddress((void**)&p_ef, d_ef);
    cudaGetSymbolAddress((void**)&p_hy16, d_hy16);
    cudaGetSymbolAddress((void**)&p_w1h, d_w1h);
    cudaGetSymbolAddress((void**)&p_w2h, d_w2h);
    cudaGetSymbolAddress((void**)&p_w3h, d_w3h);
    cudaGetSymbolAddress((void**)&p_bch, d_bch);
    cudaGetSymbolAddress((void**)&p_th1h, d_th1h);
    cudaGetSymbolAddress((void**)&p_th2h, d_th2h);
    cudaGetSymbolAddress((void**)&p_cb, d_cb);
    float* p_out = (float*)d_out;

    // ---- CSR build ----
    zero_counts_kernel<<<(NN + 255) / 256, 256>>>();
    count_kernel<<<(EE + 255) / 256, 256>>>(ei);
    scan2_kernel<<<2, 1024>>>();
    fill_kernel<<<(EE + 255) / 256, 256>>>(ei);

    // ---- conversions ----
    conv_mx_kernel<<<(NN * 40 + 255) / 256, 256>>>(mol_x);
    f2h_kernel<<<(FIN * 512 / 2 + 255) / 256, 256>>>(W1, p_w1h, FIN * 512 / 2);
    f2h_kernel<<<(256 * 512 / 2 + 255) / 256, 256>>>(W2, p_w2h, 256 * 512 / 2);
    f2h_kernel<<<(256 * 512 / 2 + 255) / 256, 256>>>(W3, p_w3h, 256 * 512 / 2);
    f2h_kernel<<<(334 * 128 / 2 + 255) / 256, 256>>>(theta1, p_th1h, 334 * 128 / 2);
    f2h_kernel<<<(128 * 128 / 2 + 255) / 256, 256>>>(theta2, p_th2h, 128 * 128 / 2);
    build_bc16_kernel<<<(512 * 256 + 255) / 256, 256>>>(fc1_w, fc2_w, fc1_b, fc2_b);

    // ---- GAT layer 1: h1 (fp16) = relu(gat(mol_x)) ----
    build_wv_kernel<<<FIN, 256>>>(W1, as1, ad1);
    attn2_kernel<<<(NN + 3) / 4, 128>>>(mol_x, FIN);
    gat_agg80_kernel<<<NN, 64>>>((const __half2*)p_mx, (__half2*)p_agg);
    run_gemm<2, 0>(p_agg, 160, 0, nullptr, 0, nullptr, 0, p_w1h, p_w1h + 256, 512, 80, FIN, FIN,
                   nullptr, 0, p_catA + 256, 512, NN, 256, 160, b1, 1, 0.5f, nullptr);

    // ---- GAT layer 2 ----
    build_wv_kernel<<<256, 256>>>(W2, as2, ad2);
    attn2h_kernel<<<(NN + 3) / 4, 128>>>(p_catA + 256, 512);
    gat_agg256_kernel<<<NN, 128>>>((const __half2*)(p_catA + 256), 256, (__half2*)p_agg);
    run_gemm<2, 0>(p_agg, 512, 0, nullptr, 0, nullptr, 0, p_w2h, p_w2h + 256, 512, 256, 256, 256,
                   nullptr, 0, p_catA, 512, NN, 256, 512, b2, 1, 0.5f, nullptr);
    run_gemm<2, 2>(p_catA, 512, 0, nullptr, 0, p_catA + 256, 512, p_bch, nullptr, 256, 512, 512, 0,
                   nullptr, 0, p_catB + 256, 512, NN, 256, 512, p_cb, 0, 1.0f, mol_bias);
    // h2 fp16 in catB[256:)

    // ---- GAT layer 3 ----
    build_wv_kernel<<<256, 256>>>(W3, as3, ad3);
    attn2h_kernel<<<(NN + 3) / 4, 128>>>(p_catB + 256, 512);
    gat_agg256_kernel<<<NN, 128>>>((const __half2*)(p_catB + 256), 256, (__half2*)p_agg);
    run_gemm<2, 0>(p_agg, 512, 0, nullptr, 0, nullptr, 0, p_w3h, p_w3h + 256, 512, 256, 256, 256,
                   nullptr, 0, p_catB, 512, NN, 256, 512, b3, 0, 0.5f, nullptr);
    run_gemm<2, 2>(p_catB, 512, 0, nullptr, 0, p_catB + 256, 512, p_bch, nullptr, 256, 512, 512, 0,
                   p_out, 384, nullptr, 0, NN, 256, 512, p_cb, 0, 1.0f, mol_bias);
    // final h fp32 in d_out[:, 0:256)

    // ---- hypergraph branch ----
    run_gemm<0, 0>(p_out, 384, 256, mol_x, FIN, nullptr, 0, p_th1h, nullptr, 128, 334, 334, 0,
                   nullptr, 0, p_xt, 128, NN, 128, 334, nullptr, 0, 1.0f, nullptr);
    hyper_gather_kernel<true ><<<NN, 64>>>((const __half2*)p_xt, p_ef, 64, nullptr, 0, 0);
    hyper_gather_kernel<true ><<<NN, 64>>>((const __half2*)p_ef, p_hy16, 64, hb1, 1, 1);
    run_gemm<2, 0>(p_hy16, 128, 0, nullptr, 0, nullptr, 0, p_th2h, nullptr, 128, 128, 128, 0,
                   nullptr, 0, p_xt, 128, NN, 128, 128, nullptr, 0, 1.0f, nullptr);
    hyper_gather_kernel<true ><<<NN, 64>>>((const __half2*)p_xt, p_ef, 64, nullptr, 0, 0);
    hyper_gather_kernel<false><<<NN, 64>>>((const __half2*)p_ef, (float2*)p_out + 128, 192,
                                           hb2, 1, 1);
}

// round 12
// speedup vs baseline: 1.6162x; 1.0670x over previous
#include <cuda_runtime.h>
#include <cuda_fp16.h>
#include <math.h>
#include <stdint.h>

#define NN 100000
#define EE 3200000
#define EA (EE + NN)
#define FIN 78
#define FG 256
#define FH 128
#define NBLK 98   // ceil(NN / 1024)

// ---------------- scratch (device globals; no allocation) ----------------
__device__ __half d_mx16[(size_t)NN * 80];
__device__ __half d_catA[(size_t)NN * 512];   // [x1 | h1]
__device__ __half d_catB[(size_t)NN * 512];   // [x2 | h2]
__device__ __half d_agg[(size_t)NN * 512];
__device__ __half d_xt[(size_t)NN * 128];
__device__ __half d_ef[(size_t)NN * 128];
__device__ __half d_hy16[(size_t)NN * 128];
__device__ __half d_w1h[FIN * 512];
__device__ __half d_w2h[256 * 512];
__device__ __half d_w3h[256 * 512];
__device__ __half d_bch[512 * 256];
__device__ __half d_th1h[334 * 128];
__device__ __half d_th2h[128 * 128];
__device__ float d_cb[256];
__device__ float d_wv[256 * 4];
__device__ float d_asrc[NN * 2];
__device__ float d_adst[NN * 2];
__device__ int csrA_off[NN + 1]; __device__ int csrA_val[EA];
__device__ int csrC_off[NN + 1]; __device__ int csrC_val[EE];
__device__ int cntA[NN], cntC[NN];
__device__ int curA[NN], curC[NN];
__device__ int d_part[2][NBLK + 2];
__device__ float d_binv[NN], d_dinv[NN];

// ---------------- CSR construction ----------------
__global__ void zero_counts_kernel() {
    int i = blockIdx.x * blockDim.x + threadIdx.x;
    if (i < NN) { cntA[i] = 0; cntC[i] = 0; }
}

__global__ void count_kernel(const int* __restrict__ ei) {
    int i = blockIdx.x * blockDim.x + threadIdx.x;
    if (i >= EE) return;
    int s = ei[i];
    int d = ei[EE + i];
    atomicAdd(&cntA[d], 1);
    atomicAdd(&cntC[s], 1);
}

// phase 1: per-block sums
__global__ void scan_p1() {
    int a = blockIdx.y;
    int i = blockIdx.x * 1024 + threadIdx.x;
    int v = 0;
    if (i < NN) v = (a == 0) ? (cntA[i] + 1) : cntC[i];
    int lane = threadIdx.x & 31, wid = threadIdx.x >> 5;
    #pragma unroll
    for (int d = 16; d; d >>= 1) v += __shfl_down_sync(0xFFFFFFFFu, v, d);
    __shared__ int ws[32];
    if (lane == 0) ws[wid] = v;
    __syncthreads();
    if (wid == 0) {
        int x = ws[lane];
        #pragma unroll
        for (int d = 16; d; d >>= 1) x += __shfl_down_sync(0xFFFFFFFFu, x, d);
        if (lane == 0) d_part[a][blockIdx.x] = x;
    }
}

// phase 2: exclusive scan of NBLK partials (2 blocks, 128 threads)
__global__ void scan_p2() {
    int a = blockIdx.x;
    int t = threadIdx.x;
    int v = (t < NBLK) ? d_part[a][t] : 0;
    int lane = t & 31, wid = t >> 5;
    int x = v;
    #pragma unroll
    for (int d = 1; d < 32; d <<= 1) {
        int y = __shfl_up_sync(0xFFFFFFFFu, x, d);
        if (lane >= d) x += y;
    }
    __shared__ int ws[4];
    if (lane == 31) ws[wid] = x;
    __syncthreads();
    int off = 0;
    for (int w = 0; w < wid; w++) off += ws[w];
    if (t < NBLK) d_part[a][t] = off + x - v;
}

// phase 3: in-block exclusive scan + global offset + side effects
__global__ void scan_p3() {
    int a = blockIdx.y;
    int i = blockIdx.x * 1024 + threadIdx.x;
    int raw = 0;
    if (i < NN) raw = (a == 0) ? cntA[i] : cntC[i];
    int v = raw + ((a == 0 && i < NN) ? 1 : 0);
    int lane = threadIdx.x & 31, wid = threadIdx.x >> 5;
    int x = v;
    #pragma unroll
    for (int d = 1; d < 32; d <<= 1) {
        int y = __shfl_up_sync(0xFFFFFFFFu, x, d);
        if (lane >= d) x += y;
    }
    __shared__ int ws[32];
    if (lane == 31) ws[wid] = x;
    __syncthreads();
    if (wid == 0) {
        int w = ws[lane];
        #pragma unroll
        for (int d = 1; d < 32; d <<= 1) {
            int y = __shfl_up_sync(0xFFFFFFFFu, w, d);
            if (lane >= d) w += y;
        }
        ws[lane] = w;
    }
    __syncthreads();
    int excl = (wid ? ws[wid - 1] : 0) + x - v + d_part[a][blockIdx.x];
    if (i < NN) {
        if (a == 0) {
            csrA_off[i] = excl;
            curA[i] = excl;
            csrA_val[excl + raw] = i;   // self loop pinned at segment end
            d_binv[i] = raw > 0 ? 1.0f / (float)raw : 0.0f;
        } else {
            csrC_off[i] = excl;
            curC[i] = excl;
            d_dinv[i] = raw > 0 ? 1.0f / (float)raw : 0.0f;
        }
    }
    if (i == NN - 1) {
        if (a == 0) csrA_off[NN] = excl + v;
        else csrC_off[NN] = excl + v;
    }
}

__global__ void fill_kernel(const int* __restrict__ ei) {
    int i = blockIdx.x * blockDim.x + threadIdx.x;
    if (i >= EE) return;
    int s = ei[i];
    int d = ei[EE + i];
    csrA_val[atomicAdd(&curA[d], 1)] = s;
    csrC_val[atomicAdd(&curC[s], 1)] = d;
}

// ---------------- weight conversion ----------------
__global__ void f2h_kernel(const float* __restrict__ src, __half* __restrict__ dst, int n2) {
    int i = blockIdx.x * blockDim.x + threadIdx.x;
    if (i < n2) {
        float2 v = ((const float2*)src)[i];
        ((__half2*)dst)[i] = __floats2half2_rn(v.x, v.y);
    }
}

__global__ void build_bc16_kernel(const float* __restrict__ fc1w, const float* __restrict__ fc2w,
                                  const float* __restrict__ fc1b, const float* __restrict__ fc2b) {
    int idx = blockIdx.x * blockDim.x + threadIdx.x;
    if (idx >= 512 * 256) return;
    int k = idx >> 8, n = idx & 255;
    float v = (k < 256) ? fc1w[n * 256 + k] : fc2w[n * 256 + (k - 256)];
    d_bch[idx] = __float2half_rn(v);
    if (idx < 256) d_cb[idx] = fc1b[idx] + fc2b[idx];
}

__global__ void conv_mx_kernel(const float* __restrict__ x) {
    int idx = blockIdx.x * blockDim.x + threadIdx.x;
    if (idx >= NN * 40) return;
    int n = idx / 40, c2 = idx % 40;
    float a = 0.f, b = 0.f;
    int c = c2 * 2;
    if (c < FIN) a = x[(size_t)n * FIN + c];
    if (c + 1 < FIN) b = x[(size_t)n * FIN + c + 1];
    ((__half2*)d_mx16)[idx] = __floats2half2_rn(a, b);
}

// ---------------- fp16 tensor-core GEMM (m16n8k16 + ldmatrix + cp.async) ----------------
__device__ __forceinline__ void mma_f16(float* c, const uint32_t* a, uint32_t b0, uint32_t b1) {
    asm volatile(
        "mma.sync.aligned.m16n8k16.row.col.f32.f16.f16.f32 "
        "{%0,%1,%2,%3},{%4,%5,%6,%7},{%8,%9},{%0,%1,%2,%3};"
        : "+f"(c[0]), "+f"(c[1]), "+f"(c[2]), "+f"(c[3])
        : "r"(a[0]), "r"(a[1]), "r"(a[2]), "r"(a[3]), "r"(b0), "r"(b1));
}

__device__ __forceinline__ void ldsm_x4(uint32_t& r0, uint32_t& r1, uint32_t& r2, uint32_t& r3,
                                        uint32_t addr) {
    asm volatile("ldmatrix.sync.aligned.m8n8.x4.shared.b16 {%0,%1,%2,%3}, [%4];"
                 : "=r"(r0), "=r"(r1), "=r"(r2), "=r"(r3) : "r"(addr));
}

__device__ __forceinline__ void ldsm_x4t(uint32_t& r0, uint32_t& r1, uint32_t& r2, uint32_t& r3,
                                         uint32_t addr) {
    asm volatile("ldmatrix.sync.aligned.m8n8.x4.trans.shared.b16 {%0,%1,%2,%3}, [%4];"
                 : "=r"(r0), "=r"(r1), "=r"(r2), "=r"(r3) : "r"(addr));
}

__device__ __forceinline__ void cp8(uint32_t d, const void* s) {
    asm volatile("cp.async.ca.shared.global [%0], [%1], 8;" :: "r"(d), "l"(s));
}
__device__ __forceinline__ void cp8z(uint32_t d, const void* s, int sz) {
    asm volatile("cp.async.ca.shared.global [%0], [%1], 8, %2;" :: "r"(d), "l"(s), "r"(sz));
}
__device__ __forceinline__ void cp_commit() {
    asm volatile("cp.async.commit_group;");
}
template <int N>
__device__ __forceinline__ void cp_wait() {
    asm volatile("cp.async.wait_group %0;" :: "n"(N));
}

#define APITCH 80
#define BPITCH 272
#define ABYTES (128 * APITCH)
#define BBYTES (32 * BPITCH)

// ASRC: 0 = fp32 A (+optional concat A2 fp32) [register path], 2 = fp16 A [cp.async path]
// EPI:  0 = v*scale+bias(+relu) -> optional fp32 Cf and fp16 Ch
//       2 = gate blend: z=sig(v+bias+molb); o=z*x(fp16 A)+(1-z)*h(fp16 Hh)
template <int ASRC, int EPI>
__global__ __launch_bounds__(256) void gemm16_kernel(
    const void* __restrict__ Ap, int lda, int K1,
    const float* __restrict__ A2, int lda2,
    const __half* __restrict__ Hh, int ldhh,
    const __half* __restrict__ B1, const __half* __restrict__ B2, int ldb,
    int SP, int KV1, int KV2,
    float* __restrict__ Cf, int ldc,
    __half* __restrict__ Ch, int ldch,
    int M, int N, int Ktot,
    const float* __restrict__ bias, int relu, float scale,
    const float* __restrict__ molb)
{
    __shared__ __align__(16) uint8_t AsmB[2 * ABYTES];
    __shared__ __align__(16) uint8_t BsmB[2 * BBYTES];
    int tid = threadIdx.x;
    int lane = tid & 31, wid = tid >> 5;
    int wm = wid & 3, wn = wid >> 2;
    int row0 = blockIdx.y * 128, col0 = blockIdx.x * 128;
    int g = lane >> 2, tg = lane & 3;
    int l15 = lane & 15;
    int lhi = (lane & 16) ? 8 : 0;

    float acc[2][8][4];
    #pragma unroll
    for (int mi = 0; mi < 2; mi++)
        #pragma unroll
        for (int ni = 0; ni < 8; ni++)
            #pragma unroll
            for (int q = 0; q < 4; q++) acc[mi][ni][q] = 0.0f;

    const float* Af = (const float*)Ap;
    const __half* Ah = (const __half*)Ap;

    uint32_t aShm = (uint32_t)__cvta_generic_to_shared(AsmB);
    uint32_t bShm = (uint32_t)__cvta_generic_to_shared(BsmB);
    int T = (Ktot + 31) >> 5;

    auto computeTile = [&](int buf) {
        uint32_t aB = aShm + buf * ABYTES;
        uint32_t bB = bShm + buf * BBYTES;
        #pragma unroll
        for (int ks = 0; ks < 2; ks++) {
            uint32_t afr[2][4];
            #pragma unroll
            for (int mi = 0; mi < 2; mi++) {
                uint32_t addr = aB + (uint32_t)((wm * 32 + mi * 16 + l15) * APITCH
                                                + (ks * 16 + lhi) * 2);
                ldsm_x4(afr[mi][0], afr[mi][1], afr[mi][2], afr[mi][3], addr);
            }
            uint32_t bfr[8][2];
            #pragma unroll
            for (int p = 0; p < 4; p++) {
                uint32_t addr = bB + (uint32_t)((ks * 16 + l15) * BPITCH
                                                + (wn * 64 + p * 16 + lhi) * 2);
                ldsm_x4t(bfr[2 * p][0], bfr[2 * p][1], bfr[2 * p + 1][0], bfr[2 * p + 1][1], addr);
            }
            #pragma unroll
            for (int ni = 0; ni < 8; ni++) {
                mma_f16(acc[0][ni], afr[0], bfr[ni][0], bfr[ni][1]);
                mma_f16(acc[1][ni], afr[1], bfr[ni][0], bfr[ni][1]);
            }
        }
    };

    if (ASRC == 2) {
        // ---------- cp.async pipeline ----------
        auto issueTile = [&](int k0, int buf) {
            uint32_t aB = aShm + buf * ABYTES;
            uint32_t bB = bShm + buf * BBYTES;
            #pragma unroll
            for (int i = 0; i < 4; i++) {
                int l4 = tid + i * 256;
                int r = l4 >> 3, c4 = (l4 & 7) << 2;
                int grow = row0 + r;
                if (grow >= M) grow = M - 1;   // clamp: A row r only feeds C row r (store-guarded)
                int gk = k0 + c4;
                cp8(aB + r * APITCH + c4 * 2, Ah + (size_t)grow * lda + gk);
            }
            #pragma unroll
            for (int i = 0; i < 4; i++) {
                int l4 = tid + i * 256;
                int k = l4 >> 5, n4 = (l4 & 31) << 2;
                int kk = k0 + k;
                const __half* src = B1;
                int sz = 0;
                if (kk < SP) {
                    if (kk < KV1) { src = B1 + (size_t)kk * ldb + col0 + n4; sz = 8; }
                } else if (kk < Ktot) {
                    int j = kk - SP;
                    if (j < KV2) { src = B2 + (size_t)j * ldb + col0 + n4; sz = 8; }
                }
                cp8z(bB + k * BPITCH + n4 * 2, src, sz);
            }
            cp_commit();
        };
        issueTile(0, 0);
        for (int t = 0; t < T; t++) {
            int buf = t & 1;
            bool more = (t + 1 < T);
            if (more) {
                issueTile((t + 1) << 5, buf ^ 1);
                cp_wait<1>();
            } else {
                cp_wait<0>();
            }
            __syncthreads();
            computeTile(buf);
            __syncthreads();
        }
    } else {
        // ---------- register-staged pipeline (fp32 A with concat) ----------
        float4 raf[4];
        uint2 rbh[4];
        auto loadA = [&](int k0) {
            #pragma unroll
            for (int i = 0; i < 4; i++) {
                int l4 = tid + i * 256;
                int r = l4 >> 3, c4 = (l4 & 7) << 2;
                int grow = row0 + r, gk = k0 + c4;
                float4 v = make_float4(0.f, 0.f, 0.f, 0.f);
                if (grow < M) {
                    if (gk + 3 < K1) {
                        v = *(const float4*)(Af + (size_t)grow * lda + gk);
                    } else {
                        float* pv = &v.x;
                        #pragma unroll
                        for (int j = 0; j < 4; j++) {
                            int kk = gk + j;
                            float x = 0.0f;
                            if (kk < K1) x = Af[(size_t)grow * lda + kk];
                            else if (kk < Ktot) x = A2[(size_t)grow * lda2 + (kk - K1)];
                            pv[j] = x;
                        }
                    }
                }
                raf[i] = v;
            }
        };
        auto storeA = [&](uint8_t* As) {
            #pragma unroll
            for (int i = 0; i < 4; i++) {
                int l4 = tid + i * 256;
                int r = l4 >> 3, c4 = (l4 & 7) << 2;
                __half2 h0 = __floats2half2_rn(raf[i].x, raf[i].y);
                __half2 h1 = __floats2half2_rn(raf[i].z, raf[i].w);
                uint2 u;
                u.x = *(uint32_t*)&h0;
                u.y = *(uint32_t*)&h1;
                *(uint2*)(As + r * APITCH + c4 * 2) = u;
            }
        };
        auto loadB = [&](int k0) {
            #pragma unroll
            for (int i = 0; i < 4; i++) {
                int l4 = tid + i * 256;
                int k = l4 >> 5, n4 = (l4 & 31) << 2;
                int kk = k0 + k;
                uint2 u = make_uint2(0u, 0u);
                if (kk < SP) {
                    if (kk < KV1) u = *(const uint2*)(B1 + (size_t)kk * ldb + col0 + n4);
                } else if (kk < Ktot) {
                    int j = kk - SP;
                    if (j < KV2) u = *(const uint2*)(B2 + (size_t)j * ldb + col0 + n4);
                }
                rbh[i] = u;
            }
        };
        auto storeB = [&](uint8_t* Bs) {
            #pragma unroll
            for (int i = 0; i < 4; i++) {
                int l4 = tid + i * 256;
                int k = l4 >> 5, n4 = (l4 & 31) << 2;
                *(uint2*)(Bs + k * BPITCH + n4 * 2) = rbh[i];
            }
        };
        loadA(0); loadB(0);
        storeA(AsmB); storeB(BsmB);
        __syncthreads();
        for (int t = 0; t < T; t++) {
            int buf = t & 1;
            bool more = (t + 1 < T);
            if (more) { loadA((t + 1) << 5); loadB((t + 1) << 5); }
            computeTile(buf);
            if (more) {
                storeA(AsmB + (buf ^ 1) * ABYTES);
                storeB(BsmB + (buf ^ 1) * BBYTES);
            }
            __syncthreads();
        }
    }

    // epilogue
    #pragma unroll
    for (int mi = 0; mi < 2; mi++) {
        int r0 = row0 + wm * 32 + mi * 16 + g;
        #pragma unroll
        for (int ni = 0; ni < 8; ni++) {
            int c = col0 + wn * 64 + ni * 8 + tg * 2;
            float v0 = acc[mi][ni][0], v1 = acc[mi][ni][1];
            float v2 = acc[mi][ni][2], v3 = acc[mi][ni][3];
            if (EPI == 0) {
                float b0v = bias ? bias[c] : 0.0f;
                float b1v = bias ? bias[c + 1] : 0.0f;
                v0 = v0 * scale + b0v; v1 = v1 * scale + b1v;
                v2 = v2 * scale + b0v; v3 = v3 * scale + b1v;
                if (relu) {
                    v0 = fmaxf(v0, 0.f); v1 = fmaxf(v1, 0.f);
                    v2 = fmaxf(v2, 0.f); v3 = fmaxf(v3, 0.f);
                }
                if (r0 < M) {
                    if (Cf) *(float2*)(Cf + (size_t)r0 * ldc + c) = make_float2(v0, v1);
                    if (Ch) *(__half2*)(Ch + (size_t)r0 * ldch + c) = __floats2half2_rn(v0, v1);
                }
                if (r0 + 8 < M) {
                    if (Cf) *(float2*)(Cf + (size_t)(r0 + 8) * ldc + c) = make_float2(v2, v3);
                    if (Ch) *(__half2*)(Ch + (size_t)(r0 + 8) * ldch + c) = __floats2half2_rn(v2, v3);
                }
            } else {
                const __half* Ah2 = (const __half*)Ap;
                float cb0 = bias[c] + molb[c];
                float cb1 = bias[c + 1] + molb[c + 1];
                #pragma unroll
                for (int hh = 0; hh < 2; hh++) {
                    int r = r0 + hh * 8;
                    if (r >= M) continue;
                    float va = hh ? v2 : v0, vb = hh ? v3 : v1;
                    float z0 = 1.0f / (1.0f + __expf(-(va + cb0)));
                    float z1 = 1.0f / (1.0f + __expf(-(vb + cb1)));
                    float2 xv = __half22float2(*(const __half2*)(Ah2 + (size_t)r * lda + c));
                    float2 hv = __half22float2(*(const __half2*)(Hh + (size_t)r * ldhh + c));
                    float o0 = z0 * xv.x + (1.0f - z0) * hv.x;
                    float o1 = z1 * xv.y + (1.0f - z1) * hv.y;
                    if (Cf) *(float2*)(Cf + (size_t)r * ldc + c) = make_float2(o0, o1);
                    if (Ch) *(__half2*)(Ch + (size_t)r * ldch + c) = __floats2half2_rn(o0, o1);
                }
            }
        }
    }
}

template <int ASRC, int EPI>
static void run_gemm(const void* A, int lda, int K1, const float* A2, int lda2,
                     const __half* Hh, int ldhh,
                     const __half* B1, const __half* B2, int ldb, int SP, int KV1, int KV2,
                     float* Cf, int ldc, __half* Ch, int ldch,
                     int M, int N, int Ktot,
                     const float* bias, int relu, float scale, const float* molb) {
    dim3 grid(N / 128, (M + 127) / 128);
    gemm16_kernel<ASRC, EPI><<<grid, 256>>>(
        A, lda, K1, A2, lda2, Hh, ldhh, B1, B2, ldb, SP, KV1, KV2,
        Cf, ldc, Ch, ldch, M, N, Ktot, bias, relu, scale, molb);
}

// ---------------- attention logits ----------------
__global__ void build_wv_kernel(const float* __restrict__ W, const float* __restrict__ as,
                                const float* __restrict__ ad) {
    int k = blockIdx.x, t = threadIdx.x;
    float w0 = W[(size_t)k * 512 + t], w1 = W[(size_t)k * 512 + 256 + t];
    float p0 = w0 * as[t], p1 = w1 * as[256 + t];
    float p2 = w0 * ad[t], p3 = w1 * ad[256 + t];
    __shared__ float red[8][4];
    int lane = t & 31, wid = t >> 5;
    #pragma unroll
    for (int d = 16; d; d >>= 1) {
        p0 += __shfl_down_sync(0xFFFFFFFFu, p0, d);
        p1 += __shfl_down_sync(0xFFFFFFFFu, p1, d);
        p2 += __shfl_down_sync(0xFFFFFFFFu, p2, d);
        p3 += __shfl_down_sync(0xFFFFFFFFu, p3, d);
    }
    if (lane == 0) { red[wid][0] = p0; red[wid][1] = p1; red[wid][2] = p2; red[wid][3] = p3; }
    __syncthreads();
    if (t == 0) {
        float r0 = 0, r1 = 0, r2 = 0, r3 = 0;
        #pragma unroll
        for (int w = 0; w < 8; w++) { r0 += red[w][0]; r1 += red[w][1]; r2 += red[w][2]; r3 += red[w][3]; }
        d_wv[k * 4 + 0] = r0; d_wv[k * 4 + 1] = r1; d_wv[k * 4 + 2] = r2; d_wv[k * 4 + 3] = r3;
    }
}

__global__ void attn2_kernel(const float* __restrict__ x, int K) {
    int warp = threadIdx.x >> 5, lane = threadIdx.x & 31;
    int n = blockIdx.x * 4 + warp;
    if (n >= NN) return;
    const float* xr = x + (size_t)n * K;
    float s0 = 0, s1 = 0, s2 = 0, s3 = 0;
    for (int c = lane; c < K; c += 32) {
        float xv = xr[c];
        float4 wv = ((const float4*)d_wv)[c];
        s0 += xv * wv.x; s1 += xv * wv.y; s2 += xv * wv.z; s3 += xv * wv.w;
    }
    #pragma unroll
    for (int d = 16; d; d >>= 1) {
        s0 += __shfl_down_sync(0xFFFFFFFFu, s0, d);
        s1 += __shfl_down_sync(0xFFFFFFFFu, s1, d);
        s2 += __shfl_down_sync(0xFFFFFFFFu, s2, d);
        s3 += __shfl_down_sync(0xFFFFFFFFu, s3, d);
    }
    if (lane == 0) {
        d_asrc[n * 2] = s0; d_asrc[n * 2 + 1] = s1;
        d_adst[n * 2] = s2; d_adst[n * 2 + 1] = s3;
    }
}

__global__ void attn2h_kernel(const __half* __restrict__ x, int ldh) {
    int warp = threadIdx.x >> 5, lane = threadIdx.x & 31;
    int n = blockIdx.x * 4 + warp;
    if (n >= NN) return;
    const __half2* xr = (const __half2*)(x + (size_t)n * ldh);
    float s0 = 0, s1 = 0, s2 = 0, s3 = 0;
    #pragma unroll
    for (int w = 0; w < 4; w++) {
        int c2 = lane + w * 32;
        float2 xv = __half22float2(xr[c2]);
        float4 wv0 = ((const float4*)d_wv)[c2 * 2];
        float4 wv1 = ((const float4*)d_wv)[c2 * 2 + 1];
        s0 += xv.x * wv0.x + xv.y * wv1.x;
        s1 += xv.x * wv0.y + xv.y * wv1.y;
        s2 += xv.x * wv0.z + xv.y * wv1.z;
        s3 += xv.x * wv0.w + xv.y * wv1.w;
    }
    #pragma unroll
    for (int d = 16; d; d >>= 1) {
        s0 += __shfl_down_sync(0xFFFFFFFFu, s0, d);
        s1 += __shfl_down_sync(0xFFFFFFFFu, s1, d);
        s2 += __shfl_down_sync(0xFFFFFFFFu, s2, d);
        s3 += __shfl_down_sync(0xFFFFFFFFu, s3, d);
    }
    if (lane == 0) {
        d_asrc[n * 2] = s0; d_asrc[n * 2 + 1] = s1;
        d_adst[n * 2] = s2; d_adst[n * 2 + 1] = s3;
    }
}

__device__ __forceinline__ float lrelu02(float v) { return v >= 0.0f ? v : 0.2f * v; }

// ---------------- fused no-max softmax + aggregate ----------------
__global__ void gat_agg80_kernel(const __half2* __restrict__ src,
                                 __half2* __restrict__ agg) {
    int n = blockIdx.x;
    int t = threadIdx.x;  // 64
    int lane = t & 31, wid = t >> 5;
    int s0 = csrA_off[n], s1 = csrA_off[n + 1];
    float2 adst = ((const float2*)d_adst)[n];
    __shared__ int ssrc[64];
    __shared__ float2 salp[64];
    __shared__ float2 ssum[2];
    float a0x = 0, a0y = 0, a1x = 0, a1y = 0, sum0 = 0, sum1 = 0;
    bool act = t < 40;
    for (int base = s0; base < s1; base += 64) {
        int cnt = min(64, s1 - base);
        __syncthreads();
        if (t < cnt) {
            int sidx = csrA_val[base + t];
            ssrc[t] = sidx;
            float2 as = ((const float2*)d_asrc)[sidx];
            float p0 = __expf(lrelu02(as.x + adst.x));
            float p1 = __expf(lrelu02(as.y + adst.y));
            salp[t] = make_float2(p0, p1);
            sum0 += p0; sum1 += p1;
        }
        __syncthreads();
        if (act) {
            #pragma unroll 2
            for (int j = 0; j < cnt; j++) {
                float2 f = __half22float2(src[(size_t)ssrc[j] * 40 + t]);
                float2 a = salp[j];
                a0x += a.x * f.x; a0y += a.x * f.y;
                a1x += a.y * f.x; a1y += a.y * f.y;
            }
        }
    }
    #pragma unroll
    for (int d = 16; d; d >>= 1) {
        sum0 += __shfl_xor_sync(0xFFFFFFFFu, sum0, d);
        sum1 += __shfl_xor_sync(0xFFFFFFFFu, sum1, d);
    }
    if (lane == 0) ssum[wid] = make_float2(sum0, sum1);
    __syncthreads();
    if (act) {
        float r0 = 1.0f / (ssum[0].x + ssum[1].x);
        float r1 = 1.0f / (ssum[0].y + ssum[1].y);
        agg[(size_t)n * 80 + t] = __floats2half2_rn(a0x * r0, a0y * r0);
        agg[(size_t)n * 80 + 40 + t] = __floats2half2_rn(a1x * r1, a1y * r1);
    }
}

__global__ void gat_agg256_kernel(const __half2* __restrict__ src, int ldh2,
                                  __half2* __restrict__ agg) {
    int n = blockIdx.x;
    int t = threadIdx.x;
    int lane = t & 31, wwid = t >> 5;
    int gid = t >> 6, tl = t & 63;
    int s0 = csrA_off[n], s1 = csrA_off[n + 1];
    float2 adst = ((const float2*)d_adst)[n];
    float h0[4] = {0, 0, 0, 0}, h1[4] = {0, 0, 0, 0};
    float sum0 = 0, sum1 = 0;
    __shared__ int ssrc[128];
    __shared__ float2 salp[128];
    __shared__ float red[64][8];
    __shared__ float2 ssum[4];
    for (int base = s0; base < s1; base += 128) {
        int cnt = min(128, s1 - base);
        __syncthreads();
        if (t < cnt) {
            int sidx = csrA_val[base + t];
            ssrc[t] = sidx;
            float2 as = ((const float2*)d_asrc)[sidx];
            float p0 = __expf(lrelu02(as.x + adst.x));
            float p1 = __expf(lrelu02(as.y + adst.y));
            salp[t] = make_float2(p0, p1);
            sum0 += p0; sum1 += p1;
        }
        __syncthreads();
        for (int j = gid; j < cnt; j += 2) {
            uint2 u = *(const uint2*)(src + (size_t)ssrc[j] * ldh2 + tl * 2);
            float2 g0 = __half22float2(*(__half2*)&u.x);
            float2 g1 = __half22float2(*(__half2*)&u.y);
            float2 a = salp[j];
            h0[0] += a.x * g0.x; h0[1] += a.x * g0.y; h0[2] += a.x * g1.x; h0[3] += a.x * g1.y;
            h1[0] += a.y * g0.x; h1[1] += a.y * g0.y; h1[2] += a.y * g1.x; h1[3] += a.y * g1.y;
        }
    }
    #pragma unroll
    for (int d = 16; d; d >>= 1) {
        sum0 += __shfl_xor_sync(0xFFFFFFFFu, sum0, d);
        sum1 += __shfl_xor_sync(0xFFFFFFFFu, sum1, d);
    }
    __syncthreads();
    if (lane == 0) ssum[wwid] = make_float2(sum0, sum1);
    if (gid == 1) {
        red[tl][0] = h0[0]; red[tl][1] = h0[1]; red[tl][2] = h0[2]; red[tl][3] = h0[3];
        red[tl][4] = h1[0]; red[tl][5] = h1[1]; red[tl][6] = h1[2]; red[tl][7] = h1[3];
    }
    __syncthreads();
    if (gid == 0) {
        float ts0 = ssum[0].x + ssum[1].x + ssum[2].x + ssum[3].x;
        float ts1 = ssum[0].y + ssum[1].y + ssum[2].y + ssum[3].y;
        float r0 = 1.0f / ts0, r1 = 1.0f / ts1;
        h0[0] += red[tl][0]; h0[1] += red[tl][1]; h0[2] += red[tl][2]; h0[3] += red[tl][3];
        h1[0] += red[tl][4]; h1[1] += red[tl][5]; h1[2] += red[tl][6]; h1[3] += red[tl][7];
        __half2* row = agg + (size_t)n * 256;
        row[tl * 2] = __floats2half2_rn(h0[0] * r0, h0[1] * r0);
        row[tl * 2 + 1] = __floats2half2_rn(h0[2] * r0, h0[3] * r0);
        row[128 + tl * 2] = __floats2half2_rn(h1[0] * r1, h1[1] * r1);
        row[128 + tl * 2 + 1] = __floats2half2_rn(h1[2] * r1, h1[3] * r1);
    }
}

// ---------------- hypergraph ----------------
template <bool OUTH>
__global__ void hyper_gather_kernel(const __half2* __restrict__ in, void* __restrict__ outp,
                                    int ostride, const float* __restrict__ bias,
                                    int which, int relu) {
    const int* off = which ? csrC_off : csrA_off;
    const int* val = which ? csrC_val : csrA_val;
    int n = blockIdx.x;
    int t = threadIdx.x;
    int gid = t >> 5, tl = t & 31;
    int s0 = off[n], s1 = off[n + 1];
    if (!which) s1 -= 1;
    float a[4] = {0, 0, 0, 0};
    __shared__ int sv[64];
    __shared__ float red[32][4];
    for (int base = s0; base < s1; base += 64) {
        int cnt = min(64, s1 - base);
        __syncthreads();
        if (t < cnt) sv[t] = val[base + t];
        __syncthreads();
        for (int j = gid; j < cnt; j += 2) {
            uint2 u = *(const uint2*)(in + (size_t)sv[j] * 64 + tl * 2);
            float2 g0 = __half22float2(*(__half2*)&u.x);
            float2 g1 = __half22float2(*(__half2*)&u.y);
            a[0] += g0.x; a[1] += g0.y; a[2] += g1.x; a[3] += g1.y;
        }
    }
    __syncthreads();
    if (gid == 1) { red[tl][0] = a[0]; red[tl][1] = a[1]; red[tl][2] = a[2]; red[tl][3] = a[3]; }
    __syncthreads();
    if (gid == 0) {
        a[0] += red[tl][0]; a[1] += red[tl][1]; a[2] += red[tl][2]; a[3] += red[tl][3];
        float inv = which ? d_dinv[n] : d_binv[n];
        #pragma unroll
        for (int q = 0; q < 4; q++) a[q] *= inv;
        if (bias) {
            a[0] += bias[tl * 4]; a[1] += bias[tl * 4 + 1];
            a[2] += bias[tl * 4 + 2]; a[3] += bias[tl * 4 + 3];
        }
        if (relu) {
            #pragma unroll
            for (int q = 0; q < 4; q++) a[q] = fmaxf(a[q], 0.f);
        }
        if (OUTH) {
            __half2* o = (__half2*)outp;
            o[(size_t)n * ostride + tl * 2] = __floats2half2_rn(a[0], a[1]);
            o[(size_t)n * ostride + tl * 2 + 1] = __floats2half2_rn(a[2], a[3]);
        } else {
            float2* o = (float2*)outp;
            o[(size_t)n * ostride + tl * 2] = make_float2(a[0], a[1]);
            o[(size_t)n * ostride + tl * 2 + 1] = make_float2(a[2], a[3]);
        }
    }
}

// ---------------- host side ----------------
extern "C" void kernel_launch(void* const* d_in, const int* in_sizes, int n_in,
                              void* d_out, int out_size) {
    const float* mol_x = (const float*)d_in[0];
    const int*   ei    = (const int*)d_in[1];
    const float* W1 = (const float*)d_in[3];
    const float* as1 = (const float*)d_in[4];
    const float* ad1 = (const float*)d_in[5];
    const float* b1 = (const float*)d_in[6];
    const float* W2 = (const float*)d_in[7];
    const float* as2 = (const float*)d_in[8];
    const float* ad2 = (const float*)d_in[9];
    const float* b2 = (const float*)d_in[10];
    const float* W3 = (const float*)d_in[11];
    const float* as3 = (const float*)d_in[12];
    const float* ad3 = (const float*)d_in[13];
    const float* b3 = (const float*)d_in[14];
    const float* fc1_w = (const float*)d_in[15];
    const float* fc1_b = (const float*)d_in[16];
    const float* fc2_w = (const float*)d_in[17];
    const float* fc2_b = (const float*)d_in[18];
    const float* mol_bias = (const float*)d_in[19];
    const float* theta1 = (const float*)d_in[20];
    const float* hb1 = (const float*)d_in[21];
    const float* theta2 = (const float*)d_in[22];
    const float* hb2 = (const float*)d_in[23];

    __half *p_mx, *p_catA, *p_catB, *p_agg, *p_xt, *p_ef, *p_hy16;
    __half *p_w1h, *p_w2h, *p_w3h, *p_bch, *p_th1h, *p_th2h;
    float *p_cb;
    cudaGetSymbolAddress((void**)&p_mx, d_mx16);
    cudaGetSymbolAddress((void**)&p_catA, d_catA);
    cudaGetSymbolAddress((void**)&p_catB, d_catB);
    cudaGetSymbolAddress((void**)&p_agg, d_agg);
    cudaGetSymbolAddress((void**)&p_xt, d_xt);
    cudaGetSymbolAddress((void**)&p_ef, d_ef);
    cudaGetSymbolAddress((void**)&p_hy16, d_hy16);
    cudaGetSymbolAddress((void**)&p_w1h, d_w1h);
    cudaGetSymbolAddress((void**)&p_w2h, d_w2h);
    cudaGetSymbolAddress((void**)&p_w3h, d_w3h);
    cudaGetSymbolAddress((void**)&p_bch, d_bch);
    cudaGetSymbolAddress((void**)&p_th1h, d_th1h);
    cudaGetSymbolAddress((void**)&p_th2h, d_th2h);
    cudaGetSymbolAddress((void**)&p_cb, d_cb);
    float* p_out = (float*)d_out;

    // ---- CSR build ----
    zero_counts_kernel<<<(NN + 255) / 256, 256>>>();
    count_kernel<<<(EE + 255) / 256, 256>>>(ei);
    scan_p1<<<dim3(NBLK, 2), 1024>>>();
    scan_p2<<<2, 128>>>();
    scan_p3<<<dim3(NBLK, 2), 1024>>>();
    fill_kernel<<<(EE + 255) / 256, 256>>>(ei);

    // ---- conversions ----
    conv_mx_kernel<<<(NN * 40 + 255) / 256, 256>>>(mol_x);
    f2h_kernel<<<(FIN * 512 / 2 + 255) / 256, 256>>>(W1, p_w1h, FIN * 512 / 2);
    f2h_kernel<<<(256 * 512 / 2 + 255) / 256, 256>>>(W2, p_w2h, 256 * 512 / 2);
    f2h_kernel<<<(256 * 512 / 2 + 255) / 256, 256>>>(W3, p_w3h, 256 * 512 / 2);
    f2h_kernel<<<(334 * 128 / 2 + 255) / 256, 256>>>(theta1, p_th1h, 334 * 128 / 2);
    f2h_kernel<<<(128 * 128 / 2 + 255) / 256, 256>>>(theta2, p_th2h, 128 * 128 / 2);
    build_bc16_kernel<<<(512 * 256 + 255) / 256, 256>>>(fc1_w, fc2_w, fc1_b, fc2_b);

    // ---- GAT layer 1: h1 (fp16) = relu(gat(mol_x)) ----
    build_wv_kernel<<<FIN, 256>>>(W1, as1, ad1);
    attn2_kernel<<<(NN + 3) / 4, 128>>>(mol_x, FIN);
    gat_agg80_kernel<<<NN, 64>>>((const __half2*)p_mx, (__half2*)p_agg);
    run_gemm<2, 0>(p_agg, 160, 0, nullptr, 0, nullptr, 0, p_w1h, p_w1h + 256, 512, 80, FIN, FIN,
                   nullptr, 0, p_catA + 256, 512, NN, 256, 160, b1, 1, 0.5f, nullptr);

    // ---- GAT layer 2 ----
    build_wv_kernel<<<256, 256>>>(W2, as2, ad2);
    attn2h_kernel<<<(NN + 3) / 4, 128>>>(p_catA + 256, 512);
    gat_agg256_kernel<<<NN, 128>>>((const __half2*)(p_catA + 256), 256, (__half2*)p_agg);
    run_gemm<2, 0>(p_agg, 512, 0, nullptr, 0, nullptr, 0, p_w2h, p_w2h + 256, 512, 256, 256, 256,
                   nullptr, 0, p_catA, 512, NN, 256, 512, b2, 1, 0.5f, nullptr);
    run_gemm<2, 2>(p_catA, 512, 0, nullptr, 0, p_catA + 256, 512, p_bch, nullptr, 256, 512, 512, 0,
                   nullptr, 0, p_catB + 256, 512, NN, 256, 512, p_cb, 0, 1.0f, mol_bias);
    // h2 fp16 in catB[256:)

    // ---- GAT layer 3 ----
    build_wv_kernel<<<256, 256>>>(W3, as3, ad3);
    attn2h_kernel<<<(NN + 3) / 4, 128>>>(p_catB + 256, 512);
    gat_agg256_kernel<<<NN, 128>>>((const __half2*)(p_catB + 256), 256, (__half2*)p_agg);
    run_gemm<2, 0>(p_agg, 512, 0, nullptr, 0, nullptr, 0, p_w3h, p_w3h + 256, 512, 256, 256, 256,
                   nullptr, 0, p_catB, 512, NN, 256, 512, b3, 0, 0.5f, nullptr);
    run_gemm<2, 2>(p_catB, 512, 0, nullptr, 0, p_catB + 256, 512, p_bch, nullptr, 256, 512, 512, 0,
                   p_out, 384, nullptr, 0, NN, 256, 512, p_cb, 0, 1.0f, mol_bias);
    // final h fp32 in d_out[:, 0:256)

    // ---- hypergraph branch ----
    run_gemm<0, 0>(p_out, 384, 256, mol_x, FIN, nullptr, 0, p_th1h, nullptr, 128, 334, 334, 0,
                   nullptr, 0, p_xt, 128, NN, 128, 334, nullptr, 0, 1.0f, nullptr);
    hyper_gather_kernel<true ><<<NN, 64>>>((const __half2*)p_xt, p_ef, 64, nullptr, 0, 0);
    hyper_gather_kernel<true ><<<NN, 64>>>((const __half2*)p_ef, p_hy16, 64, hb1, 1, 1);
    run_gemm<2, 0>(p_hy16, 128, 0, nullptr, 0, nullptr, 0, p_th2h, nullptr, 128, 128, 128, 0,
                   nullptr, 0, p_xt, 128, NN, 128, 128, nullptr, 0, 1.0f, nullptr);
    hyper_gather_kernel<true ><<<NN, 64>>>((const __half2*)p_xt, p_ef, 64, nullptr, 0, 0);
    hyper_gather_kernel<false><<<NN, 64>>>((const __half2*)p_ef, (float2*)p_out + 128, 192,
                                           hb2, 1, 1);
}